// round 7
// baseline (speedup 1.0000x reference)
#include <cuda_runtime.h>
#include <cuda_bf16.h>
#include <cstdint>

// Problem constants: B=8, LQ=LK=2048, D=1024
#define B_   8
#define LQ_  2048
#define LK_  2048
#define DIM_ 1024

typedef __nv_bfloat16 bf16;

// ---------------- device scratch (allocation-free rule) ----------------
#define NE_BIG ((size_t)B_ * LQ_ * DIM_)      // 16M
#define NE_P   ((size_t)B_ * LQ_ * LK_)       // 32M
__device__ bf16 g_xqh[NE_BIG], g_xql[NE_BIG];   // query split
__device__ bf16 g_xkh[NE_BIG], g_xkl[NE_BIG];   // key split
__device__ bf16 g_wqh[DIM_*DIM_], g_wql[DIM_*DIM_];
__device__ bf16 g_wkh[DIM_*DIM_], g_wkl[DIM_*DIM_];
__device__ bf16 g_wvh[DIM_*DIM_], g_wvl[DIM_*DIM_];
__device__ bf16 g_qh[NE_BIG], g_ql[NE_BIG];     // q proj split
__device__ bf16 g_kh[NE_BIG], g_kl[NE_BIG];     // k proj split
__device__ float g_v[NE_BIG];                   // v proj fp32
__device__ bf16 g_vth[NE_BIG], g_vtl[NE_BIG];   // v transposed split [B,D,LK]
__device__ bf16 g_ph[NE_P],  g_pl[NE_P];        // softmax(P) split

// ============================ helpers ============================
__device__ __forceinline__ uint32_t smem_u32(const void* p) {
    uint32_t a;
    asm("{ .reg .u64 t; cvta.to.shared.u64 t, %1; cvt.u32.u64 %0, t; }" : "=r"(a) : "l"(p));
    return a;
}
__device__ __forceinline__ void ldm_x4(uint32_t* r, uint32_t addr) {
    asm volatile("ldmatrix.sync.aligned.m8n8.x4.shared.b16 {%0,%1,%2,%3}, [%4];"
        : "=r"(r[0]), "=r"(r[1]), "=r"(r[2]), "=r"(r[3]) : "r"(addr));
}
__device__ __forceinline__ void mma_bf16(float* d, const uint32_t* a, const uint32_t* b) {
    asm volatile(
        "mma.sync.aligned.m16n8k16.row.col.f32.bf16.bf16.f32 "
        "{%0,%1,%2,%3}, {%4,%5,%6,%7}, {%8,%9}, {%0,%1,%2,%3};"
        : "+f"(d[0]), "+f"(d[1]), "+f"(d[2]), "+f"(d[3])
        : "r"(a[0]), "r"(a[1]), "r"(a[2]), "r"(a[3]), "r"(b[0]), "r"(b[1]));
}
__device__ __forceinline__ uint32_t pack_bf2(bf16 a, bf16 b) {
    __nv_bfloat162 t(a, b);
    return *reinterpret_cast<uint32_t*>(&t);
}
__device__ __forceinline__ void cp16(uint32_t dst, const void* src) {
    asm volatile("cp.async.cg.shared.global [%0], [%1], 16;" :: "r"(dst), "l"(src));
}
#define CP_COMMIT() asm volatile("cp.async.commit_group;" ::: "memory")
#define CP_WAIT1()  asm volatile("cp.async.wait_group 1;" ::: "memory")

// [row][k] bf16 tile, 64B rows, 16B-chunk XOR swizzle (conflict-free ldmatrix)
__device__ __forceinline__ uint32_t swoff(uint32_t row, uint32_t k) {
    uint32_t c = (k >> 3) ^ ((row >> 1) & 3u);
    return row * 64u + c * 16u + (k & 7u) * 2u;
}

__device__ __forceinline__ void split4(float4 t, uint2& h, uint2& l) {
    bf16 hx = __float2bfloat16_rn(t.x);
    bf16 hy = __float2bfloat16_rn(t.y);
    bf16 hz = __float2bfloat16_rn(t.z);
    bf16 hw = __float2bfloat16_rn(t.w);
    h.x = pack_bf2(hx, hy); h.y = pack_bf2(hz, hw);
    l.x = pack_bf2(__float2bfloat16_rn(t.x - __bfloat162float(hx)),
                   __float2bfloat16_rn(t.y - __bfloat162float(hy)));
    l.y = pack_bf2(__float2bfloat16_rn(t.z - __bfloat162float(hz)),
                   __float2bfloat16_rn(t.w - __bfloat162float(hw)));
}

// ============================ GEMM ============================
// C[M,N] = (Ah+Al)[M,K] * (Bh+Bl)[N,K]^T, bf16x3, fp32 accum.
// PERSISTENT: grid is 1-D, each CTA loops linearized tiles t += gridDim.x,
// t -> (bx = t%gx, by = (t/gx)%gy, bz = t/(gx*gy)). No wave quantization.
// Tile 128x128x32, 8 warps (2M x 4N), warp tile 64x32, 2 CTAs/SM.
// EPI: 0 none, 1 +bias[n], 2 mask[n]==0 ? -1e9 : acc*scale
// OUT: 0 fp32 -> Cf ; 1 bf16 hi/lo -> Ch/Cl
#define BM 128
#define BN 128
#define BK 32
#define NTH 256
#define NSTAGES 3
#define OFF_AH 0
#define OFF_AL 8192
#define OFF_BH 16384
#define OFF_BL 24576
#define STG    32768
#define SMEM_DYN (NSTAGES * STG)
#define GRID_P 304   // 2 * 152 SMs (GB300)

__device__ __forceinline__ void stage_load(uint32_t st,
    const bf16* __restrict__ pAh, const bf16* __restrict__ pAl,
    const bf16* __restrict__ pBh, const bf16* __restrict__ pBl,
    int K_, int k0, int tid)
{
#pragma unroll
    for (int i = 0; i < 2; i++) {
        int c = tid + i * NTH;              // 0..511 chunk id
        int row = c >> 2;                   // 0..127
        int kc = (c & 3) * 8;
        uint32_t off = swoff((uint32_t)row, (uint32_t)kc);
        long g = (long)row * K_ + k0 + kc;
        cp16(st + OFF_AH + off, pAh + g);
        cp16(st + OFF_AL + off, pAl + g);
        cp16(st + OFF_BH + off, pBh + g);
        cp16(st + OFF_BL + off, pBl + g);
    }
}

template <int EPI, int OUT>
__global__ __launch_bounds__(NTH, 2)
void gemm_hl(const bf16* __restrict__ Ah, const bf16* __restrict__ Al,
             const bf16* __restrict__ Bh, const bf16* __restrict__ Bl,
             float* __restrict__ Cf, bf16* __restrict__ Ch, bf16* __restrict__ Cl,
             int N_, int K_, long sA, long sB, long sC,
             const float* __restrict__ bias,
             const int* __restrict__ mask, long sMask, float scale,
             int nT, int gx, int gy)
{
    extern __shared__ char sm[];
    const uint32_t smb = smem_u32(sm);

    const int tid = threadIdx.x;
    const int lane = tid & 31;
    const int wid = tid >> 5;
    const int wm = wid & 1;        // 2 warps along M (64 each)
    const int wn = wid >> 1;       // 4 warps along N (32 each)

    const uint32_t a_row  = (uint32_t)(wm * 64 + (lane & 15));
    const uint32_t a_cadd = (uint32_t)(lane >> 4);
    const uint32_t b_row  = (uint32_t)(wn * 32 + (lane & 7) + ((lane >> 4) << 3));
    const uint32_t b_cadd = (uint32_t)((lane >> 3) & 1);

    const int nkt = K_ / BK;

    for (int t = blockIdx.x; t < nT; t += gridDim.x) {
        const int bx = t % gx;
        const int tmp = t / gx;
        const int by = tmp % gy;
        const int bz = tmp / gy;
        const int m0 = by * BM;
        const int n0 = bx * BN;

        const bf16* pAh = Ah + (long)bz * sA + (long)m0 * K_;
        const bf16* pAl = Al + (long)bz * sA + (long)m0 * K_;
        const bf16* pBh = Bh + (long)bz * sB + (long)n0 * K_;
        const bf16* pBl = Bl + (long)bz * sB + (long)n0 * K_;

        float acc[4][4][4];
#pragma unroll
        for (int i = 0; i < 4; i++)
#pragma unroll
            for (int j = 0; j < 4; j++)
#pragma unroll
                for (int l = 0; l < 4; l++) acc[i][j][l] = 0.f;

        // prologue: prefetch NSTAGES-1 stages
#pragma unroll
        for (int s = 0; s < NSTAGES - 1; s++) {
            stage_load(smb + s * STG, pAh, pAl, pBh, pBl, K_, s * BK, tid);
            CP_COMMIT();
        }

        for (int kt = 0; kt < nkt; kt++) {
            CP_WAIT1();
            __syncthreads();
            const uint32_t curb = smb + (uint32_t)(kt % NSTAGES) * STG;

            // prefetch stage kt+2 (last read at kt-1, behind the barrier above)
            const int pf = kt + NSTAGES - 1;
            if (pf < nkt)
                stage_load(smb + (uint32_t)(pf % NSTAGES) * STG, pAh, pAl, pBh, pBl,
                           K_, pf * BK, tid);
            CP_COMMIT();

#pragma unroll
            for (int ks = 0; ks < 2; ks++) {
                const uint32_t c0 = (uint32_t)(ks * 2);
                // phase 1: Ah * Bh
                uint32_t ah[4][4], bh[2][4];
#pragma unroll
                for (int mf = 0; mf < 4; mf++)
                    ldm_x4(ah[mf], curb + OFF_AH + swoff(a_row + mf * 16, (c0 + a_cadd) * 8));
#pragma unroll
                for (int np = 0; np < 2; np++)
                    ldm_x4(bh[np], curb + OFF_BH + swoff(b_row + np * 16, (c0 + b_cadd) * 8));
#pragma unroll
                for (int mf = 0; mf < 4; mf++)
#pragma unroll
                    for (int nf = 0; nf < 4; nf++)
                        mma_bf16(acc[mf][nf], ah[mf], &bh[nf >> 1][(nf & 1) * 2]);
                // phase 2: Al * Bh
                {
                    uint32_t al[4][4];
#pragma unroll
                    for (int mf = 0; mf < 4; mf++)
                        ldm_x4(al[mf], curb + OFF_AL + swoff(a_row + mf * 16, (c0 + a_cadd) * 8));
#pragma unroll
                    for (int mf = 0; mf < 4; mf++)
#pragma unroll
                        for (int nf = 0; nf < 4; nf++)
                            mma_bf16(acc[mf][nf], al[mf], &bh[nf >> 1][(nf & 1) * 2]);
                }
                // phase 3: Ah * Bl
                {
                    uint32_t bl[2][4];
#pragma unroll
                    for (int np = 0; np < 2; np++)
                        ldm_x4(bl[np], curb + OFF_BL + swoff(b_row + np * 16, (c0 + b_cadd) * 8));
#pragma unroll
                    for (int mf = 0; mf < 4; mf++)
#pragma unroll
                        for (int nf = 0; nf < 4; nf++)
                            mma_bf16(acc[mf][nf], ah[mf], &bl[nf >> 1][(nf & 1) * 2]);
                }
            }
        }

        // ---- epilogue (registers only; no smem reads) ----
        float* Cfb = Cf ? Cf + (long)bz * sC : nullptr;
        bf16*  Chb = Ch ? Ch + (long)bz * sC : nullptr;
        bf16*  Clb = Cl ? Cl + (long)bz * sC : nullptr;
#pragma unroll
        for (int mf = 0; mf < 4; mf++) {
            const int r0 = m0 + wm * 64 + mf * 16 + (lane >> 2);
#pragma unroll
            for (int half = 0; half < 2; half++) {
                const long r = r0 + half * 8;
#pragma unroll
                for (int nf = 0; nf < 4; nf++) {
                    const int n = n0 + wn * 32 + nf * 8 + (lane & 3) * 2;
                    float v0 = acc[mf][nf][half * 2 + 0];
                    float v1 = acc[mf][nf][half * 2 + 1];
                    if (EPI == 1) { v0 += bias[n]; v1 += bias[n + 1]; }
                    if (EPI == 2) {
                        int mv0 = mask[bz * sMask + n];
                        int mv1 = mask[bz * sMask + n + 1];
                        v0 = (mv0 == 0) ? -1e9f : v0 * scale;
                        v1 = (mv1 == 0) ? -1e9f : v1 * scale;
                    }
                    if (OUT == 0) {
                        float2 o = { v0, v1 };
                        *reinterpret_cast<float2*>(Cfb + r * N_ + n) = o;
                    } else {
                        bf16 h0 = __float2bfloat16_rn(v0);
                        bf16 h1 = __float2bfloat16_rn(v1);
                        *reinterpret_cast<uint32_t*>(Chb + r * N_ + n) = pack_bf2(h0, h1);
                        *reinterpret_cast<uint32_t*>(Clb + r * N_ + n) =
                            pack_bf2(__float2bfloat16_rn(v0 - __bfloat162float(h0)),
                                     __float2bfloat16_rn(v1 - __bfloat162float(h1)));
                    }
                }
            }
        }
        // protect smem: no warp may start next tile's prologue while another
        // warp still reads this tile's stages.
        __syncthreads();
    }
}

// ---------------- convert fp32 -> bf16 hi/lo ----------------
__global__ __launch_bounds__(256)
void cvt_hl(const float* __restrict__ in, bf16* __restrict__ h,
            bf16* __restrict__ l, long n4)
{
    long i = (long)blockIdx.x * blockDim.x + threadIdx.x;
    if (i >= n4) return;
    float4 t = reinterpret_cast<const float4*>(in)[i];
    uint2 hh, ll;
    split4(t, hh, ll);
    reinterpret_cast<uint2*>(h)[i] = hh;
    reinterpret_cast<uint2*>(l)[i] = ll;
}

// ---------------- transpose v[B,LK,D] fp32 -> vT hi/lo [B,D,LK] ----------------
__global__ __launch_bounds__(256)
void transpose_hl(const float* __restrict__ in, bf16* __restrict__ oh,
                  bf16* __restrict__ ol)
{
    __shared__ float t[32][33];
    const int b = blockIdx.z;
    const int lk0 = blockIdx.x * 32;
    const int d0 = blockIdx.y * 32;
    const float* ib = in + (size_t)b * LK_ * DIM_;
    bf16* ohb = oh + (size_t)b * DIM_ * LK_;
    bf16* olb = ol + (size_t)b * DIM_ * LK_;
    const int tx = threadIdx.x & 31;
    const int ty = threadIdx.x >> 5;
#pragma unroll
    for (int i = 0; i < 32; i += 8)
        t[ty + i][tx] = ib[(size_t)(lk0 + ty + i) * DIM_ + d0 + tx];
    __syncthreads();
#pragma unroll
    for (int i = 0; i < 32; i += 8) {
        float v = t[tx][ty + i];
        bf16 h = __float2bfloat16_rn(v);
        size_t o = (size_t)(d0 + ty + i) * LK_ + lk0 + tx;
        ohb[o] = h;
        olb[o] = __float2bfloat16_rn(v - __bfloat162float(h));
    }
}

// ---------------- softmax + emit P hi/lo ----------------
__global__ __launch_bounds__(256)
void softmax_kernel(float* __restrict__ score, bf16* __restrict__ ph,
                    bf16* __restrict__ pl)
{
    __shared__ float red[8];
    __shared__ float bcast;

    const long row = blockIdx.x;
    float* p = score + row * (long)LK_;
    const int tid = threadIdx.x;

    float4 a = reinterpret_cast<const float4*>(p)[tid];
    float4 b = reinterpret_cast<const float4*>(p)[tid + 256];

    float m = fmaxf(fmaxf(fmaxf(a.x, a.y), fmaxf(a.z, a.w)),
                    fmaxf(fmaxf(b.x, b.y), fmaxf(b.z, b.w)));
#pragma unroll
    for (int o = 16; o > 0; o >>= 1) m = fmaxf(m, __shfl_xor_sync(0xffffffffu, m, o));
    if ((tid & 31) == 0) red[tid >> 5] = m;
    __syncthreads();
    if (tid == 0) {
        float mm = red[0];
#pragma unroll
        for (int w = 1; w < 8; w++) mm = fmaxf(mm, red[w]);
        bcast = mm;
    }
    __syncthreads();
    m = bcast;
    __syncthreads();

    a.x = __expf(a.x - m); a.y = __expf(a.y - m);
    a.z = __expf(a.z - m); a.w = __expf(a.w - m);
    b.x = __expf(b.x - m); b.y = __expf(b.y - m);
    b.z = __expf(b.z - m); b.w = __expf(b.w - m);

    float s = (a.x + a.y) + (a.z + a.w) + (b.x + b.y) + (b.z + b.w);
#pragma unroll
    for (int o = 16; o > 0; o >>= 1) s += __shfl_xor_sync(0xffffffffu, s, o);
    if ((tid & 31) == 0) red[tid >> 5] = s;
    __syncthreads();
    if (tid == 0) {
        float ss = 0.f;
#pragma unroll
        for (int w = 0; w < 8; w++) ss += red[w];
        bcast = ss;
    }
    __syncthreads();
    s = bcast;

    float inv = 1.0f / s;
    a.x *= inv; a.y *= inv; a.z *= inv; a.w *= inv;
    b.x *= inv; b.y *= inv; b.z *= inv; b.w *= inv;

    reinterpret_cast<float4*>(p)[tid]       = a;
    reinterpret_cast<float4*>(p)[tid + 256] = b;

    uint2 h0, l0, h1, l1;
    split4(a, h0, l0);
    split4(b, h1, l1);
    bf16* phr = ph + row * (long)LK_;
    bf16* plr = pl + row * (long)LK_;
    reinterpret_cast<uint2*>(phr)[tid]       = h0;
    reinterpret_cast<uint2*>(plr)[tid]       = l0;
    reinterpret_cast<uint2*>(phr)[tid + 256] = h1;
    reinterpret_cast<uint2*>(plr)[tid + 256] = l1;
}

// ============================ launch ============================
static inline unsigned pgrid(int nT) { return (unsigned)(nT < GRID_P ? nT : GRID_P); }

extern "C" void kernel_launch(void* const* d_in, const int* in_sizes, int n_in,
                              void* d_out, int out_size)
{
    const float* key   = (const float*)d_in[0];
    const float* query = (const float*)d_in[1];
    const int*   mask  = (const int*)d_in[2];
    const float* Wq    = (const float*)d_in[3];
    const float* bq    = (const float*)d_in[4];
    const float* Wk    = (const float*)d_in[5];
    const float* bk    = (const float*)d_in[6];
    const float* Wv    = (const float*)d_in[7];
    const float* bv    = (const float*)d_in[8];

    float* out   = (float*)d_out;                         // [B, LQ, D]
    float* score = out + (size_t)B_ * LQ_ * DIM_;         // [B, LQ, LK]

    bf16 *xqh, *xql, *xkh, *xkl, *wqh, *wql, *wkh, *wkl, *wvh, *wvl;
    bf16 *qh, *ql, *kh, *kl, *vth, *vtl, *ph, *pl;
    float* vbuf;
    cudaGetSymbolAddress((void**)&xqh, g_xqh); cudaGetSymbolAddress((void**)&xql, g_xql);
    cudaGetSymbolAddress((void**)&xkh, g_xkh); cudaGetSymbolAddress((void**)&xkl, g_xkl);
    cudaGetSymbolAddress((void**)&wqh, g_wqh); cudaGetSymbolAddress((void**)&wql, g_wql);
    cudaGetSymbolAddress((void**)&wkh, g_wkh); cudaGetSymbolAddress((void**)&wkl, g_wkl);
    cudaGetSymbolAddress((void**)&wvh, g_wvh); cudaGetSymbolAddress((void**)&wvl, g_wvl);
    cudaGetSymbolAddress((void**)&qh, g_qh);   cudaGetSymbolAddress((void**)&ql, g_ql);
    cudaGetSymbolAddress((void**)&kh, g_kh);   cudaGetSymbolAddress((void**)&kl, g_kl);
    cudaGetSymbolAddress((void**)&vth, g_vth); cudaGetSymbolAddress((void**)&vtl, g_vtl);
    cudaGetSymbolAddress((void**)&ph, g_ph);   cudaGetSymbolAddress((void**)&pl, g_pl);
    cudaGetSymbolAddress((void**)&vbuf, g_v);

    cudaFuncSetAttribute(gemm_hl<0,0>, cudaFuncAttributeMaxDynamicSharedMemorySize, SMEM_DYN);
    cudaFuncSetAttribute(gemm_hl<1,0>, cudaFuncAttributeMaxDynamicSharedMemorySize, SMEM_DYN);
    cudaFuncSetAttribute(gemm_hl<1,1>, cudaFuncAttributeMaxDynamicSharedMemorySize, SMEM_DYN);
    cudaFuncSetAttribute(gemm_hl<2,0>, cudaFuncAttributeMaxDynamicSharedMemorySize, SMEM_DYN);

    dim3 blk(NTH);
    const float scale = 0.03125f;  // 1/sqrt(1024)
    const long NBIG4 = (long)NE_BIG / 4;
    const long NW4 = (long)DIM_ * DIM_ / 4;

    // 0. split inputs and weights into bf16 hi/lo
    cvt_hl<<<(unsigned)((NBIG4 + 255) / 256), 256>>>(query, xqh, xql, NBIG4);
    cvt_hl<<<(unsigned)((NBIG4 + 255) / 256), 256>>>(key,   xkh, xkl, NBIG4);
    cvt_hl<<<(unsigned)((NW4 + 255) / 256), 256>>>(Wq, wqh, wql, NW4);
    cvt_hl<<<(unsigned)((NW4 + 255) / 256), 256>>>(Wk, wkh, wkl, NW4);
    cvt_hl<<<(unsigned)((NW4 + 255) / 256), 256>>>(Wv, wvh, wvl, NW4);

    // 1. q = query @ Wq^T + bq  -> hi/lo   (gx=8, gy=128, nT=1024)
    {
        int gx = DIM_ / BN, gy = (B_ * LQ_) / BM, nT = gx * gy;
        gemm_hl<1,1><<<pgrid(nT), blk, SMEM_DYN>>>(xqh, xql, wqh, wql, nullptr, qh, ql,
                                                   DIM_, DIM_, 0, 0, 0, bq, nullptr, 0,
                                                   1.f, nT, gx, gy);
    }
    // 2. k = key @ Wk^T + bk  -> hi/lo
    {
        int gx = DIM_ / BN, gy = (B_ * LK_) / BM, nT = gx * gy;
        gemm_hl<1,1><<<pgrid(nT), blk, SMEM_DYN>>>(xkh, xkl, wkh, wkl, nullptr, kh, kl,
                                                   DIM_, DIM_, 0, 0, 0, bk, nullptr, 0,
                                                   1.f, nT, gx, gy);
    }
    // 3. v = k_proj @ Wv^T + bv  -> fp32
    {
        int gx = DIM_ / BN, gy = (B_ * LK_) / BM, nT = gx * gy;
        gemm_hl<1,0><<<pgrid(nT), blk, SMEM_DYN>>>(kh, kl, wvh, wvl, vbuf, nullptr, nullptr,
                                                   DIM_, DIM_, 0, 0, 0, bv, nullptr, 0,
                                                   1.f, nT, gx, gy);
    }
    // 4. score_raw = (q @ k^T) * scale, masked  (gx=16, gy=16, gz=8, nT=2048)
    {
        int gx = LK_ / BN, gy = LQ_ / BM, nT = gx * gy * B_;
        gemm_hl<2,0><<<pgrid(nT), blk, SMEM_DYN>>>(qh, ql, kh, kl, score, nullptr, nullptr,
                                                   LK_, DIM_, (long)LQ_ * DIM_,
                                                   (long)LK_ * DIM_, (long)LQ_ * LK_,
                                                   nullptr, mask, LK_, scale, nT, gx, gy);
    }
    // 5. vT hi/lo
    {
        dim3 g(LK_ / 32, DIM_ / 32, B_);
        transpose_hl<<<g, 256>>>(vbuf, vth, vtl);
    }
    // 6. softmax rows in place + P hi/lo
    softmax_kernel<<<B_ * LQ_, 256>>>(score, ph, pl);

    // 7. output = P @ V  (gx=8, gy=16, gz=8, nT=1024)
    {
        int gx = DIM_ / BN, gy = LQ_ / BM, nT = gx * gy * B_;
        gemm_hl<0,0><<<pgrid(nT), blk, SMEM_DYN>>>(ph, pl, vth, vtl, out, nullptr, nullptr,
                                                   DIM_, LK_, (long)LQ_ * LK_,
                                                   (long)DIM_ * LK_, (long)LQ_ * DIM_,
                                                   nullptr, nullptr, 0, 1.f, nT, gx, gy);
    }
}

// round 8
// speedup vs baseline: 1.2157x; 1.2157x over previous
#include <cuda_runtime.h>
#include <cuda_bf16.h>
#include <cuda_fp16.h>
#include <cstdint>

// Problem constants: B=8, LQ=LK=2048, D=1024
#define B_   8
#define LQ_  2048
#define LK_  2048
#define DIM_ 1024

typedef __nv_bfloat16 bf16;
typedef __half f16;

// ---------------- device scratch (allocation-free rule) ----------------
#define NE_BIG ((size_t)B_ * LQ_ * DIM_)      // 16M
#define NE_P   ((size_t)B_ * LQ_ * LK_)       // 32M
__device__ bf16 g_xqh[NE_BIG], g_xql[NE_BIG];   // query split (bf16)
__device__ bf16 g_xkh[NE_BIG], g_xkl[NE_BIG];   // key split (bf16)
__device__ bf16 g_wqh[DIM_*DIM_], g_wql[DIM_*DIM_];
__device__ bf16 g_wkh[DIM_*DIM_], g_wkl[DIM_*DIM_];
__device__ bf16 g_wvh[DIM_*DIM_], g_wvl[DIM_*DIM_];
__device__ f16  g_q16h[NE_BIG], g_q16l[NE_BIG]; // q proj fp16 hi/lo (score A)
__device__ bf16 g_kh[NE_BIG], g_kl[NE_BIG];     // k proj bf16 hi/lo (v-proj A)
__device__ f16  g_k16[NE_BIG];                  // k proj fp16 single (score B)
__device__ float g_v[NE_BIG];                   // v proj fp32
__device__ f16  g_vt16[NE_BIG];                 // v transposed fp16 [B,D,LK]
__device__ f16  g_ph[NE_P], g_pl[NE_P];         // softmax(P) fp16 hi/lo

// ============================ helpers ============================
__device__ __forceinline__ uint32_t smem_u32(const void* p) {
    uint32_t a;
    asm("{ .reg .u64 t; cvta.to.shared.u64 t, %1; cvt.u32.u64 %0, t; }" : "=r"(a) : "l"(p));
    return a;
}
__device__ __forceinline__ void ldm_x4(uint32_t* r, uint32_t addr) {
    asm volatile("ldmatrix.sync.aligned.m8n8.x4.shared.b16 {%0,%1,%2,%3}, [%4];"
        : "=r"(r[0]), "=r"(r[1]), "=r"(r[2]), "=r"(r[3]) : "r"(addr));
}
__device__ __forceinline__ void mma_bf16(float* d, const uint32_t* a, const uint32_t* b) {
    asm volatile(
        "mma.sync.aligned.m16n8k16.row.col.f32.bf16.bf16.f32 "
        "{%0,%1,%2,%3}, {%4,%5,%6,%7}, {%8,%9}, {%0,%1,%2,%3};"
        : "+f"(d[0]), "+f"(d[1]), "+f"(d[2]), "+f"(d[3])
        : "r"(a[0]), "r"(a[1]), "r"(a[2]), "r"(a[3]), "r"(b[0]), "r"(b[1]));
}
__device__ __forceinline__ void mma_f16(float* d, const uint32_t* a, const uint32_t* b) {
    asm volatile(
        "mma.sync.aligned.m16n8k16.row.col.f32.f16.f16.f32 "
        "{%0,%1,%2,%3}, {%4,%5,%6,%7}, {%8,%9}, {%0,%1,%2,%3};"
        : "+f"(d[0]), "+f"(d[1]), "+f"(d[2]), "+f"(d[3])
        : "r"(a[0]), "r"(a[1]), "r"(a[2]), "r"(a[3]), "r"(b[0]), "r"(b[1]));
}
__device__ __forceinline__ uint32_t pack_bf2(bf16 a, bf16 b) {
    __nv_bfloat162 t(a, b);
    return *reinterpret_cast<uint32_t*>(&t);
}
__device__ __forceinline__ uint32_t pack_h2(f16 a, f16 b) {
    __half2 t(a, b);
    return *reinterpret_cast<uint32_t*>(&t);
}
__device__ __forceinline__ void cp16(uint32_t dst, const void* src) {
    asm volatile("cp.async.cg.shared.global [%0], [%1], 16;" :: "r"(dst), "l"(src));
}
#define CP_COMMIT() asm volatile("cp.async.commit_group;" ::: "memory")
#define CP_WAIT1()  asm volatile("cp.async.wait_group 1;" ::: "memory")

// [row][k] 16-bit tile, 64B rows, 16B-chunk XOR swizzle (conflict-free ldmatrix)
__device__ __forceinline__ uint32_t swoff(uint32_t row, uint32_t k) {
    uint32_t c = (k >> 3) ^ ((row >> 1) & 3u);
    return row * 64u + c * 16u + (k & 7u) * 2u;
}

__device__ __forceinline__ void split4(float4 t, uint2& h, uint2& l) {
    bf16 hx = __float2bfloat16_rn(t.x);
    bf16 hy = __float2bfloat16_rn(t.y);
    bf16 hz = __float2bfloat16_rn(t.z);
    bf16 hw = __float2bfloat16_rn(t.w);
    h.x = pack_bf2(hx, hy); h.y = pack_bf2(hz, hw);
    l.x = pack_bf2(__float2bfloat16_rn(t.x - __bfloat162float(hx)),
                   __float2bfloat16_rn(t.y - __bfloat162float(hy)));
    l.y = pack_bf2(__float2bfloat16_rn(t.z - __bfloat162float(hz)),
                   __float2bfloat16_rn(t.w - __bfloat162float(hw)));
}
__device__ __forceinline__ void split4_f16(float4 t, uint2& h, uint2& l) {
    f16 hx = __float2half_rn(t.x);
    f16 hy = __float2half_rn(t.y);
    f16 hz = __float2half_rn(t.z);
    f16 hw = __float2half_rn(t.w);
    h.x = pack_h2(hx, hy); h.y = pack_h2(hz, hw);
    l.x = pack_h2(__float2half_rn(t.x - __half2float(hx)),
                  __float2half_rn(t.y - __half2float(hy)));
    l.y = pack_h2(__float2half_rn(t.z - __half2float(hz)),
                  __float2half_rn(t.w - __half2float(hw)));
}

// ===================== bf16x3 GEMM (projections) =====================
// C[M,N] = (Ah+Al)[M,K] * (Bh+Bl)[N,K]^T, fp32 accum, 128x128x32 tile,
// 8 warps (2M x 4N), 2 CTAs/SM, 3-stage cp.async.
// EPI: 1 +bias[n].  OUT: 0 fp32 -> p0
//                        2 bf16 hi/lo -> p0,p1 AND fp16 single -> p2
//                        3 fp16 hi/lo -> p0,p1
#define BM 128
#define BN 128
#define BK 32
#define NTH 256
#define NSTAGES 3
#define OFF_AH 0
#define OFF_AL 8192
#define OFF_BH 16384
#define OFF_BL 24576
#define STG    32768
#define SMEM_B3 (NSTAGES * STG)

__device__ __forceinline__ void stage_load(uint32_t st,
    const bf16* __restrict__ pAh, const bf16* __restrict__ pAl,
    const bf16* __restrict__ pBh, const bf16* __restrict__ pBl,
    int K_, int k0, int tid)
{
#pragma unroll
    for (int i = 0; i < 2; i++) {
        int c = tid + i * NTH;
        int row = c >> 2;
        int kc = (c & 3) * 8;
        uint32_t off = swoff((uint32_t)row, (uint32_t)kc);
        long g = (long)row * K_ + k0 + kc;
        cp16(st + OFF_AH + off, pAh + g);
        cp16(st + OFF_AL + off, pAl + g);
        cp16(st + OFF_BH + off, pBh + g);
        cp16(st + OFF_BL + off, pBl + g);
    }
}

template <int EPI, int OUT>
__global__ __launch_bounds__(NTH, 2)
void gemm_hl(const bf16* __restrict__ Ah, const bf16* __restrict__ Al,
             const bf16* __restrict__ Bh, const bf16* __restrict__ Bl,
             void* __restrict__ p0, void* __restrict__ p1, void* __restrict__ p2,
             int N_, int K_, const float* __restrict__ bias)
{
    extern __shared__ char sm[];
    const uint32_t smb = smem_u32(sm);

    const int tid = threadIdx.x;
    const int lane = tid & 31;
    const int wid = tid >> 5;
    const int wm = wid & 1;
    const int wn = wid >> 1;

    const int m0 = blockIdx.y * BM;
    const int n0 = blockIdx.x * BN;

    const bf16* pAh = Ah + (long)m0 * K_;
    const bf16* pAl = Al + (long)m0 * K_;
    const bf16* pBh = Bh + (long)n0 * K_;
    const bf16* pBl = Bl + (long)n0 * K_;

    const uint32_t a_row  = (uint32_t)(wm * 64 + (lane & 15));
    const uint32_t a_cadd = (uint32_t)(lane >> 4);
    const uint32_t b_row  = (uint32_t)(wn * 32 + (lane & 7) + ((lane >> 4) << 3));
    const uint32_t b_cadd = (uint32_t)((lane >> 3) & 1);

    float acc[4][4][4];
#pragma unroll
    for (int i = 0; i < 4; i++)
#pragma unroll
        for (int j = 0; j < 4; j++)
#pragma unroll
            for (int l = 0; l < 4; l++) acc[i][j][l] = 0.f;

    const int nkt = K_ / BK;

#pragma unroll
    for (int s = 0; s < NSTAGES - 1; s++) {
        stage_load(smb + s * STG, pAh, pAl, pBh, pBl, K_, s * BK, tid);
        CP_COMMIT();
    }

    for (int kt = 0; kt < nkt; kt++) {
        CP_WAIT1();
        __syncthreads();
        const uint32_t curb = smb + (uint32_t)(kt % NSTAGES) * STG;

        const int pf = kt + NSTAGES - 1;
        if (pf < nkt)
            stage_load(smb + (uint32_t)(pf % NSTAGES) * STG, pAh, pAl, pBh, pBl,
                       K_, pf * BK, tid);
        CP_COMMIT();

#pragma unroll
        for (int ks = 0; ks < 2; ks++) {
            const uint32_t c0 = (uint32_t)(ks * 2);
            uint32_t ah[4][4], bh[2][4];
#pragma unroll
            for (int mf = 0; mf < 4; mf++)
                ldm_x4(ah[mf], curb + OFF_AH + swoff(a_row + mf * 16, (c0 + a_cadd) * 8));
#pragma unroll
            for (int np = 0; np < 2; np++)
                ldm_x4(bh[np], curb + OFF_BH + swoff(b_row + np * 16, (c0 + b_cadd) * 8));
#pragma unroll
            for (int mf = 0; mf < 4; mf++)
#pragma unroll
                for (int nf = 0; nf < 4; nf++)
                    mma_bf16(acc[mf][nf], ah[mf], &bh[nf >> 1][(nf & 1) * 2]);
            {
                uint32_t al[4][4];
#pragma unroll
                for (int mf = 0; mf < 4; mf++)
                    ldm_x4(al[mf], curb + OFF_AL + swoff(a_row + mf * 16, (c0 + a_cadd) * 8));
#pragma unroll
                for (int mf = 0; mf < 4; mf++)
#pragma unroll
                    for (int nf = 0; nf < 4; nf++)
                        mma_bf16(acc[mf][nf], al[mf], &bh[nf >> 1][(nf & 1) * 2]);
            }
            {
                uint32_t bl[2][4];
#pragma unroll
                for (int np = 0; np < 2; np++)
                    ldm_x4(bl[np], curb + OFF_BL + swoff(b_row + np * 16, (c0 + b_cadd) * 8));
#pragma unroll
                for (int mf = 0; mf < 4; mf++)
#pragma unroll
                    for (int nf = 0; nf < 4; nf++)
                        mma_bf16(acc[mf][nf], ah[mf], &bl[nf >> 1][(nf & 1) * 2]);
            }
        }
    }

    // ---- epilogue ----
#pragma unroll
    for (int mf = 0; mf < 4; mf++) {
        const int r0 = m0 + wm * 64 + mf * 16 + (lane >> 2);
#pragma unroll
        for (int half = 0; half < 2; half++) {
            const long r = r0 + half * 8;
#pragma unroll
            for (int nf = 0; nf < 4; nf++) {
                const int n = n0 + wn * 32 + nf * 8 + (lane & 3) * 2;
                float v0 = acc[mf][nf][half * 2 + 0];
                float v1 = acc[mf][nf][half * 2 + 1];
                if (EPI == 1) { v0 += bias[n]; v1 += bias[n + 1]; }
                if (OUT == 0) {
                    float2 o = { v0, v1 };
                    *reinterpret_cast<float2*>((float*)p0 + r * N_ + n) = o;
                } else if (OUT == 3) {
                    f16 h0 = __float2half_rn(v0);
                    f16 h1 = __float2half_rn(v1);
                    *reinterpret_cast<uint32_t*>((f16*)p0 + r * N_ + n) = pack_h2(h0, h1);
                    *reinterpret_cast<uint32_t*>((f16*)p1 + r * N_ + n) =
                        pack_h2(__float2half_rn(v0 - __half2float(h0)),
                                __float2half_rn(v1 - __half2float(h1)));
                } else { // OUT == 2
                    bf16 h0 = __float2bfloat16_rn(v0);
                    bf16 h1 = __float2bfloat16_rn(v1);
                    *reinterpret_cast<uint32_t*>((bf16*)p0 + r * N_ + n) = pack_bf2(h0, h1);
                    *reinterpret_cast<uint32_t*>((bf16*)p1 + r * N_ + n) =
                        pack_bf2(__float2bfloat16_rn(v0 - __bfloat162float(h0)),
                                 __float2bfloat16_rn(v1 - __bfloat162float(h1)));
                    *reinterpret_cast<uint32_t*>((f16*)p2 + r * N_ + n) =
                        pack_h2(__float2half_rn(v0), __float2half_rn(v1));
                }
            }
        }
    }
}

// ===================== fp16 2-product GEMM (score / PV) =====================
// C[M,N] = (Ah+Al)[M,K] * B[N,K]^T, fp16 frags, fp32 accum.
// EPI: 0 none, 2 mask[n]==0 ? -1e9 : acc*scale
#define F_OFF_AH 0
#define F_OFF_AL 8192
#define F_OFF_B  16384
#define F_STG    24576
#define SMEM_F16 (NSTAGES * F_STG)

__device__ __forceinline__ void stage_load_f16(uint32_t st,
    const f16* __restrict__ pAh, const f16* __restrict__ pAl,
    const f16* __restrict__ pB, int K_, int k0, int tid)
{
#pragma unroll
    for (int i = 0; i < 2; i++) {
        int c = tid + i * NTH;
        int row = c >> 2;
        int kc = (c & 3) * 8;
        uint32_t off = swoff((uint32_t)row, (uint32_t)kc);
        long g = (long)row * K_ + k0 + kc;
        cp16(st + F_OFF_AH + off, pAh + g);
        cp16(st + F_OFF_AL + off, pAl + g);
        cp16(st + F_OFF_B  + off, pB  + g);
    }
}

template <int EPI>
__global__ __launch_bounds__(NTH, 2)
void gemm_f16(const f16* __restrict__ Ah, const f16* __restrict__ Al,
              const f16* __restrict__ Bm, float* __restrict__ Cf,
              int N_, int K_, long sA, long sB, long sC,
              const int* __restrict__ mask, long sMask, float scale)
{
    extern __shared__ char sm[];
    const uint32_t smb = smem_u32(sm);

    const int tid = threadIdx.x;
    const int lane = tid & 31;
    const int wid = tid >> 5;
    const int wm = wid & 1;
    const int wn = wid >> 1;

    const int bz = blockIdx.z;
    const int m0 = blockIdx.y * BM;
    const int n0 = blockIdx.x * BN;

    const f16* pAh = Ah + (long)bz * sA + (long)m0 * K_;
    const f16* pAl = Al + (long)bz * sA + (long)m0 * K_;
    const f16* pB  = Bm + (long)bz * sB + (long)n0 * K_;

    const uint32_t a_row  = (uint32_t)(wm * 64 + (lane & 15));
    const uint32_t a_cadd = (uint32_t)(lane >> 4);
    const uint32_t b_row  = (uint32_t)(wn * 32 + (lane & 7) + ((lane >> 4) << 3));
    const uint32_t b_cadd = (uint32_t)((lane >> 3) & 1);

    float acc[4][4][4];
#pragma unroll
    for (int i = 0; i < 4; i++)
#pragma unroll
        for (int j = 0; j < 4; j++)
#pragma unroll
            for (int l = 0; l < 4; l++) acc[i][j][l] = 0.f;

    const int nkt = K_ / BK;

#pragma unroll
    for (int s = 0; s < NSTAGES - 1; s++) {
        stage_load_f16(smb + s * F_STG, pAh, pAl, pB, K_, s * BK, tid);
        CP_COMMIT();
    }

    for (int kt = 0; kt < nkt; kt++) {
        CP_WAIT1();
        __syncthreads();
        const uint32_t curb = smb + (uint32_t)(kt % NSTAGES) * F_STG;

        const int pf = kt + NSTAGES - 1;
        if (pf < nkt)
            stage_load_f16(smb + (uint32_t)(pf % NSTAGES) * F_STG, pAh, pAl, pB,
                           K_, pf * BK, tid);
        CP_COMMIT();

#pragma unroll
        for (int ks = 0; ks < 2; ks++) {
            const uint32_t c0 = (uint32_t)(ks * 2);
            uint32_t ah[4][4], bb[2][4];
#pragma unroll
            for (int mf = 0; mf < 4; mf++)
                ldm_x4(ah[mf], curb + F_OFF_AH + swoff(a_row + mf * 16, (c0 + a_cadd) * 8));
#pragma unroll
            for (int np = 0; np < 2; np++)
                ldm_x4(bb[np], curb + F_OFF_B + swoff(b_row + np * 16, (c0 + b_cadd) * 8));
#pragma unroll
            for (int mf = 0; mf < 4; mf++)
#pragma unroll
                for (int nf = 0; nf < 4; nf++)
                    mma_f16(acc[mf][nf], ah[mf], &bb[nf >> 1][(nf & 1) * 2]);
            {
                uint32_t al[4][4];
#pragma unroll
                for (int mf = 0; mf < 4; mf++)
                    ldm_x4(al[mf], curb + F_OFF_AL + swoff(a_row + mf * 16, (c0 + a_cadd) * 8));
#pragma unroll
                for (int mf = 0; mf < 4; mf++)
#pragma unroll
                    for (int nf = 0; nf < 4; nf++)
                        mma_f16(acc[mf][nf], al[mf], &bb[nf >> 1][(nf & 1) * 2]);
            }
        }
    }

    float* Cb = Cf + (long)bz * sC;
#pragma unroll
    for (int mf = 0; mf < 4; mf++) {
        const int r0 = m0 + wm * 64 + mf * 16 + (lane >> 2);
#pragma unroll
        for (int half = 0; half < 2; half++) {
            const long r = r0 + half * 8;
#pragma unroll
            for (int nf = 0; nf < 4; nf++) {
                const int n = n0 + wn * 32 + nf * 8 + (lane & 3) * 2;
                float v0 = acc[mf][nf][half * 2 + 0];
                float v1 = acc[mf][nf][half * 2 + 1];
                if (EPI == 2) {
                    int mv0 = mask[bz * sMask + n];
                    int mv1 = mask[bz * sMask + n + 1];
                    v0 = (mv0 == 0) ? -1e9f : v0 * scale;
                    v1 = (mv1 == 0) ? -1e9f : v1 * scale;
                }
                float2 o = { v0, v1 };
                *reinterpret_cast<float2*>(Cb + r * N_ + n) = o;
            }
        }
    }
}

// ---------------- convert fp32 -> bf16 hi/lo ----------------
__global__ __launch_bounds__(256)
void cvt_hl(const float* __restrict__ in, bf16* __restrict__ h,
            bf16* __restrict__ l, long n4)
{
    long i = (long)blockIdx.x * blockDim.x + threadIdx.x;
    if (i >= n4) return;
    float4 t = reinterpret_cast<const float4*>(in)[i];
    uint2 hh, ll;
    split4(t, hh, ll);
    reinterpret_cast<uint2*>(h)[i] = hh;
    reinterpret_cast<uint2*>(l)[i] = ll;
}

// ---------------- transpose v[B,LK,D] fp32 -> vT fp16 [B,D,LK] ----------------
__global__ __launch_bounds__(256)
void transpose_f16(const float* __restrict__ in, f16* __restrict__ oh)
{
    __shared__ float t[32][33];
    const int b = blockIdx.z;
    const int lk0 = blockIdx.x * 32;
    const int d0 = blockIdx.y * 32;
    const float* ib = in + (size_t)b * LK_ * DIM_;
    f16* ohb = oh + (size_t)b * DIM_ * LK_;
    const int tx = threadIdx.x & 31;
    const int ty = threadIdx.x >> 5;
#pragma unroll
    for (int i = 0; i < 32; i += 8)
        t[ty + i][tx] = ib[(size_t)(lk0 + ty + i) * DIM_ + d0 + tx];
    __syncthreads();
#pragma unroll
    for (int i = 0; i < 32; i += 8)
        ohb[(size_t)(d0 + ty + i) * LK_ + lk0 + tx] = __float2half_rn(t[tx][ty + i]);
}

// ---------------- softmax + emit P fp16 hi/lo ----------------
__global__ __launch_bounds__(256)
void softmax_kernel(float* __restrict__ score, f16* __restrict__ ph,
                    f16* __restrict__ pl)
{
    __shared__ float red[8];
    __shared__ float bcast;

    const long row = blockIdx.x;
    float* p = score + row * (long)LK_;
    const int tid = threadIdx.x;

    float4 a = reinterpret_cast<const float4*>(p)[tid];
    float4 b = reinterpret_cast<const float4*>(p)[tid + 256];

    float m = fmaxf(fmaxf(fmaxf(a.x, a.y), fmaxf(a.z, a.w)),
                    fmaxf(fmaxf(b.x, b.y), fmaxf(b.z, b.w)));
#pragma unroll
    for (int o = 16; o > 0; o >>= 1) m = fmaxf(m, __shfl_xor_sync(0xffffffffu, m, o));
    if ((tid & 31) == 0) red[tid >> 5] = m;
    __syncthreads();
    if (tid == 0) {
        float mm = red[0];
#pragma unroll
        for (int w = 1; w < 8; w++) mm = fmaxf(mm, red[w]);
        bcast = mm;
    }
    __syncthreads();
    m = bcast;
    __syncthreads();

    a.x = __expf(a.x - m); a.y = __expf(a.y - m);
    a.z = __expf(a.z - m); a.w = __expf(a.w - m);
    b.x = __expf(b.x - m); b.y = __expf(b.y - m);
    b.z = __expf(b.z - m); b.w = __expf(b.w - m);

    float s = (a.x + a.y) + (a.z + a.w) + (b.x + b.y) + (b.z + b.w);
#pragma unroll
    for (int o = 16; o > 0; o >>= 1) s += __shfl_xor_sync(0xffffffffu, s, o);
    if ((tid & 31) == 0) red[tid >> 5] = s;
    __syncthreads();
    if (tid == 0) {
        float ss = 0.f;
#pragma unroll
        for (int w = 0; w < 8; w++) ss += red[w];
        bcast = ss;
    }
    __syncthreads();
    s = bcast;

    float inv = 1.0f / s;
    a.x *= inv; a.y *= inv; a.z *= inv; a.w *= inv;
    b.x *= inv; b.y *= inv; b.z *= inv; b.w *= inv;

    reinterpret_cast<float4*>(p)[tid]       = a;
    reinterpret_cast<float4*>(p)[tid + 256] = b;

    uint2 h0, l0, h1, l1;
    split4_f16(a, h0, l0);
    split4_f16(b, h1, l1);
    f16* phr = ph + row * (long)LK_;
    f16* plr = pl + row * (long)LK_;
    reinterpret_cast<uint2*>(phr)[tid]       = h0;
    reinterpret_cast<uint2*>(plr)[tid]       = l0;
    reinterpret_cast<uint2*>(phr)[tid + 256] = h1;
    reinterpret_cast<uint2*>(plr)[tid + 256] = l1;
}

// ============================ launch ============================
extern "C" void kernel_launch(void* const* d_in, const int* in_sizes, int n_in,
                              void* d_out, int out_size)
{
    const float* key   = (const float*)d_in[0];
    const float* query = (const float*)d_in[1];
    const int*   mask  = (const int*)d_in[2];
    const float* Wq    = (const float*)d_in[3];
    const float* bq    = (const float*)d_in[4];
    const float* Wk    = (const float*)d_in[5];
    const float* bk    = (const float*)d_in[6];
    const float* Wv    = (const float*)d_in[7];
    const float* bv    = (const float*)d_in[8];

    float* out   = (float*)d_out;                         // [B, LQ, D]
    float* score = out + (size_t)B_ * LQ_ * DIM_;         // [B, LQ, LK]

    bf16 *xqh, *xql, *xkh, *xkl, *wqh, *wql, *wkh, *wkl, *wvh, *wvl, *kh, *kl;
    f16 *q16h, *q16l, *k16, *vt16, *ph, *pl;
    float* vbuf;
    cudaGetSymbolAddress((void**)&xqh, g_xqh); cudaGetSymbolAddress((void**)&xql, g_xql);
    cudaGetSymbolAddress((void**)&xkh, g_xkh); cudaGetSymbolAddress((void**)&xkl, g_xkl);
    cudaGetSymbolAddress((void**)&wqh, g_wqh); cudaGetSymbolAddress((void**)&wql, g_wql);
    cudaGetSymbolAddress((void**)&wkh, g_wkh); cudaGetSymbolAddress((void**)&wkl, g_wkl);
    cudaGetSymbolAddress((void**)&wvh, g_wvh); cudaGetSymbolAddress((void**)&wvl, g_wvl);
    cudaGetSymbolAddress((void**)&q16h, g_q16h); cudaGetSymbolAddress((void**)&q16l, g_q16l);
    cudaGetSymbolAddress((void**)&kh, g_kh);   cudaGetSymbolAddress((void**)&kl, g_kl);
    cudaGetSymbolAddress((void**)&k16, g_k16);
    cudaGetSymbolAddress((void**)&vt16, g_vt16);
    cudaGetSymbolAddress((void**)&ph, g_ph);   cudaGetSymbolAddress((void**)&pl, g_pl);
    cudaGetSymbolAddress((void**)&vbuf, g_v);

    cudaFuncSetAttribute(gemm_hl<1,0>, cudaFuncAttributeMaxDynamicSharedMemorySize, SMEM_B3);
    cudaFuncSetAttribute(gemm_hl<1,2>, cudaFuncAttributeMaxDynamicSharedMemorySize, SMEM_B3);
    cudaFuncSetAttribute(gemm_hl<1,3>, cudaFuncAttributeMaxDynamicSharedMemorySize, SMEM_B3);
    cudaFuncSetAttribute(gemm_f16<0>,  cudaFuncAttributeMaxDynamicSharedMemorySize, SMEM_F16);
    cudaFuncSetAttribute(gemm_f16<2>,  cudaFuncAttributeMaxDynamicSharedMemorySize, SMEM_F16);

    dim3 blk(NTH);
    const float scale = 0.03125f;  // 1/sqrt(1024)
    const long NBIG4 = (long)NE_BIG / 4;
    const long NW4 = (long)DIM_ * DIM_ / 4;
    const unsigned GB = (unsigned)((NBIG4 + 255) / 256);
    const unsigned GW = (unsigned)((NW4 + 255) / 256);

    // order chosen so ncu's -s 5 lands on a projection GEMM
    cvt_hl<<<GB, 256>>>(query, xqh, xql, NBIG4);                     // 0
    cvt_hl<<<GW, 256>>>(Wq, wqh, wql, NW4);                          // 1
    {   // 2: q = query @ Wq^T + bq -> fp16 hi/lo
        dim3 g(DIM_ / BN, (B_ * LQ_) / BM, 1);
        gemm_hl<1,3><<<g, blk, SMEM_B3>>>(xqh, xql, wqh, wql,
                                          q16h, q16l, nullptr, DIM_, DIM_, bq);
    }
    cvt_hl<<<GB, 256>>>(key, xkh, xkl, NBIG4);                       // 3
    cvt_hl<<<GW, 256>>>(Wk, wkh, wkl, NW4);                          // 4
    {   // 5: k = key @ Wk^T + bk -> bf16 hi/lo + fp16 single
        dim3 g(DIM_ / BN, (B_ * LK_) / BM, 1);
        gemm_hl<1,2><<<g, blk, SMEM_B3>>>(xkh, xkl, wkh, wkl,
                                          kh, kl, k16, DIM_, DIM_, bk);
    }
    cvt_hl<<<GW, 256>>>(Wv, wvh, wvl, NW4);                          // 6
    {   // 7: v = k_proj @ Wv^T + bv -> fp32
        dim3 g(DIM_ / BN, (B_ * LK_) / BM, 1);
        gemm_hl<1,0><<<g, blk, SMEM_B3>>>(kh, kl, wvh, wvl,
                                          vbuf, nullptr, nullptr, DIM_, DIM_, bv);
    }
    {   // 8: score_raw = (q @ k^T) * scale, masked (fp16 2-prod, batched)
        dim3 g(LK_ / BN, LQ_ / BM, B_);
        gemm_f16<2><<<g, blk, SMEM_F16>>>(q16h, q16l, k16, score,
                                          LK_, DIM_, (long)LQ_ * DIM_,
                                          (long)LK_ * DIM_, (long)LQ_ * LK_,
                                          mask, LK_, scale);
    }
    {   // 9: vT fp16
        dim3 g(LK_ / 32, DIM_ / 32, B_);
        transpose_f16<<<g, 256>>>(vbuf, vt16);
    }
    // 10: softmax rows in place + P fp16 hi/lo
    softmax_kernel<<<B_ * LQ_, 256>>>(score, ph, pl);
    {   // 11: output = P @ V (fp16 2-prod, batched NT, K = LK)
        dim3 g(DIM_ / BN, LQ_ / BM, B_);
        gemm_f16<0><<<g, blk, SMEM_F16>>>(ph, pl, vt16, out,
                                          DIM_, LK_, (long)LQ_ * LK_,
                                          (long)DIM_ * LK_, (long)LQ_ * DIM_,
                                          nullptr, 0, 1.f);
    }
}

// round 9
// speedup vs baseline: 1.4060x; 1.1565x over previous
#include <cuda_runtime.h>
#include <cuda_fp16.h>
#include <cstdint>

// Problem constants: B=8, LQ=LK=2048, D=1024
#define B_   8
#define LQ_  2048
#define LK_  2048
#define DIM_ 1024

typedef __half f16;

// ---------------- device scratch (allocation-free rule) ----------------
#define NE_BIG ((size_t)B_ * LQ_ * DIM_)      // 16M
#define NE_P   ((size_t)B_ * LQ_ * LK_)       // 32M
__device__ f16  g_xqh[NE_BIG], g_xql[NE_BIG];   // query split fp16
__device__ f16  g_xkh[NE_BIG], g_xkl[NE_BIG];   // key split fp16
__device__ f16  g_wq16[DIM_*DIM_];
__device__ f16  g_wk16[DIM_*DIM_];
__device__ f16  g_wv16[DIM_*DIM_];
__device__ f16  g_q16h[NE_BIG], g_q16l[NE_BIG]; // q proj fp16 hi/lo
__device__ f16  g_k16h[NE_BIG], g_k16l[NE_BIG]; // k proj fp16 hi/lo (hi = score B)
__device__ float g_v[NE_BIG];                   // v proj fp32
__device__ f16  g_vt16[NE_BIG];                 // v transposed fp16 [B,D,LK]
__device__ f16  g_ph[NE_P], g_pl[NE_P];         // softmax(P) fp16 hi/lo

// ============================ helpers ============================
__device__ __forceinline__ uint32_t smem_u32(const void* p) {
    uint32_t a;
    asm("{ .reg .u64 t; cvta.to.shared.u64 t, %1; cvt.u32.u64 %0, t; }" : "=r"(a) : "l"(p));
    return a;
}
__device__ __forceinline__ void ldm_x4(uint32_t* r, uint32_t addr) {
    asm volatile("ldmatrix.sync.aligned.m8n8.x4.shared.b16 {%0,%1,%2,%3}, [%4];"
        : "=r"(r[0]), "=r"(r[1]), "=r"(r[2]), "=r"(r[3]) : "r"(addr));
}
__device__ __forceinline__ void mma_f16(float* d, const uint32_t* a, const uint32_t* b) {
    asm volatile(
        "mma.sync.aligned.m16n8k16.row.col.f32.f16.f16.f32 "
        "{%0,%1,%2,%3}, {%4,%5,%6,%7}, {%8,%9}, {%0,%1,%2,%3};"
        : "+f"(d[0]), "+f"(d[1]), "+f"(d[2]), "+f"(d[3])
        : "r"(a[0]), "r"(a[1]), "r"(a[2]), "r"(a[3]), "r"(b[0]), "r"(b[1]));
}
__device__ __forceinline__ uint32_t pack_h2(f16 a, f16 b) {
    __half2 t(a, b);
    return *reinterpret_cast<uint32_t*>(&t);
}
__device__ __forceinline__ void cp16(uint32_t dst, const void* src) {
    asm volatile("cp.async.cg.shared.global [%0], [%1], 16;" :: "r"(dst), "l"(src));
}
#define CP_COMMIT() asm volatile("cp.async.commit_group;" ::: "memory")
#define CP_WAIT1()  asm volatile("cp.async.wait_group 1;" ::: "memory")

// [row][k] 16-bit tile, 64B rows, 16B-chunk XOR swizzle (conflict-free ldmatrix)
__device__ __forceinline__ uint32_t swoff(uint32_t row, uint32_t k) {
    uint32_t c = (k >> 3) ^ ((row >> 1) & 3u);
    return row * 64u + c * 16u + (k & 7u) * 2u;
}

__device__ __forceinline__ void split4_f16(float4 t, uint2& h, uint2& l) {
    f16 hx = __float2half_rn(t.x);
    f16 hy = __float2half_rn(t.y);
    f16 hz = __float2half_rn(t.z);
    f16 hw = __float2half_rn(t.w);
    h.x = pack_h2(hx, hy); h.y = pack_h2(hz, hw);
    l.x = pack_h2(__float2half_rn(t.x - __half2float(hx)),
                  __float2half_rn(t.y - __half2float(hy)));
    l.y = pack_h2(__float2half_rn(t.z - __half2float(hz)),
                  __float2half_rn(t.w - __half2float(hw)));
}

// ===================== fp16 2-product GEMM =====================
// C[M,N] = (Ah+Al)[M,K] * B[N,K]^T, fp16 frags, fp32 accum.
// 128x128x32 tile, 8 warps (2M x 4N), 2 CTAs/SM, 3-stage cp.async.
// EPI: 0 none, 1 +bias[n], 2 mask[n]==0 ? -1e9 : acc*scale
// OUT: 0 fp32 -> p0 ; 1 fp16 hi/lo -> p0,p1
#define BM 128
#define BN 128
#define BK 32
#define NTH 256
#define NSTAGES 3
#define F_OFF_AH 0
#define F_OFF_AL 8192
#define F_OFF_B  16384
#define F_STG    24576
#define SMEM_F16 (NSTAGES * F_STG)

__device__ __forceinline__ void stage_load_f16(uint32_t st,
    const f16* __restrict__ pAh, const f16* __restrict__ pAl,
    const f16* __restrict__ pB, int K_, int k0, int tid)
{
#pragma unroll
    for (int i = 0; i < 2; i++) {
        int c = tid + i * NTH;
        int row = c >> 2;
        int kc = (c & 3) * 8;
        uint32_t off = swoff((uint32_t)row, (uint32_t)kc);
        long g = (long)row * K_ + k0 + kc;
        cp16(st + F_OFF_AH + off, pAh + g);
        cp16(st + F_OFF_AL + off, pAl + g);
        cp16(st + F_OFF_B  + off, pB  + g);
    }
}

template <int EPI, int OUT>
__global__ __launch_bounds__(NTH, 2)
void gemm_f16(const f16* __restrict__ Ah, const f16* __restrict__ Al,
              const f16* __restrict__ Bm,
              void* __restrict__ p0, void* __restrict__ p1,
              int N_, int K_, long sA, long sB, long sC,
              const float* __restrict__ bias,
              const int* __restrict__ mask, long sMask, float scale)
{
    extern __shared__ char sm[];
    const uint32_t smb = smem_u32(sm);

    const int tid = threadIdx.x;
    const int lane = tid & 31;
    const int wid = tid >> 5;
    const int wm = wid & 1;
    const int wn = wid >> 1;

    const int bz = blockIdx.z;
    const int m0 = blockIdx.y * BM;
    const int n0 = blockIdx.x * BN;

    const f16* pAh = Ah + (long)bz * sA + (long)m0 * K_;
    const f16* pAl = Al + (long)bz * sA + (long)m0 * K_;
    const f16* pB  = Bm + (long)bz * sB + (long)n0 * K_;

    const uint32_t a_row  = (uint32_t)(wm * 64 + (lane & 15));
    const uint32_t a_cadd = (uint32_t)(lane >> 4);
    const uint32_t b_row  = (uint32_t)(wn * 32 + (lane & 7) + ((lane >> 4) << 3));
    const uint32_t b_cadd = (uint32_t)((lane >> 3) & 1);

    float acc[4][4][4];
#pragma unroll
    for (int i = 0; i < 4; i++)
#pragma unroll
        for (int j = 0; j < 4; j++)
#pragma unroll
            for (int l = 0; l < 4; l++) acc[i][j][l] = 0.f;

    const int nkt = K_ / BK;

#pragma unroll
    for (int s = 0; s < NSTAGES - 1; s++) {
        stage_load_f16(smb + s * F_STG, pAh, pAl, pB, K_, s * BK, tid);
        CP_COMMIT();
    }

    for (int kt = 0; kt < nkt; kt++) {
        CP_WAIT1();
        __syncthreads();
        const uint32_t curb = smb + (uint32_t)(kt % NSTAGES) * F_STG;

        const int pf = kt + NSTAGES - 1;
        if (pf < nkt)
            stage_load_f16(smb + (uint32_t)(pf % NSTAGES) * F_STG, pAh, pAl, pB,
                           K_, pf * BK, tid);
        CP_COMMIT();

#pragma unroll
        for (int ks = 0; ks < 2; ks++) {
            const uint32_t c0 = (uint32_t)(ks * 2);
            uint32_t ah[4][4], bb[2][4];
#pragma unroll
            for (int mf = 0; mf < 4; mf++)
                ldm_x4(ah[mf], curb + F_OFF_AH + swoff(a_row + mf * 16, (c0 + a_cadd) * 8));
#pragma unroll
            for (int np = 0; np < 2; np++)
                ldm_x4(bb[np], curb + F_OFF_B + swoff(b_row + np * 16, (c0 + b_cadd) * 8));
#pragma unroll
            for (int mf = 0; mf < 4; mf++)
#pragma unroll
                for (int nf = 0; nf < 4; nf++)
                    mma_f16(acc[mf][nf], ah[mf], &bb[nf >> 1][(nf & 1) * 2]);
            {
                uint32_t al[4][4];
#pragma unroll
                for (int mf = 0; mf < 4; mf++)
                    ldm_x4(al[mf], curb + F_OFF_AL + swoff(a_row + mf * 16, (c0 + a_cadd) * 8));
#pragma unroll
                for (int mf = 0; mf < 4; mf++)
#pragma unroll
                    for (int nf = 0; nf < 4; nf++)
                        mma_f16(acc[mf][nf], al[mf], &bb[nf >> 1][(nf & 1) * 2]);
            }
        }
    }

    // ---- epilogue ----
#pragma unroll
    for (int mf = 0; mf < 4; mf++) {
        const int r0 = m0 + wm * 64 + mf * 16 + (lane >> 2);
#pragma unroll
        for (int half = 0; half < 2; half++) {
            const long r = r0 + half * 8;
#pragma unroll
            for (int nf = 0; nf < 4; nf++) {
                const int n = n0 + wn * 32 + nf * 8 + (lane & 3) * 2;
                float v0 = acc[mf][nf][half * 2 + 0];
                float v1 = acc[mf][nf][half * 2 + 1];
                if (EPI == 1) { v0 += bias[n]; v1 += bias[n + 1]; }
                if (EPI == 2) {
                    int mv0 = mask[bz * sMask + n];
                    int mv1 = mask[bz * sMask + n + 1];
                    v0 = (mv0 == 0) ? -1e9f : v0 * scale;
                    v1 = (mv1 == 0) ? -1e9f : v1 * scale;
                }
                if (OUT == 0) {
                    float2 o = { v0, v1 };
                    *reinterpret_cast<float2*>((float*)p0 + ((long)bz * sC + r * N_ + n)) = o;
                } else {
                    f16 h0 = __float2half_rn(v0);
                    f16 h1 = __float2half_rn(v1);
                    long o = (long)bz * sC + r * N_ + n;
                    *reinterpret_cast<uint32_t*>((f16*)p0 + o) = pack_h2(h0, h1);
                    *reinterpret_cast<uint32_t*>((f16*)p1 + o) =
                        pack_h2(__float2half_rn(v0 - __half2float(h0)),
                                __float2half_rn(v1 - __half2float(h1)));
                }
            }
        }
    }
}

// ---------------- convert fp32 -> fp16 hi/lo ----------------
__global__ __launch_bounds__(256)
void cvt_hl_f16(const float* __restrict__ in, f16* __restrict__ h,
                f16* __restrict__ l, long n4)
{
    long i = (long)blockIdx.x * blockDim.x + threadIdx.x;
    if (i >= n4) return;
    float4 t = reinterpret_cast<const float4*>(in)[i];
    uint2 hh, ll;
    split4_f16(t, hh, ll);
    reinterpret_cast<uint2*>(h)[i] = hh;
    reinterpret_cast<uint2*>(l)[i] = ll;
}

// ---------------- convert fp32 -> fp16 single ----------------
__global__ __launch_bounds__(256)
void cvt_f16(const float* __restrict__ in, f16* __restrict__ h, long n4)
{
    long i = (long)blockIdx.x * blockDim.x + threadIdx.x;
    if (i >= n4) return;
    float4 t = reinterpret_cast<const float4*>(in)[i];
    uint2 hh = { pack_h2(__float2half_rn(t.x), __float2half_rn(t.y)),
                 pack_h2(__float2half_rn(t.z), __float2half_rn(t.w)) };
    reinterpret_cast<uint2*>(h)[i] = hh;
}

// ---------------- transpose v[B,LK,D] fp32 -> vT fp16 [B,D,LK] ----------------
__global__ __launch_bounds__(256)
void transpose_f16(const float* __restrict__ in, f16* __restrict__ oh)
{
    __shared__ float t[32][33];
    const int b = blockIdx.z;
    const int lk0 = blockIdx.x * 32;
    const int d0 = blockIdx.y * 32;
    const float* ib = in + (size_t)b * LK_ * DIM_;
    f16* ohb = oh + (size_t)b * DIM_ * LK_;
    const int tx = threadIdx.x & 31;
    const int ty = threadIdx.x >> 5;
#pragma unroll
    for (int i = 0; i < 32; i += 8)
        t[ty + i][tx] = ib[(size_t)(lk0 + ty + i) * DIM_ + d0 + tx];
    __syncthreads();
#pragma unroll
    for (int i = 0; i < 32; i += 8)
        ohb[(size_t)(d0 + ty + i) * LK_ + lk0 + tx] = __float2half_rn(t[tx][ty + i]);
}

// ---------------- softmax + emit P fp16 hi/lo ----------------
__global__ __launch_bounds__(256)
void softmax_kernel(float* __restrict__ score, f16* __restrict__ ph,
                    f16* __restrict__ pl)
{
    __shared__ float red[8];
    __shared__ float bcast;

    const long row = blockIdx.x;
    float* p = score + row * (long)LK_;
    const int tid = threadIdx.x;

    float4 a = reinterpret_cast<const float4*>(p)[tid];
    float4 b = reinterpret_cast<const float4*>(p)[tid + 256];

    float m = fmaxf(fmaxf(fmaxf(a.x, a.y), fmaxf(a.z, a.w)),
                    fmaxf(fmaxf(b.x, b.y), fmaxf(b.z, b.w)));
#pragma unroll
    for (int o = 16; o > 0; o >>= 1) m = fmaxf(m, __shfl_xor_sync(0xffffffffu, m, o));
    if ((tid & 31) == 0) red[tid >> 5] = m;
    __syncthreads();
    if (tid == 0) {
        float mm = red[0];
#pragma unroll
        for (int w = 1; w < 8; w++) mm = fmaxf(mm, red[w]);
        bcast = mm;
    }
    __syncthreads();
    m = bcast;
    __syncthreads();

    a.x = __expf(a.x - m); a.y = __expf(a.y - m);
    a.z = __expf(a.z - m); a.w = __expf(a.w - m);
    b.x = __expf(b.x - m); b.y = __expf(b.y - m);
    b.z = __expf(b.z - m); b.w = __expf(b.w - m);

    float s = (a.x + a.y) + (a.z + a.w) + (b.x + b.y) + (b.z + b.w);
#pragma unroll
    for (int o = 16; o > 0; o >>= 1) s += __shfl_xor_sync(0xffffffffu, s, o);
    if ((tid & 31) == 0) red[tid >> 5] = s;
    __syncthreads();
    if (tid == 0) {
        float ss = 0.f;
#pragma unroll
        for (int w = 0; w < 8; w++) ss += red[w];
        bcast = ss;
    }
    __syncthreads();
    s = bcast;

    float inv = 1.0f / s;
    a.x *= inv; a.y *= inv; a.z *= inv; a.w *= inv;
    b.x *= inv; b.y *= inv; b.z *= inv; b.w *= inv;

    reinterpret_cast<float4*>(p)[tid]       = a;
    reinterpret_cast<float4*>(p)[tid + 256] = b;

    uint2 h0, l0, h1, l1;
    split4_f16(a, h0, l0);
    split4_f16(b, h1, l1);
    f16* phr = ph + row * (long)LK_;
    f16* plr = pl + row * (long)LK_;
    reinterpret_cast<uint2*>(phr)[tid]       = h0;
    reinterpret_cast<uint2*>(plr)[tid]       = l0;
    reinterpret_cast<uint2*>(phr)[tid + 256] = h1;
    reinterpret_cast<uint2*>(plr)[tid + 256] = l1;
}

// ============================ launch ============================
extern "C" void kernel_launch(void* const* d_in, const int* in_sizes, int n_in,
                              void* d_out, int out_size)
{
    const float* key   = (const float*)d_in[0];
    const float* query = (const float*)d_in[1];
    const int*   mask  = (const int*)d_in[2];
    const float* Wq    = (const float*)d_in[3];
    const float* bq    = (const float*)d_in[4];
    const float* Wk    = (const float*)d_in[5];
    const float* bk    = (const float*)d_in[6];
    const float* Wv    = (const float*)d_in[7];
    const float* bv    = (const float*)d_in[8];

    float* out   = (float*)d_out;                         // [B, LQ, D]
    float* score = out + (size_t)B_ * LQ_ * DIM_;         // [B, LQ, LK]

    f16 *xqh, *xql, *xkh, *xkl, *wq16, *wk16, *wv16;
    f16 *q16h, *q16l, *k16h, *k16l, *vt16, *ph, *pl;
    float* vbuf;
    cudaGetSymbolAddress((void**)&xqh, g_xqh);   cudaGetSymbolAddress((void**)&xql, g_xql);
    cudaGetSymbolAddress((void**)&xkh, g_xkh);   cudaGetSymbolAddress((void**)&xkl, g_xkl);
    cudaGetSymbolAddress((void**)&wq16, g_wq16);
    cudaGetSymbolAddress((void**)&wk16, g_wk16);
    cudaGetSymbolAddress((void**)&wv16, g_wv16);
    cudaGetSymbolAddress((void**)&q16h, g_q16h); cudaGetSymbolAddress((void**)&q16l, g_q16l);
    cudaGetSymbolAddress((void**)&k16h, g_k16h); cudaGetSymbolAddress((void**)&k16l, g_k16l);
    cudaGetSymbolAddress((void**)&vt16, g_vt16);
    cudaGetSymbolAddress((void**)&ph, g_ph);     cudaGetSymbolAddress((void**)&pl, g_pl);
    cudaGetSymbolAddress((void**)&vbuf, g_v);

    cudaFuncSetAttribute(gemm_f16<0,0>, cudaFuncAttributeMaxDynamicSharedMemorySize, SMEM_F16);
    cudaFuncSetAttribute(gemm_f16<1,0>, cudaFuncAttributeMaxDynamicSharedMemorySize, SMEM_F16);
    cudaFuncSetAttribute(gemm_f16<1,1>, cudaFuncAttributeMaxDynamicSharedMemorySize, SMEM_F16);
    cudaFuncSetAttribute(gemm_f16<2,0>, cudaFuncAttributeMaxDynamicSharedMemorySize, SMEM_F16);

    dim3 blk(NTH);
    const float scale = 0.03125f;  // 1/sqrt(1024)
    const long NBIG4 = (long)NE_BIG / 4;
    const long NW4 = (long)DIM_ * DIM_ / 4;
    const unsigned GB = (unsigned)((NBIG4 + 255) / 256);
    const unsigned GW = (unsigned)((NW4 + 255) / 256);

    // 0-2: q path
    cvt_hl_f16<<<GB, 256>>>(query, xqh, xql, NBIG4);
    cvt_f16<<<GW, 256>>>(Wq, wq16, NW4);
    {   // q = query @ Wq^T + bq -> fp16 hi/lo
        dim3 g(DIM_ / BN, (B_ * LQ_) / BM, 1);
        gemm_f16<1,1><<<g, blk, SMEM_F16>>>(xqh, xql, wq16, q16h, q16l,
                                            DIM_, DIM_, 0, 0, 0, bq, nullptr, 0, 1.f);
    }
    // 3-5: k path
    cvt_hl_f16<<<GB, 256>>>(key, xkh, xkl, NBIG4);
    cvt_f16<<<GW, 256>>>(Wk, wk16, NW4);
    {   // k = key @ Wk^T + bk -> fp16 hi/lo (hi doubles as score-B)
        dim3 g(DIM_ / BN, (B_ * LK_) / BM, 1);
        gemm_f16<1,1><<<g, blk, SMEM_F16>>>(xkh, xkl, wk16, k16h, k16l,
                                            DIM_, DIM_, 0, 0, 0, bk, nullptr, 0, 1.f);
    }
    // 6-7: v path (A = k fp16 hi/lo, B = Wv fp16)
    cvt_f16<<<GW, 256>>>(Wv, wv16, NW4);
    {   // v = k_proj @ Wv^T + bv -> fp32
        dim3 g(DIM_ / BN, (B_ * LK_) / BM, 1);
        gemm_f16<1,0><<<g, blk, SMEM_F16>>>(k16h, k16l, wv16, vbuf, nullptr,
                                            DIM_, DIM_, 0, 0, 0, bv, nullptr, 0, 1.f);
    }
    // 8: score_raw = (q @ k^T) * scale, masked (batched)
    {
        dim3 g(LK_ / BN, LQ_ / BM, B_);
        gemm_f16<2,0><<<g, blk, SMEM_F16>>>(q16h, q16l, k16h, score, nullptr,
                                            LK_, DIM_, (long)LQ_ * DIM_,
                                            (long)LK_ * DIM_, (long)LQ_ * LK_,
                                            nullptr, mask, LK_, scale);
    }
    // 9: vT fp16
    {
        dim3 g(LK_ / 32, DIM_ / 32, B_);
        transpose_f16<<<g, 256>>>(vbuf, vt16);
    }
    // 10: softmax rows in place + P fp16 hi/lo
    softmax_kernel<<<B_ * LQ_, 256>>>(score, ph, pl);
    // 11: output = P @ V (batched NT, K = LK)
    {
        dim3 g(DIM_ / BN, LQ_ / BM, B_);
        gemm_f16<0,0><<<g, blk, SMEM_F16>>>(ph, pl, vt16, out, nullptr,
                                            DIM_, LK_, (long)LQ_ * LK_,
                                            (long)DIM_ * LK_, (long)LQ_ * DIM_,
                                            nullptr, nullptr, 0, 1.f);
    }
}

// round 10
// speedup vs baseline: 1.6023x; 1.1396x over previous
#include <cuda_runtime.h>
#include <cuda_fp16.h>
#include <cstdint>

// Problem constants: B=8, LQ=LK=2048, D=1024
#define B_   8
#define LQ_  2048
#define LK_  2048
#define DIM_ 1024

typedef __half f16;

// ---------------- device scratch (allocation-free rule) ----------------
#define NE_BIG ((size_t)B_ * LQ_ * DIM_)      // 16M
#define NE_P   ((size_t)B_ * LQ_ * LK_)       // 32M
__device__ f16  g_xqh[NE_BIG], g_xql[NE_BIG];   // query split fp16
__device__ f16  g_xkh[NE_BIG], g_xkl[NE_BIG];   // key split fp16
__device__ f16  g_wq16[DIM_*DIM_];
__device__ f16  g_wk16[DIM_*DIM_];
__device__ f16  g_wv16[DIM_*DIM_];
__device__ f16  g_q16h[NE_BIG], g_q16l[NE_BIG]; // q proj fp16 hi/lo
__device__ f16  g_k16h[NE_BIG], g_k16l[NE_BIG]; // k proj fp16 hi/lo (hi = score B)
__device__ float g_v[NE_BIG];                   // v proj fp32
__device__ f16  g_vt16[NE_BIG];                 // v transposed fp16 [B,D,LK]
__device__ f16  g_ph[NE_P];                     // softmax(P) fp16 (single)

// ============================ helpers ============================
__device__ __forceinline__ uint32_t smem_u32(const void* p) {
    uint32_t a;
    asm("{ .reg .u64 t; cvta.to.shared.u64 t, %1; cvt.u32.u64 %0, t; }" : "=r"(a) : "l"(p));
    return a;
}
__device__ __forceinline__ void ldm_x4(uint32_t* r, uint32_t addr) {
    asm volatile("ldmatrix.sync.aligned.m8n8.x4.shared.b16 {%0,%1,%2,%3}, [%4];"
        : "=r"(r[0]), "=r"(r[1]), "=r"(r[2]), "=r"(r[3]) : "r"(addr));
}
__device__ __forceinline__ void mma_f16(float* d, const uint32_t* a, const uint32_t* b) {
    asm volatile(
        "mma.sync.aligned.m16n8k16.row.col.f32.f16.f16.f32 "
        "{%0,%1,%2,%3}, {%4,%5,%6,%7}, {%8,%9}, {%0,%1,%2,%3};"
        : "+f"(d[0]), "+f"(d[1]), "+f"(d[2]), "+f"(d[3])
        : "r"(a[0]), "r"(a[1]), "r"(a[2]), "r"(a[3]), "r"(b[0]), "r"(b[1]));
}
__device__ __forceinline__ uint32_t pack_h2(f16 a, f16 b) {
    __half2 t(a, b);
    return *reinterpret_cast<uint32_t*>(&t);
}
__device__ __forceinline__ void cp16(uint32_t dst, const void* src) {
    asm volatile("cp.async.cg.shared.global [%0], [%1], 16;" :: "r"(dst), "l"(src));
}
#define CP_COMMIT() asm volatile("cp.async.commit_group;" ::: "memory")
#define CP_WAIT1()  asm volatile("cp.async.wait_group 1;" ::: "memory")

// [row][k] 16-bit tile, 64B rows, 16B-chunk XOR swizzle (conflict-free ldmatrix)
__device__ __forceinline__ uint32_t swoff(uint32_t row, uint32_t k) {
    uint32_t c = (k >> 3) ^ ((row >> 1) & 3u);
    return row * 64u + c * 16u + (k & 7u) * 2u;
}

__device__ __forceinline__ void split4_f16(float4 t, uint2& h, uint2& l) {
    f16 hx = __float2half_rn(t.x);
    f16 hy = __float2half_rn(t.y);
    f16 hz = __float2half_rn(t.z);
    f16 hw = __float2half_rn(t.w);
    h.x = pack_h2(hx, hy); h.y = pack_h2(hz, hw);
    l.x = pack_h2(__float2half_rn(t.x - __half2float(hx)),
                  __float2half_rn(t.y - __half2float(hy)));
    l.y = pack_h2(__float2half_rn(t.z - __half2float(hz)),
                  __float2half_rn(t.w - __half2float(hw)));
}

// ===================== fp16 GEMM (1 or 2 product) =====================
// C[M,N] = (Ah [+ Al])[M,K] * B[N,K]^T, fp16 frags, fp32 accum.
// 128x128x32 tile, 8 warps (2M x 4N), 2 CTAs/SM, 3-stage cp.async.
// EPI: 0 none, 1 +bias[n], 2 mask[n]==0 ? -1e9 : acc*scale
// OUT: 0 fp32 -> p0 ; 1 fp16 hi/lo -> p0,p1
// NPROD: 1 (A single) or 2 (A hi/lo)
#define BM 128
#define BN 128
#define BK 32
#define NTH 256
#define NSTAGES 3
#define F_OFF_AH 0
#define F_OFF_AL 8192
#define F_OFF_B  16384
#define F_STG    24576
#define SMEM_F16 (NSTAGES * F_STG)

template <int NPROD>
__device__ __forceinline__ void stage_load_f16(uint32_t st,
    const f16* __restrict__ pAh, const f16* __restrict__ pAl,
    const f16* __restrict__ pB, int K_, int k0, int tid)
{
#pragma unroll
    for (int i = 0; i < 2; i++) {
        int c = tid + i * NTH;
        int row = c >> 2;
        int kc = (c & 3) * 8;
        uint32_t off = swoff((uint32_t)row, (uint32_t)kc);
        long g = (long)row * K_ + k0 + kc;
        cp16(st + F_OFF_AH + off, pAh + g);
        if (NPROD == 2) cp16(st + F_OFF_AL + off, pAl + g);
        cp16(st + F_OFF_B  + off, pB  + g);
    }
}

template <int EPI, int OUT, int NPROD>
__global__ __launch_bounds__(NTH, 2)
void gemm_f16(const f16* __restrict__ Ah, const f16* __restrict__ Al,
              const f16* __restrict__ Bm,
              void* __restrict__ p0, void* __restrict__ p1,
              int N_, int K_, long sA, long sB, long sC,
              const float* __restrict__ bias,
              const int* __restrict__ mask, long sMask, float scale)
{
    extern __shared__ char sm[];
    const uint32_t smb = smem_u32(sm);

    const int tid = threadIdx.x;
    const int lane = tid & 31;
    const int wid = tid >> 5;
    const int wm = wid & 1;
    const int wn = wid >> 1;

    const int bz = blockIdx.z;
    const int m0 = blockIdx.y * BM;
    const int n0 = blockIdx.x * BN;

    const f16* pAh = Ah + (long)bz * sA + (long)m0 * K_;
    const f16* pAl = (NPROD == 2) ? Al + (long)bz * sA + (long)m0 * K_ : nullptr;
    const f16* pB  = Bm + (long)bz * sB + (long)n0 * K_;

    const uint32_t a_row  = (uint32_t)(wm * 64 + (lane & 15));
    const uint32_t a_cadd = (uint32_t)(lane >> 4);
    const uint32_t b_row  = (uint32_t)(wn * 32 + (lane & 7) + ((lane >> 4) << 3));
    const uint32_t b_cadd = (uint32_t)((lane >> 3) & 1);

    float acc[4][4][4];
#pragma unroll
    for (int i = 0; i < 4; i++)
#pragma unroll
        for (int j = 0; j < 4; j++)
#pragma unroll
            for (int l = 0; l < 4; l++) acc[i][j][l] = 0.f;

    const int nkt = K_ / BK;

#pragma unroll
    for (int s = 0; s < NSTAGES - 1; s++) {
        stage_load_f16<NPROD>(smb + s * F_STG, pAh, pAl, pB, K_, s * BK, tid);
        CP_COMMIT();
    }

    for (int kt = 0; kt < nkt; kt++) {
        CP_WAIT1();
        __syncthreads();
        const uint32_t curb = smb + (uint32_t)(kt % NSTAGES) * F_STG;

        const int pf = kt + NSTAGES - 1;
        if (pf < nkt)
            stage_load_f16<NPROD>(smb + (uint32_t)(pf % NSTAGES) * F_STG, pAh, pAl, pB,
                                  K_, pf * BK, tid);
        CP_COMMIT();

#pragma unroll
        for (int ks = 0; ks < 2; ks++) {
            const uint32_t c0 = (uint32_t)(ks * 2);
            uint32_t ah[4][4], bb[2][4];
#pragma unroll
            for (int mf = 0; mf < 4; mf++)
                ldm_x4(ah[mf], curb + F_OFF_AH + swoff(a_row + mf * 16, (c0 + a_cadd) * 8));
#pragma unroll
            for (int np = 0; np < 2; np++)
                ldm_x4(bb[np], curb + F_OFF_B + swoff(b_row + np * 16, (c0 + b_cadd) * 8));
#pragma unroll
            for (int mf = 0; mf < 4; mf++)
#pragma unroll
                for (int nf = 0; nf < 4; nf++)
                    mma_f16(acc[mf][nf], ah[mf], &bb[nf >> 1][(nf & 1) * 2]);
            if (NPROD == 2) {
                uint32_t al[4][4];
#pragma unroll
                for (int mf = 0; mf < 4; mf++)
                    ldm_x4(al[mf], curb + F_OFF_AL + swoff(a_row + mf * 16, (c0 + a_cadd) * 8));
#pragma unroll
                for (int mf = 0; mf < 4; mf++)
#pragma unroll
                    for (int nf = 0; nf < 4; nf++)
                        mma_f16(acc[mf][nf], al[mf], &bb[nf >> 1][(nf & 1) * 2]);
            }
        }
    }

    // ---- epilogue ----
#pragma unroll
    for (int mf = 0; mf < 4; mf++) {
        const int r0 = m0 + wm * 64 + mf * 16 + (lane >> 2);
#pragma unroll
        for (int half = 0; half < 2; half++) {
            const long r = r0 + half * 8;
#pragma unroll
            for (int nf = 0; nf < 4; nf++) {
                const int n = n0 + wn * 32 + nf * 8 + (lane & 3) * 2;
                float v0 = acc[mf][nf][half * 2 + 0];
                float v1 = acc[mf][nf][half * 2 + 1];
                if (EPI == 1) { v0 += bias[n]; v1 += bias[n + 1]; }
                if (EPI == 2) {
                    int mv0 = mask[bz * sMask + n];
                    int mv1 = mask[bz * sMask + n + 1];
                    v0 = (mv0 == 0) ? -1e9f : v0 * scale;
                    v1 = (mv1 == 0) ? -1e9f : v1 * scale;
                }
                if (OUT == 0) {
                    float2 o = { v0, v1 };
                    *reinterpret_cast<float2*>((float*)p0 + ((long)bz * sC + r * N_ + n)) = o;
                } else {
                    f16 h0 = __float2half_rn(v0);
                    f16 h1 = __float2half_rn(v1);
                    long o = (long)bz * sC + r * N_ + n;
                    *reinterpret_cast<uint32_t*>((f16*)p0 + o) = pack_h2(h0, h1);
                    *reinterpret_cast<uint32_t*>((f16*)p1 + o) =
                        pack_h2(__float2half_rn(v0 - __half2float(h0)),
                                __float2half_rn(v1 - __half2float(h1)));
                }
            }
        }
    }
}

// ---------------- convert fp32 -> fp16 hi/lo ----------------
__global__ __launch_bounds__(256)
void cvt_hl_f16(const float* __restrict__ in, f16* __restrict__ h,
                f16* __restrict__ l, long n4)
{
    long i = (long)blockIdx.x * blockDim.x + threadIdx.x;
    if (i >= n4) return;
    float4 t = reinterpret_cast<const float4*>(in)[i];
    uint2 hh, ll;
    split4_f16(t, hh, ll);
    reinterpret_cast<uint2*>(h)[i] = hh;
    reinterpret_cast<uint2*>(l)[i] = ll;
}

// ---------------- convert fp32 -> fp16 single ----------------
__global__ __launch_bounds__(256)
void cvt_f16(const float* __restrict__ in, f16* __restrict__ h, long n4)
{
    long i = (long)blockIdx.x * blockDim.x + threadIdx.x;
    if (i >= n4) return;
    float4 t = reinterpret_cast<const float4*>(in)[i];
    uint2 hh = { pack_h2(__float2half_rn(t.x), __float2half_rn(t.y)),
                 pack_h2(__float2half_rn(t.z), __float2half_rn(t.w)) };
    reinterpret_cast<uint2*>(h)[i] = hh;
}

// ---------------- transpose v[B,LK,D] fp32 -> vT fp16 [B,D,LK] ----------------
__global__ __launch_bounds__(256)
void transpose_f16(const float* __restrict__ in, f16* __restrict__ oh)
{
    __shared__ float t[32][33];
    const int b = blockIdx.z;
    const int lk0 = blockIdx.x * 32;
    const int d0 = blockIdx.y * 32;
    const float* ib = in + (size_t)b * LK_ * DIM_;
    f16* ohb = oh + (size_t)b * DIM_ * LK_;
    const int tx = threadIdx.x & 31;
    const int ty = threadIdx.x >> 5;
#pragma unroll
    for (int i = 0; i < 32; i += 8)
        t[ty + i][tx] = ib[(size_t)(lk0 + ty + i) * DIM_ + d0 + tx];
    __syncthreads();
#pragma unroll
    for (int i = 0; i < 32; i += 8)
        ohb[(size_t)(d0 + ty + i) * LK_ + lk0 + tx] = __float2half_rn(t[tx][ty + i]);
}

// ---------------- softmax + emit P fp16 (single) ----------------
__global__ __launch_bounds__(256)
void softmax_kernel(float* __restrict__ score, f16* __restrict__ ph)
{
    __shared__ float red[8];
    __shared__ float bcast;

    const long row = blockIdx.x;
    float* p = score + row * (long)LK_;
    const int tid = threadIdx.x;

    float4 a = reinterpret_cast<const float4*>(p)[tid];
    float4 b = reinterpret_cast<const float4*>(p)[tid + 256];

    float m = fmaxf(fmaxf(fmaxf(a.x, a.y), fmaxf(a.z, a.w)),
                    fmaxf(fmaxf(b.x, b.y), fmaxf(b.z, b.w)));
#pragma unroll
    for (int o = 16; o > 0; o >>= 1) m = fmaxf(m, __shfl_xor_sync(0xffffffffu, m, o));
    if ((tid & 31) == 0) red[tid >> 5] = m;
    __syncthreads();
    if (tid == 0) {
        float mm = red[0];
#pragma unroll
        for (int w = 1; w < 8; w++) mm = fmaxf(mm, red[w]);
        bcast = mm;
    }
    __syncthreads();
    m = bcast;
    __syncthreads();

    a.x = __expf(a.x - m); a.y = __expf(a.y - m);
    a.z = __expf(a.z - m); a.w = __expf(a.w - m);
    b.x = __expf(b.x - m); b.y = __expf(b.y - m);
    b.z = __expf(b.z - m); b.w = __expf(b.w - m);

    float s = (a.x + a.y) + (a.z + a.w) + (b.x + b.y) + (b.z + b.w);
#pragma unroll
    for (int o = 16; o > 0; o >>= 1) s += __shfl_xor_sync(0xffffffffu, s, o);
    if ((tid & 31) == 0) red[tid >> 5] = s;
    __syncthreads();
    if (tid == 0) {
        float ss = 0.f;
#pragma unroll
        for (int w = 0; w < 8; w++) ss += red[w];
        bcast = ss;
    }
    __syncthreads();
    s = bcast;

    float inv = 1.0f / s;
    a.x *= inv; a.y *= inv; a.z *= inv; a.w *= inv;
    b.x *= inv; b.y *= inv; b.z *= inv; b.w *= inv;

    reinterpret_cast<float4*>(p)[tid]       = a;
    reinterpret_cast<float4*>(p)[tid + 256] = b;

    f16* phr = ph + row * (long)LK_;
    uint2 h0 = { pack_h2(__float2half_rn(a.x), __float2half_rn(a.y)),
                 pack_h2(__float2half_rn(a.z), __float2half_rn(a.w)) };
    uint2 h1 = { pack_h2(__float2half_rn(b.x), __float2half_rn(b.y)),
                 pack_h2(__float2half_rn(b.z), __float2half_rn(b.w)) };
    reinterpret_cast<uint2*>(phr)[tid]       = h0;
    reinterpret_cast<uint2*>(phr)[tid + 256] = h1;
}

// ============================ launch ============================
extern "C" void kernel_launch(void* const* d_in, const int* in_sizes, int n_in,
                              void* d_out, int out_size)
{
    const float* key   = (const float*)d_in[0];
    const float* query = (const float*)d_in[1];
    const int*   mask  = (const int*)d_in[2];
    const float* Wq    = (const float*)d_in[3];
    const float* bq    = (const float*)d_in[4];
    const float* Wk    = (const float*)d_in[5];
    const float* bk    = (const float*)d_in[6];
    const float* Wv    = (const float*)d_in[7];
    const float* bv    = (const float*)d_in[8];

    float* out   = (float*)d_out;                         // [B, LQ, D]
    float* score = out + (size_t)B_ * LQ_ * DIM_;         // [B, LQ, LK]

    f16 *xqh, *xql, *xkh, *xkl, *wq16, *wk16, *wv16;
    f16 *q16h, *q16l, *k16h, *k16l, *vt16, *ph;
    float* vbuf;
    cudaGetSymbolAddress((void**)&xqh, g_xqh);   cudaGetSymbolAddress((void**)&xql, g_xql);
    cudaGetSymbolAddress((void**)&xkh, g_xkh);   cudaGetSymbolAddress((void**)&xkl, g_xkl);
    cudaGetSymbolAddress((void**)&wq16, g_wq16);
    cudaGetSymbolAddress((void**)&wk16, g_wk16);
    cudaGetSymbolAddress((void**)&wv16, g_wv16);
    cudaGetSymbolAddress((void**)&q16h, g_q16h); cudaGetSymbolAddress((void**)&q16l, g_q16l);
    cudaGetSymbolAddress((void**)&k16h, g_k16h); cudaGetSymbolAddress((void**)&k16l, g_k16l);
    cudaGetSymbolAddress((void**)&vt16, g_vt16);
    cudaGetSymbolAddress((void**)&ph, g_ph);
    cudaGetSymbolAddress((void**)&vbuf, g_v);

    cudaFuncSetAttribute(gemm_f16<0,0,1>, cudaFuncAttributeMaxDynamicSharedMemorySize, SMEM_F16);
    cudaFuncSetAttribute(gemm_f16<1,0,2>, cudaFuncAttributeMaxDynamicSharedMemorySize, SMEM_F16);
    cudaFuncSetAttribute(gemm_f16<1,1,2>, cudaFuncAttributeMaxDynamicSharedMemorySize, SMEM_F16);
    cudaFuncSetAttribute(gemm_f16<2,0,2>, cudaFuncAttributeMaxDynamicSharedMemorySize, SMEM_F16);

    dim3 blk(NTH);
    const float scale = 0.03125f;  // 1/sqrt(1024)
    const long NBIG4 = (long)NE_BIG / 4;
    const long NW4 = (long)DIM_ * DIM_ / 4;
    const unsigned GB = (unsigned)((NBIG4 + 255) / 256);
    const unsigned GW = (unsigned)((NW4 + 255) / 256);

    // q path
    cvt_hl_f16<<<GB, 256>>>(query, xqh, xql, NBIG4);
    cvt_f16<<<GW, 256>>>(Wq, wq16, NW4);
    {   // q = query @ Wq^T + bq -> fp16 hi/lo
        dim3 g(DIM_ / BN, (B_ * LQ_) / BM, 1);
        gemm_f16<1,1,2><<<g, blk, SMEM_F16>>>(xqh, xql, wq16, q16h, q16l,
                                              DIM_, DIM_, 0, 0, 0, bq, nullptr, 0, 1.f);
    }
    // k path
    cvt_hl_f16<<<GB, 256>>>(key, xkh, xkl, NBIG4);
    cvt_f16<<<GW, 256>>>(Wk, wk16, NW4);
    {   // k = key @ Wk^T + bk -> fp16 hi/lo (hi doubles as score-B)
        dim3 g(DIM_ / BN, (B_ * LK_) / BM, 1);
        gemm_f16<1,1,2><<<g, blk, SMEM_F16>>>(xkh, xkl, wk16, k16h, k16l,
                                              DIM_, DIM_, 0, 0, 0, bk, nullptr, 0, 1.f);
    }
    // v path (A = k fp16 hi/lo, B = Wv fp16)
    cvt_f16<<<GW, 256>>>(Wv, wv16, NW4);
    {   // v = k_proj @ Wv^T + bv -> fp32
        dim3 g(DIM_ / BN, (B_ * LK_) / BM, 1);
        gemm_f16<1,0,2><<<g, blk, SMEM_F16>>>(k16h, k16l, wv16, vbuf, nullptr,
                                              DIM_, DIM_, 0, 0, 0, bv, nullptr, 0, 1.f);
    }
    // score_raw = (q @ k^T) * scale, masked (batched, 2-prod)
    {
        dim3 g(LK_ / BN, LQ_ / BM, B_);
        gemm_f16<2,0,2><<<g, blk, SMEM_F16>>>(q16h, q16l, k16h, score, nullptr,
                                              LK_, DIM_, (long)LQ_ * DIM_,
                                              (long)LK_ * DIM_, (long)LQ_ * LK_,
                                              nullptr, mask, LK_, scale);
    }
    // vT fp16
    {
        dim3 g(LK_ / 32, DIM_ / 32, B_);
        transpose_f16<<<g, 256>>>(vbuf, vt16);
    }
    // softmax rows in place + P fp16 single
    softmax_kernel<<<B_ * LQ_, 256>>>(score, ph);
    // output = P @ V (batched NT, K = LK, 1-prod)
    {
        dim3 g(DIM_ / BN, LQ_ / BM, B_);
        gemm_f16<0,0,1><<<g, blk, SMEM_F16>>>(ph, nullptr, vt16, out, nullptr,
                                              DIM_, LK_, (long)LQ_ * LK_,
                                              (long)DIM_ * LK_, (long)LQ_ * DIM_,
                                              nullptr, nullptr, 0, 1.f);
    }
}

// round 11
// speedup vs baseline: 1.8579x; 1.1596x over previous
#include <cuda_runtime.h>
#include <cuda_fp16.h>
#include <cstdint>

// Problem constants: B=8, LQ=LK=2048, D=1024
#define B_   8
#define LQ_  2048
#define LK_  2048
#define DIM_ 1024

typedef __half f16;

// ---------------- device scratch (allocation-free rule) ----------------
#define NE_BIG ((size_t)B_ * LQ_ * DIM_)      // 16M
#define NE_P   ((size_t)B_ * LQ_ * LK_)       // 32M
__device__ f16  g_xqh[NE_BIG], g_xql[NE_BIG];   // query split fp16
__device__ f16  g_xkh[NE_BIG], g_xkl[NE_BIG];   // key split fp16
__device__ f16  g_wq16[DIM_*DIM_];
__device__ f16  g_wk16[DIM_*DIM_];
__device__ f16  g_wv16[DIM_*DIM_];
__device__ f16  g_q16[NE_BIG];                  // q proj fp16 single (score A)
__device__ f16  g_k16h[NE_BIG], g_k16l[NE_BIG]; // k proj fp16 hi/lo (hi = score B)
__device__ float g_v[NE_BIG];                   // v proj fp32
__device__ f16  g_vt16[NE_BIG];                 // v transposed fp16 [B,D,LK]
__device__ f16  g_ph[NE_P];                     // softmax(P) fp16 (single)

// ============================ helpers ============================
__device__ __forceinline__ uint32_t smem_u32(const void* p) {
    uint32_t a;
    asm("{ .reg .u64 t; cvta.to.shared.u64 t, %1; cvt.u32.u64 %0, t; }" : "=r"(a) : "l"(p));
    return a;
}
__device__ __forceinline__ void ldm_x4(uint32_t* r, uint32_t addr) {
    asm volatile("ldmatrix.sync.aligned.m8n8.x4.shared.b16 {%0,%1,%2,%3}, [%4];"
        : "=r"(r[0]), "=r"(r[1]), "=r"(r[2]), "=r"(r[3]) : "r"(addr));
}
__device__ __forceinline__ void mma_f16(float* d, const uint32_t* a, const uint32_t* b) {
    asm volatile(
        "mma.sync.aligned.m16n8k16.row.col.f32.f16.f16.f32 "
        "{%0,%1,%2,%3}, {%4,%5,%6,%7}, {%8,%9}, {%0,%1,%2,%3};"
        : "+f"(d[0]), "+f"(d[1]), "+f"(d[2]), "+f"(d[3])
        : "r"(a[0]), "r"(a[1]), "r"(a[2]), "r"(a[3]), "r"(b[0]), "r"(b[1]));
}
__device__ __forceinline__ uint32_t pack_h2(f16 a, f16 b) {
    __half2 t(a, b);
    return *reinterpret_cast<uint32_t*>(&t);
}
__device__ __forceinline__ void cp16(uint32_t dst, const void* src) {
    asm volatile("cp.async.cg.shared.global [%0], [%1], 16;" :: "r"(dst), "l"(src));
}
#define CP_COMMIT() asm volatile("cp.async.commit_group;" ::: "memory")
#define CP_WAIT1()  asm volatile("cp.async.wait_group 1;" ::: "memory")

// [row][k] 16-bit tile, 64B rows, 16B-chunk XOR swizzle (conflict-free ldmatrix)
__device__ __forceinline__ uint32_t swoff(uint32_t row, uint32_t k) {
    uint32_t c = (k >> 3) ^ ((row >> 1) & 3u);
    return row * 64u + c * 16u + (k & 7u) * 2u;
}

__device__ __forceinline__ void split4_f16(float4 t, uint2& h, uint2& l) {
    f16 hx = __float2half_rn(t.x);
    f16 hy = __float2half_rn(t.y);
    f16 hz = __float2half_rn(t.z);
    f16 hw = __float2half_rn(t.w);
    h.x = pack_h2(hx, hy); h.y = pack_h2(hz, hw);
    l.x = pack_h2(__float2half_rn(t.x - __half2float(hx)),
                  __float2half_rn(t.y - __half2float(hy)));
    l.y = pack_h2(__float2half_rn(t.z - __half2float(hz)),
                  __float2half_rn(t.w - __half2float(hw)));
}

// ===================== fp16 GEMM (1 or 2 product) =====================
// C[M,N] = (Ah [+ Al])[M,K] * B[N,K]^T, fp16 frags, fp32 accum.
// 128x128x32 tile, 8 warps (2M x 4N), 2 CTAs/SM, 3-stage cp.async.
// EPI: 0 none, 1 +bias[n], 2 mask[n]==0 ? -1e9 : acc*scale
// OUT: 0 fp32 -> p0 ; 1 fp16 hi/lo -> p0,p1 ; 2 fp16 single -> p0
// NPROD: 1 (A single) or 2 (A hi/lo)
#define BM 128
#define BN 128
#define BK 32
#define NTH 256
#define NSTAGES 3
#define F_OFF_AH 0
#define F_OFF_AL 8192
#define F_OFF_B  16384
#define F_STG    24576
#define SMEM_F16 (NSTAGES * F_STG)

template <int NPROD>
__device__ __forceinline__ void stage_load_f16(uint32_t st,
    const f16* __restrict__ pAh, const f16* __restrict__ pAl,
    const f16* __restrict__ pB, int K_, int k0, int tid)
{
#pragma unroll
    for (int i = 0; i < 2; i++) {
        int c = tid + i * NTH;
        int row = c >> 2;
        int kc = (c & 3) * 8;
        uint32_t off = swoff((uint32_t)row, (uint32_t)kc);
        long g = (long)row * K_ + k0 + kc;
        cp16(st + F_OFF_AH + off, pAh + g);
        if (NPROD == 2) cp16(st + F_OFF_AL + off, pAl + g);
        cp16(st + F_OFF_B  + off, pB  + g);
    }
}

template <int EPI, int OUT, int NPROD>
__global__ __launch_bounds__(NTH, 2)
void gemm_f16(const f16* __restrict__ Ah, const f16* __restrict__ Al,
              const f16* __restrict__ Bm,
              void* __restrict__ p0, void* __restrict__ p1,
              int N_, int K_, long sA, long sB, long sC,
              const float* __restrict__ bias,
              const int* __restrict__ mask, long sMask, float scale)
{
    extern __shared__ char sm[];
    const uint32_t smb = smem_u32(sm);

    const int tid = threadIdx.x;
    const int lane = tid & 31;
    const int wid = tid >> 5;
    const int wm = wid & 1;
    const int wn = wid >> 1;

    const int bz = blockIdx.z;
    const int m0 = blockIdx.y * BM;
    const int n0 = blockIdx.x * BN;

    const f16* pAh = Ah + (long)bz * sA + (long)m0 * K_;
    const f16* pAl = (NPROD == 2) ? Al + (long)bz * sA + (long)m0 * K_ : nullptr;
    const f16* pB  = Bm + (long)bz * sB + (long)n0 * K_;

    const uint32_t a_row  = (uint32_t)(wm * 64 + (lane & 15));
    const uint32_t a_cadd = (uint32_t)(lane >> 4);
    const uint32_t b_row  = (uint32_t)(wn * 32 + (lane & 7) + ((lane >> 4) << 3));
    const uint32_t b_cadd = (uint32_t)((lane >> 3) & 1);

    float acc[4][4][4];
#pragma unroll
    for (int i = 0; i < 4; i++)
#pragma unroll
        for (int j = 0; j < 4; j++)
#pragma unroll
            for (int l = 0; l < 4; l++) acc[i][j][l] = 0.f;

    const int nkt = K_ / BK;

#pragma unroll
    for (int s = 0; s < NSTAGES - 1; s++) {
        stage_load_f16<NPROD>(smb + s * F_STG, pAh, pAl, pB, K_, s * BK, tid);
        CP_COMMIT();
    }

    for (int kt = 0; kt < nkt; kt++) {
        CP_WAIT1();
        __syncthreads();
        const uint32_t curb = smb + (uint32_t)(kt % NSTAGES) * F_STG;

        const int pf = kt + NSTAGES - 1;
        if (pf < nkt)
            stage_load_f16<NPROD>(smb + (uint32_t)(pf % NSTAGES) * F_STG, pAh, pAl, pB,
                                  K_, pf * BK, tid);
        CP_COMMIT();

#pragma unroll
        for (int ks = 0; ks < 2; ks++) {
            const uint32_t c0 = (uint32_t)(ks * 2);
            uint32_t ah[4][4], bb[2][4];
#pragma unroll
            for (int mf = 0; mf < 4; mf++)
                ldm_x4(ah[mf], curb + F_OFF_AH + swoff(a_row + mf * 16, (c0 + a_cadd) * 8));
#pragma unroll
            for (int np = 0; np < 2; np++)
                ldm_x4(bb[np], curb + F_OFF_B + swoff(b_row + np * 16, (c0 + b_cadd) * 8));
#pragma unroll
            for (int mf = 0; mf < 4; mf++)
#pragma unroll
                for (int nf = 0; nf < 4; nf++)
                    mma_f16(acc[mf][nf], ah[mf], &bb[nf >> 1][(nf & 1) * 2]);
            if (NPROD == 2) {
                uint32_t al[4][4];
#pragma unroll
                for (int mf = 0; mf < 4; mf++)
                    ldm_x4(al[mf], curb + F_OFF_AL + swoff(a_row + mf * 16, (c0 + a_cadd) * 8));
#pragma unroll
                for (int mf = 0; mf < 4; mf++)
#pragma unroll
                    for (int nf = 0; nf < 4; nf++)
                        mma_f16(acc[mf][nf], al[mf], &bb[nf >> 1][(nf & 1) * 2]);
            }
        }
    }

    // ---- epilogue ----
#pragma unroll
    for (int mf = 0; mf < 4; mf++) {
        const int r0 = m0 + wm * 64 + mf * 16 + (lane >> 2);
#pragma unroll
        for (int half = 0; half < 2; half++) {
            const long r = r0 + half * 8;
#pragma unroll
            for (int nf = 0; nf < 4; nf++) {
                const int n = n0 + wn * 32 + nf * 8 + (lane & 3) * 2;
                float v0 = acc[mf][nf][half * 2 + 0];
                float v1 = acc[mf][nf][half * 2 + 1];
                if (EPI == 1) { v0 += bias[n]; v1 += bias[n + 1]; }
                if (EPI == 2) {
                    int mv0 = mask[bz * sMask + n];
                    int mv1 = mask[bz * sMask + n + 1];
                    v0 = (mv0 == 0) ? -1e9f : v0 * scale;
                    v1 = (mv1 == 0) ? -1e9f : v1 * scale;
                }
                long o = (long)bz * sC + r * N_ + n;
                if (OUT == 0) {
                    float2 ov = { v0, v1 };
                    *reinterpret_cast<float2*>((float*)p0 + o) = ov;
                } else if (OUT == 2) {
                    *reinterpret_cast<uint32_t*>((f16*)p0 + o) =
                        pack_h2(__float2half_rn(v0), __float2half_rn(v1));
                } else {
                    f16 h0 = __float2half_rn(v0);
                    f16 h1 = __float2half_rn(v1);
                    *reinterpret_cast<uint32_t*>((f16*)p0 + o) = pack_h2(h0, h1);
                    *reinterpret_cast<uint32_t*>((f16*)p1 + o) =
                        pack_h2(__float2half_rn(v0 - __half2float(h0)),
                                __float2half_rn(v1 - __half2float(h1)));
                }
            }
        }
    }
}

// ---------------- convert fp32 -> fp16 hi/lo ----------------
__global__ __launch_bounds__(256)
void cvt_hl_f16(const float* __restrict__ in, f16* __restrict__ h,
                f16* __restrict__ l, long n4)
{
    long i = (long)blockIdx.x * blockDim.x + threadIdx.x;
    if (i >= n4) return;
    float4 t = reinterpret_cast<const float4*>(in)[i];
    uint2 hh, ll;
    split4_f16(t, hh, ll);
    reinterpret_cast<uint2*>(h)[i] = hh;
    reinterpret_cast<uint2*>(l)[i] = ll;
}

// ---------------- convert fp32 -> fp16 single ----------------
__global__ __launch_bounds__(256)
void cvt_f16(const float* __restrict__ in, f16* __restrict__ h, long n4)
{
    long i = (long)blockIdx.x * blockDim.x + threadIdx.x;
    if (i >= n4) return;
    float4 t = reinterpret_cast<const float4*>(in)[i];
    uint2 hh = { pack_h2(__float2half_rn(t.x), __float2half_rn(t.y)),
                 pack_h2(__float2half_rn(t.z), __float2half_rn(t.w)) };
    reinterpret_cast<uint2*>(h)[i] = hh;
}

// ---------------- transpose v[B,LK,D] fp32 -> vT fp16 [B,D,LK] ----------------
__global__ __launch_bounds__(256)
void transpose_f16(const float* __restrict__ in, f16* __restrict__ oh)
{
    __shared__ float t[32][33];
    const int b = blockIdx.z;
    const int lk0 = blockIdx.x * 32;
    const int d0 = blockIdx.y * 32;
    const float* ib = in + (size_t)b * LK_ * DIM_;
    f16* ohb = oh + (size_t)b * DIM_ * LK_;
    const int tx = threadIdx.x & 31;
    const int ty = threadIdx.x >> 5;
#pragma unroll
    for (int i = 0; i < 32; i += 8)
        t[ty + i][tx] = ib[(size_t)(lk0 + ty + i) * DIM_ + d0 + tx];
    __syncthreads();
#pragma unroll
    for (int i = 0; i < 32; i += 8)
        ohb[(size_t)(d0 + ty + i) * LK_ + lk0 + tx] = __float2half_rn(t[tx][ty + i]);
}

// ---------------- softmax + emit P fp16 (single) ----------------
__global__ __launch_bounds__(256)
void softmax_kernel(float* __restrict__ score, f16* __restrict__ ph)
{
    __shared__ float red[8];
    __shared__ float bcast;

    const long row = blockIdx.x;
    float* p = score + row * (long)LK_;
    const int tid = threadIdx.x;

    float4 a = reinterpret_cast<const float4*>(p)[tid];
    float4 b = reinterpret_cast<const float4*>(p)[tid + 256];

    float m = fmaxf(fmaxf(fmaxf(a.x, a.y), fmaxf(a.z, a.w)),
                    fmaxf(fmaxf(b.x, b.y), fmaxf(b.z, b.w)));
#pragma unroll
    for (int o = 16; o > 0; o >>= 1) m = fmaxf(m, __shfl_xor_sync(0xffffffffu, m, o));
    if ((tid & 31) == 0) red[tid >> 5] = m;
    __syncthreads();
    if (tid == 0) {
        float mm = red[0];
#pragma unroll
        for (int w = 1; w < 8; w++) mm = fmaxf(mm, red[w]);
        bcast = mm;
    }
    __syncthreads();
    m = bcast;
    __syncthreads();

    a.x = __expf(a.x - m); a.y = __expf(a.y - m);
    a.z = __expf(a.z - m); a.w = __expf(a.w - m);
    b.x = __expf(b.x - m); b.y = __expf(b.y - m);
    b.z = __expf(b.z - m); b.w = __expf(b.w - m);

    float s = (a.x + a.y) + (a.z + a.w) + (b.x + b.y) + (b.z + b.w);
#pragma unroll
    for (int o = 16; o > 0; o >>= 1) s += __shfl_xor_sync(0xffffffffu, s, o);
    if ((tid & 31) == 0) red[tid >> 5] = s;
    __syncthreads();
    if (tid == 0) {
        float ss = 0.f;
#pragma unroll
        for (int w = 0; w < 8; w++) ss += red[w];
        bcast = ss;
    }
    __syncthreads();
    s = bcast;

    float inv = 1.0f / s;
    a.x *= inv; a.y *= inv; a.z *= inv; a.w *= inv;
    b.x *= inv; b.y *= inv; b.z *= inv; b.w *= inv;

    reinterpret_cast<float4*>(p)[tid]       = a;
    reinterpret_cast<float4*>(p)[tid + 256] = b;

    f16* phr = ph + row * (long)LK_;
    uint2 h0 = { pack_h2(__float2half_rn(a.x), __float2half_rn(a.y)),
                 pack_h2(__float2half_rn(a.z), __float2half_rn(a.w)) };
    uint2 h1 = { pack_h2(__float2half_rn(b.x), __float2half_rn(b.y)),
                 pack_h2(__float2half_rn(b.z), __float2half_rn(b.w)) };
    reinterpret_cast<uint2*>(phr)[tid]       = h0;
    reinterpret_cast<uint2*>(phr)[tid + 256] = h1;
}

// ============================ launch ============================
extern "C" void kernel_launch(void* const* d_in, const int* in_sizes, int n_in,
                              void* d_out, int out_size)
{
    const float* key   = (const float*)d_in[0];
    const float* query = (const float*)d_in[1];
    const int*   mask  = (const int*)d_in[2];
    const float* Wq    = (const float*)d_in[3];
    const float* bq    = (const float*)d_in[4];
    const float* Wk    = (const float*)d_in[5];
    const float* bk    = (const float*)d_in[6];
    const float* Wv    = (const float*)d_in[7];
    const float* bv    = (const float*)d_in[8];

    float* out   = (float*)d_out;                         // [B, LQ, D]
    float* score = out + (size_t)B_ * LQ_ * DIM_;         // [B, LQ, LK]

    f16 *xqh, *xql, *xkh, *xkl, *wq16, *wk16, *wv16;
    f16 *q16, *k16h, *k16l, *vt16, *ph;
    float* vbuf;
    cudaGetSymbolAddress((void**)&xqh, g_xqh);   cudaGetSymbolAddress((void**)&xql, g_xql);
    cudaGetSymbolAddress((void**)&xkh, g_xkh);   cudaGetSymbolAddress((void**)&xkl, g_xkl);
    cudaGetSymbolAddress((void**)&wq16, g_wq16);
    cudaGetSymbolAddress((void**)&wk16, g_wk16);
    cudaGetSymbolAddress((void**)&wv16, g_wv16);
    cudaGetSymbolAddress((void**)&q16, g_q16);
    cudaGetSymbolAddress((void**)&k16h, g_k16h); cudaGetSymbolAddress((void**)&k16l, g_k16l);
    cudaGetSymbolAddress((void**)&vt16, g_vt16);
    cudaGetSymbolAddress((void**)&ph, g_ph);
    cudaGetSymbolAddress((void**)&vbuf, g_v);

    cudaFuncSetAttribute(gemm_f16<0,0,1>, cudaFuncAttributeMaxDynamicSharedMemorySize, SMEM_F16);
    cudaFuncSetAttribute(gemm_f16<1,0,2>, cudaFuncAttributeMaxDynamicSharedMemorySize, SMEM_F16);
    cudaFuncSetAttribute(gemm_f16<1,1,2>, cudaFuncAttributeMaxDynamicSharedMemorySize, SMEM_F16);
    cudaFuncSetAttribute(gemm_f16<1,2,2>, cudaFuncAttributeMaxDynamicSharedMemorySize, SMEM_F16);
    cudaFuncSetAttribute(gemm_f16<2,0,1>, cudaFuncAttributeMaxDynamicSharedMemorySize, SMEM_F16);

    dim3 blk(NTH);
    const float scale = 0.03125f;  // 1/sqrt(1024)
    const long NBIG4 = (long)NE_BIG / 4;
    const long NW4 = (long)DIM_ * DIM_ / 4;
    const unsigned GB = (unsigned)((NBIG4 + 255) / 256);
    const unsigned GW = (unsigned)((NW4 + 255) / 256);

    // q path
    cvt_hl_f16<<<GB, 256>>>(query, xqh, xql, NBIG4);
    cvt_f16<<<GW, 256>>>(Wq, wq16, NW4);
    {   // q = query @ Wq^T + bq -> fp16 single (2-prod GEMM)
        dim3 g(DIM_ / BN, (B_ * LQ_) / BM, 1);
        gemm_f16<1,2,2><<<g, blk, SMEM_F16>>>(xqh, xql, wq16, q16, nullptr,
                                              DIM_, DIM_, 0, 0, 0, bq, nullptr, 0, 1.f);
    }
    // k path
    cvt_hl_f16<<<GB, 256>>>(key, xkh, xkl, NBIG4);
    cvt_f16<<<GW, 256>>>(Wk, wk16, NW4);
    {   // k = key @ Wk^T + bk -> fp16 hi/lo (hi doubles as score-B)
        dim3 g(DIM_ / BN, (B_ * LK_) / BM, 1);
        gemm_f16<1,1,2><<<g, blk, SMEM_F16>>>(xkh, xkl, wk16, k16h, k16l,
                                              DIM_, DIM_, 0, 0, 0, bk, nullptr, 0, 1.f);
    }
    // v path (A = k fp16 hi/lo, B = Wv fp16)
    cvt_f16<<<GW, 256>>>(Wv, wv16, NW4);
    {   // v = k_proj @ Wv^T + bv -> fp32
        dim3 g(DIM_ / BN, (B_ * LK_) / BM, 1);
        gemm_f16<1,0,2><<<g, blk, SMEM_F16>>>(k16h, k16l, wv16, vbuf, nullptr,
                                              DIM_, DIM_, 0, 0, 0, bv, nullptr, 0, 1.f);
    }
    // score_raw = (q @ k^T) * scale, masked (batched, 1-prod)
    {
        dim3 g(LK_ / BN, LQ_ / BM, B_);
        gemm_f16<2,0,1><<<g, blk, SMEM_F16>>>(q16, nullptr, k16h, score, nullptr,
                                              LK_, DIM_, (long)LQ_ * DIM_,
                                              (long)LK_ * DIM_, (long)LQ_ * LK_,
                                              nullptr, mask, LK_, scale);
    }
    // vT fp16
    {
        dim3 g(LK_ / 32, DIM_ / 32, B_);
        transpose_f16<<<g, 256>>>(vbuf, vt16);
    }
    // softmax rows in place + P fp16 single
    softmax_kernel<<<B_ * LQ_, 256>>>(score, ph);
    // output = P @ V (batched NT, K = LK, 1-prod)
    {
        dim3 g(DIM_ / BN, LQ_ / BM, B_);
        gemm_f16<0,0,1><<<g, blk, SMEM_F16>>>(ph, nullptr, vt16, out, nullptr,
                                              DIM_, LK_, (long)LQ_ * LK_,
                                              (long)DIM_ * LK_, (long)LQ_ * DIM_,
                                              nullptr, nullptr, 0, 1.f);
    }
}

// round 12
// speedup vs baseline: 2.2166x; 1.1930x over previous
#include <cuda_runtime.h>
#include <cuda_fp16.h>
#include <cstdint>

// Problem constants: B=8, LQ=LK=2048, D=1024
#define B_   8
#define LQ_  2048
#define LK_  2048
#define DIM_ 1024

typedef __half f16;

// ---------------- device scratch (allocation-free rule) ----------------
#define NE_BIG ((size_t)B_ * LQ_ * DIM_)      // 16M
#define NE_P   ((size_t)B_ * LQ_ * LK_)       // 32M
__device__ f16  g_xq16[NE_BIG];                 // query fp16 single
__device__ f16  g_xkh[NE_BIG], g_xkl[NE_BIG];   // key split fp16
__device__ f16  g_wq16[DIM_*DIM_];
__device__ f16  g_wk16[DIM_*DIM_];
__device__ f16  g_wv16[DIM_*DIM_];
__device__ f16  g_q16[NE_BIG];                  // q proj fp16 single (score A)
__device__ f16  g_k16[NE_BIG];                  // k proj fp16 single (score B / v-proj A)
__device__ float g_v[NE_BIG];                   // v proj fp32
__device__ f16  g_vt16[NE_BIG];                 // v transposed fp16 [B,D,LK]
__device__ f16  g_ph[NE_P];                     // softmax(P) fp16 (single)

// ============================ helpers ============================
__device__ __forceinline__ uint32_t smem_u32(const void* p) {
    uint32_t a;
    asm("{ .reg .u64 t; cvta.to.shared.u64 t, %1; cvt.u32.u64 %0, t; }" : "=r"(a) : "l"(p));
    return a;
}
__device__ __forceinline__ void ldm_x4(uint32_t* r, uint32_t addr) {
    asm volatile("ldmatrix.sync.aligned.m8n8.x4.shared.b16 {%0,%1,%2,%3}, [%4];"
        : "=r"(r[0]), "=r"(r[1]), "=r"(r[2]), "=r"(r[3]) : "r"(addr));
}
__device__ __forceinline__ void mma_f16(float* d, const uint32_t* a, const uint32_t* b) {
    asm volatile(
        "mma.sync.aligned.m16n8k16.row.col.f32.f16.f16.f32 "
        "{%0,%1,%2,%3}, {%4,%5,%6,%7}, {%8,%9}, {%0,%1,%2,%3};"
        : "+f"(d[0]), "+f"(d[1]), "+f"(d[2]), "+f"(d[3])
        : "r"(a[0]), "r"(a[1]), "r"(a[2]), "r"(a[3]), "r"(b[0]), "r"(b[1]));
}
__device__ __forceinline__ uint32_t pack_h2(f16 a, f16 b) {
    __half2 t(a, b);
    return *reinterpret_cast<uint32_t*>(&t);
}
__device__ __forceinline__ void cp16(uint32_t dst, const void* src) {
    asm volatile("cp.async.cg.shared.global [%0], [%1], 16;" :: "r"(dst), "l"(src));
}
#define CP_COMMIT() asm volatile("cp.async.commit_group;" ::: "memory")
#define CP_WAIT1()  asm volatile("cp.async.wait_group 1;" ::: "memory")

// [row][k] 16-bit tile, 64B rows, 16B-chunk XOR swizzle (conflict-free ldmatrix)
__device__ __forceinline__ uint32_t swoff(uint32_t row, uint32_t k) {
    uint32_t c = (k >> 3) ^ ((row >> 1) & 3u);
    return row * 64u + c * 16u + (k & 7u) * 2u;
}

__device__ __forceinline__ void split4_f16(float4 t, uint2& h, uint2& l) {
    f16 hx = __float2half_rn(t.x);
    f16 hy = __float2half_rn(t.y);
    f16 hz = __float2half_rn(t.z);
    f16 hw = __float2half_rn(t.w);
    h.x = pack_h2(hx, hy); h.y = pack_h2(hz, hw);
    l.x = pack_h2(__float2half_rn(t.x - __half2float(hx)),
                  __float2half_rn(t.y - __half2float(hy)));
    l.y = pack_h2(__float2half_rn(t.z - __half2float(hz)),
                  __float2half_rn(t.w - __half2float(hw)));
}

// ===================== fp16 GEMM (1 or 2 product) =====================
// C[M,N] = (Ah [+ Al])[M,K] * B[N,K]^T, fp16 frags, fp32 accum.
// 128x128x32 tile, 8 warps (2M x 4N), 2 CTAs/SM, 3-stage cp.async.
// EPI: 0 none, 1 +bias[n], 2 mask[n]==0 ? -1e9 : acc*scale
// OUT: 0 fp32 -> p0 ; 2 fp16 single -> p0
// NPROD: 1 (A single) or 2 (A hi/lo)
#define BM 128
#define BN 128
#define BK 32
#define NTH 256
#define NSTAGES 3
#define F_OFF_AH 0
#define F_OFF_AL 8192
#define F_OFF_B  16384
#define F_STG    24576
#define SMEM_F16 (NSTAGES * F_STG)

template <int NPROD>
__device__ __forceinline__ void stage_load_f16(uint32_t st,
    const f16* __restrict__ pAh, const f16* __restrict__ pAl,
    const f16* __restrict__ pB, int K_, int k0, int tid)
{
#pragma unroll
    for (int i = 0; i < 2; i++) {
        int c = tid + i * NTH;
        int row = c >> 2;
        int kc = (c & 3) * 8;
        uint32_t off = swoff((uint32_t)row, (uint32_t)kc);
        long g = (long)row * K_ + k0 + kc;
        cp16(st + F_OFF_AH + off, pAh + g);
        if (NPROD == 2) cp16(st + F_OFF_AL + off, pAl + g);
        cp16(st + F_OFF_B  + off, pB  + g);
    }
}

template <int EPI, int OUT, int NPROD>
__global__ __launch_bounds__(NTH, 2)
void gemm_f16(const f16* __restrict__ Ah, const f16* __restrict__ Al,
              const f16* __restrict__ Bm,
              void* __restrict__ p0,
              int N_, int K_, long sA, long sB, long sC,
              const float* __restrict__ bias,
              const int* __restrict__ mask, long sMask, float scale)
{
    extern __shared__ char sm[];
    const uint32_t smb = smem_u32(sm);

    const int tid = threadIdx.x;
    const int lane = tid & 31;
    const int wid = tid >> 5;
    const int wm = wid & 1;
    const int wn = wid >> 1;

    const int bz = blockIdx.z;
    const int m0 = blockIdx.y * BM;
    const int n0 = blockIdx.x * BN;

    const f16* pAh = Ah + (long)bz * sA + (long)m0 * K_;
    const f16* pAl = (NPROD == 2) ? Al + (long)bz * sA + (long)m0 * K_ : nullptr;
    const f16* pB  = Bm + (long)bz * sB + (long)n0 * K_;

    const uint32_t a_row  = (uint32_t)(wm * 64 + (lane & 15));
    const uint32_t a_cadd = (uint32_t)(lane >> 4);
    const uint32_t b_row  = (uint32_t)(wn * 32 + (lane & 7) + ((lane >> 4) << 3));
    const uint32_t b_cadd = (uint32_t)((lane >> 3) & 1);

    float acc[4][4][4];
#pragma unroll
    for (int i = 0; i < 4; i++)
#pragma unroll
        for (int j = 0; j < 4; j++)
#pragma unroll
            for (int l = 0; l < 4; l++) acc[i][j][l] = 0.f;

    const int nkt = K_ / BK;

#pragma unroll
    for (int s = 0; s < NSTAGES - 1; s++) {
        stage_load_f16<NPROD>(smb + s * F_STG, pAh, pAl, pB, K_, s * BK, tid);
        CP_COMMIT();
    }

    for (int kt = 0; kt < nkt; kt++) {
        CP_WAIT1();
        __syncthreads();
        const uint32_t curb = smb + (uint32_t)(kt % NSTAGES) * F_STG;

        const int pf = kt + NSTAGES - 1;
        if (pf < nkt)
            stage_load_f16<NPROD>(smb + (uint32_t)(pf % NSTAGES) * F_STG, pAh, pAl, pB,
                                  K_, pf * BK, tid);
        CP_COMMIT();

#pragma unroll
        for (int ks = 0; ks < 2; ks++) {
            const uint32_t c0 = (uint32_t)(ks * 2);
            uint32_t ah[4][4], bb[2][4];
#pragma unroll
            for (int mf = 0; mf < 4; mf++)
                ldm_x4(ah[mf], curb + F_OFF_AH + swoff(a_row + mf * 16, (c0 + a_cadd) * 8));
#pragma unroll
            for (int np = 0; np < 2; np++)
                ldm_x4(bb[np], curb + F_OFF_B + swoff(b_row + np * 16, (c0 + b_cadd) * 8));
#pragma unroll
            for (int mf = 0; mf < 4; mf++)
#pragma unroll
                for (int nf = 0; nf < 4; nf++)
                    mma_f16(acc[mf][nf], ah[mf], &bb[nf >> 1][(nf & 1) * 2]);
            if (NPROD == 2) {
                uint32_t al[4][4];
#pragma unroll
                for (int mf = 0; mf < 4; mf++)
                    ldm_x4(al[mf], curb + F_OFF_AL + swoff(a_row + mf * 16, (c0 + a_cadd) * 8));
#pragma unroll
                for (int mf = 0; mf < 4; mf++)
#pragma unroll
                    for (int nf = 0; nf < 4; nf++)
                        mma_f16(acc[mf][nf], al[mf], &bb[nf >> 1][(nf & 1) * 2]);
            }
        }
    }

    // ---- epilogue ----
#pragma unroll
    for (int mf = 0; mf < 4; mf++) {
        const int r0 = m0 + wm * 64 + mf * 16 + (lane >> 2);
#pragma unroll
        for (int half = 0; half < 2; half++) {
            const long r = r0 + half * 8;
#pragma unroll
            for (int nf = 0; nf < 4; nf++) {
                const int n = n0 + wn * 32 + nf * 8 + (lane & 3) * 2;
                float v0 = acc[mf][nf][half * 2 + 0];
                float v1 = acc[mf][nf][half * 2 + 1];
                if (EPI == 1) { v0 += bias[n]; v1 += bias[n + 1]; }
                if (EPI == 2) {
                    int mv0 = mask[bz * sMask + n];
                    int mv1 = mask[bz * sMask + n + 1];
                    v0 = (mv0 == 0) ? -1e9f : v0 * scale;
                    v1 = (mv1 == 0) ? -1e9f : v1 * scale;
                }
                long o = (long)bz * sC + r * N_ + n;
                if (OUT == 0) {
                    float2 ov = { v0, v1 };
                    *reinterpret_cast<float2*>((float*)p0 + o) = ov;
                } else { // OUT == 2
                    *reinterpret_cast<uint32_t*>((f16*)p0 + o) =
                        pack_h2(__float2half_rn(v0), __float2half_rn(v1));
                }
            }
        }
    }
}

// ---------------- convert fp32 -> fp16 hi/lo ----------------
__global__ __launch_bounds__(256)
void cvt_hl_f16(const float* __restrict__ in, f16* __restrict__ h,
                f16* __restrict__ l, long n4)
{
    long i = (long)blockIdx.x * blockDim.x + threadIdx.x;
    if (i >= n4) return;
    float4 t = reinterpret_cast<const float4*>(in)[i];
    uint2 hh, ll;
    split4_f16(t, hh, ll);
    reinterpret_cast<uint2*>(h)[i] = hh;
    reinterpret_cast<uint2*>(l)[i] = ll;
}

// ---------------- convert fp32 -> fp16 single ----------------
__global__ __launch_bounds__(256)
void cvt_f16(const float* __restrict__ in, f16* __restrict__ h, long n4)
{
    long i = (long)blockIdx.x * blockDim.x + threadIdx.x;
    if (i >= n4) return;
    float4 t = reinterpret_cast<const float4*>(in)[i];
    uint2 hh = { pack_h2(__float2half_rn(t.x), __float2half_rn(t.y)),
                 pack_h2(__float2half_rn(t.z), __float2half_rn(t.w)) };
    reinterpret_cast<uint2*>(h)[i] = hh;
}

// ---------------- transpose v[B,LK,D] fp32 -> vT fp16 [B,D,LK] ----------------
__global__ __launch_bounds__(256)
void transpose_f16(const float* __restrict__ in, f16* __restrict__ oh)
{
    __shared__ float t[32][33];
    const int b = blockIdx.z;
    const int lk0 = blockIdx.x * 32;
    const int d0 = blockIdx.y * 32;
    const float* ib = in + (size_t)b * LK_ * DIM_;
    f16* ohb = oh + (size_t)b * DIM_ * LK_;
    const int tx = threadIdx.x & 31;
    const int ty = threadIdx.x >> 5;
#pragma unroll
    for (int i = 0; i < 32; i += 8)
        t[ty + i][tx] = ib[(size_t)(lk0 + ty + i) * DIM_ + d0 + tx];
    __syncthreads();
#pragma unroll
    for (int i = 0; i < 32; i += 8)
        ohb[(size_t)(d0 + ty + i) * LK_ + lk0 + tx] = __float2half_rn(t[tx][ty + i]);
}

// ---------------- softmax + emit P fp16 (single) ----------------
__global__ __launch_bounds__(256)
void softmax_kernel(float* __restrict__ score, f16* __restrict__ ph)
{
    __shared__ float red[8];
    __shared__ float bcast;

    const long row = blockIdx.x;
    float* p = score + row * (long)LK_;
    const int tid = threadIdx.x;

    float4 a = reinterpret_cast<const float4*>(p)[tid];
    float4 b = reinterpret_cast<const float4*>(p)[tid + 256];

    float m = fmaxf(fmaxf(fmaxf(a.x, a.y), fmaxf(a.z, a.w)),
                    fmaxf(fmaxf(b.x, b.y), fmaxf(b.z, b.w)));
#pragma unroll
    for (int o = 16; o > 0; o >>= 1) m = fmaxf(m, __shfl_xor_sync(0xffffffffu, m, o));
    if ((tid & 31) == 0) red[tid >> 5] = m;
    __syncthreads();
    if (tid == 0) {
        float mm = red[0];
#pragma unroll
        for (int w = 1; w < 8; w++) mm = fmaxf(mm, red[w]);
        bcast = mm;
    }
    __syncthreads();
    m = bcast;
    __syncthreads();

    a.x = __expf(a.x - m); a.y = __expf(a.y - m);
    a.z = __expf(a.z - m); a.w = __expf(a.w - m);
    b.x = __expf(b.x - m); b.y = __expf(b.y - m);
    b.z = __expf(b.z - m); b.w = __expf(b.w - m);

    float s = (a.x + a.y) + (a.z + a.w) + (b.x + b.y) + (b.z + b.w);
#pragma unroll
    for (int o = 16; o > 0; o >>= 1) s += __shfl_xor_sync(0xffffffffu, s, o);
    if ((tid & 31) == 0) red[tid >> 5] = s;
    __syncthreads();
    if (tid == 0) {
        float ss = 0.f;
#pragma unroll
        for (int w = 0; w < 8; w++) ss += red[w];
        bcast = ss;
    }
    __syncthreads();
    s = bcast;

    float inv = 1.0f / s;
    a.x *= inv; a.y *= inv; a.z *= inv; a.w *= inv;
    b.x *= inv; b.y *= inv; b.z *= inv; b.w *= inv;

    reinterpret_cast<float4*>(p)[tid]       = a;
    reinterpret_cast<float4*>(p)[tid + 256] = b;

    f16* phr = ph + row * (long)LK_;
    uint2 h0 = { pack_h2(__float2half_rn(a.x), __float2half_rn(a.y)),
                 pack_h2(__float2half_rn(a.z), __float2half_rn(a.w)) };
    uint2 h1 = { pack_h2(__float2half_rn(b.x), __float2half_rn(b.y)),
                 pack_h2(__float2half_rn(b.z), __float2half_rn(b.w)) };
    reinterpret_cast<uint2*>(phr)[tid]       = h0;
    reinterpret_cast<uint2*>(phr)[tid + 256] = h1;
}

// ============================ launch ============================
extern "C" void kernel_launch(void* const* d_in, const int* in_sizes, int n_in,
                              void* d_out, int out_size)
{
    const float* key   = (const float*)d_in[0];
    const float* query = (const float*)d_in[1];
    const int*   mask  = (const int*)d_in[2];
    const float* Wq    = (const float*)d_in[3];
    const float* bq    = (const float*)d_in[4];
    const float* Wk    = (const float*)d_in[5];
    const float* bk    = (const float*)d_in[6];
    const float* Wv    = (const float*)d_in[7];
    const float* bv    = (const float*)d_in[8];

    float* out   = (float*)d_out;                         // [B, LQ, D]
    float* score = out + (size_t)B_ * LQ_ * DIM_;         // [B, LQ, LK]

    f16 *xq16, *xkh, *xkl, *wq16, *wk16, *wv16;
    f16 *q16, *k16, *vt16, *ph;
    float* vbuf;
    cudaGetSymbolAddress((void**)&xq16, g_xq16);
    cudaGetSymbolAddress((void**)&xkh, g_xkh);   cudaGetSymbolAddress((void**)&xkl, g_xkl);
    cudaGetSymbolAddress((void**)&wq16, g_wq16);
    cudaGetSymbolAddress((void**)&wk16, g_wk16);
    cudaGetSymbolAddress((void**)&wv16, g_wv16);
    cudaGetSymbolAddress((void**)&q16, g_q16);
    cudaGetSymbolAddress((void**)&k16, g_k16);
    cudaGetSymbolAddress((void**)&vt16, g_vt16);
    cudaGetSymbolAddress((void**)&ph, g_ph);
    cudaGetSymbolAddress((void**)&vbuf, g_v);

    cudaFuncSetAttribute(gemm_f16<0,0,1>, cudaFuncAttributeMaxDynamicSharedMemorySize, SMEM_F16);
    cudaFuncSetAttribute(gemm_f16<1,0,1>, cudaFuncAttributeMaxDynamicSharedMemorySize, SMEM_F16);
    cudaFuncSetAttribute(gemm_f16<1,2,1>, cudaFuncAttributeMaxDynamicSharedMemorySize, SMEM_F16);
    cudaFuncSetAttribute(gemm_f16<1,2,2>, cudaFuncAttributeMaxDynamicSharedMemorySize, SMEM_F16);
    cudaFuncSetAttribute(gemm_f16<2,0,1>, cudaFuncAttributeMaxDynamicSharedMemorySize, SMEM_F16);

    dim3 blk(NTH);
    const float scale = 0.03125f;  // 1/sqrt(1024)
    const long NBIG4 = (long)NE_BIG / 4;
    const long NW4 = (long)DIM_ * DIM_ / 4;
    const unsigned GB = (unsigned)((NBIG4 + 255) / 256);
    const unsigned GW = (unsigned)((NW4 + 255) / 256);

    // q path: query single fp16, 1-prod projection
    cvt_f16<<<GB, 256>>>(query, xq16, NBIG4);
    cvt_f16<<<GW, 256>>>(Wq, wq16, NW4);
    {   // q = query @ Wq^T + bq -> fp16 single (1-prod)
        dim3 g(DIM_ / BN, (B_ * LQ_) / BM, 1);
        gemm_f16<1,2,1><<<g, blk, SMEM_F16>>>(xq16, nullptr, wq16, q16,
                                              DIM_, DIM_, 0, 0, 0, bq, nullptr, 0, 1.f);
    }
    // k path: key split, 2-prod projection (k anchors both error paths)
    cvt_hl_f16<<<GB, 256>>>(key, xkh, xkl, NBIG4);
    cvt_f16<<<GW, 256>>>(Wk, wk16, NW4);
    {   // k = key @ Wk^T + bk -> fp16 single (2-prod)
        dim3 g(DIM_ / BN, (B_ * LK_) / BM, 1);
        gemm_f16<1,2,2><<<g, blk, SMEM_F16>>>(xkh, xkl, wk16, k16,
                                              DIM_, DIM_, 0, 0, 0, bk, nullptr, 0, 1.f);
    }
    // v path: A = k16 single, 1-prod
    cvt_f16<<<GW, 256>>>(Wv, wv16, NW4);
    {   // v = k_proj @ Wv^T + bv -> fp32 (1-prod)
        dim3 g(DIM_ / BN, (B_ * LK_) / BM, 1);
        gemm_f16<1,0,1><<<g, blk, SMEM_F16>>>(k16, nullptr, wv16, vbuf,
                                              DIM_, DIM_, 0, 0, 0, bv, nullptr, 0, 1.f);
    }
    // score_raw = (q @ k^T) * scale, masked (batched, 1-prod)
    {
        dim3 g(LK_ / BN, LQ_ / BM, B_);
        gemm_f16<2,0,1><<<g, blk, SMEM_F16>>>(q16, nullptr, k16, score,
                                              LK_, DIM_, (long)LQ_ * DIM_,
                                              (long)LK_ * DIM_, (long)LQ_ * LK_,
                                              nullptr, mask, LK_, scale);
    }
    // vT fp16
    {
        dim3 g(LK_ / 32, DIM_ / 32, B_);
        transpose_f16<<<g, 256>>>(vbuf, vt16);
    }
    // softmax rows in place + P fp16 single
    softmax_kernel<<<B_ * LQ_, 256>>>(score, ph);
    // output = P @ V (batched NT, K = LK, 1-prod)
    {
        dim3 g(DIM_ / BN, LQ_ / BM, B_);
        gemm_f16<0,0,1><<<g, blk, SMEM_F16>>>(ph, nullptr, vt16, out,
                                              DIM_, LK_, (long)LQ_ * LK_,
                                              (long)DIM_ * LK_, (long)LQ_ * DIM_,
                                              nullptr, nullptr, 0, 1.f);
    }
}

// round 13
// speedup vs baseline: 2.4412x; 1.1013x over previous
#include <cuda_runtime.h>
#include <cuda_fp16.h>
#include <cstdint>

// Problem constants: B=8, LQ=LK=2048, D=1024
#define B_   8
#define LQ_  2048
#define LK_  2048
#define DIM_ 1024

typedef __half f16;

// ---------------- device scratch (allocation-free rule) ----------------
#define NE_BIG ((size_t)B_ * LQ_ * DIM_)      // 16M
#define NE_P   ((size_t)B_ * LQ_ * LK_)       // 32M
__device__ f16  g_xq16[NE_BIG];                 // query fp16 single
__device__ f16  g_xk16[NE_BIG];                 // key fp16 single
__device__ f16  g_wq16[DIM_*DIM_];
__device__ f16  g_wk16[DIM_*DIM_];
__device__ f16  g_wv16[DIM_*DIM_];
__device__ f16  g_q16[NE_BIG];                  // q proj fp16 single (score A)
__device__ f16  g_k16[NE_BIG];                  // k proj fp16 single (score B / v-proj A)
__device__ float g_v[NE_BIG];                   // v proj fp32
__device__ f16  g_vt16[NE_BIG];                 // v transposed fp16 [B,D,LK]
__device__ f16  g_ph[NE_P];                     // softmax(P) fp16 (single)

// ============================ helpers ============================
__device__ __forceinline__ uint32_t smem_u32(const void* p) {
    uint32_t a;
    asm("{ .reg .u64 t; cvta.to.shared.u64 t, %1; cvt.u32.u64 %0, t; }" : "=r"(a) : "l"(p));
    return a;
}
__device__ __forceinline__ void ldm_x4(uint32_t* r, uint32_t addr) {
    asm volatile("ldmatrix.sync.aligned.m8n8.x4.shared.b16 {%0,%1,%2,%3}, [%4];"
        : "=r"(r[0]), "=r"(r[1]), "=r"(r[2]), "=r"(r[3]) : "r"(addr));
}
__device__ __forceinline__ void mma_f16(float* d, const uint32_t* a, const uint32_t* b) {
    asm volatile(
        "mma.sync.aligned.m16n8k16.row.col.f32.f16.f16.f32 "
        "{%0,%1,%2,%3}, {%4,%5,%6,%7}, {%8,%9}, {%0,%1,%2,%3};"
        : "+f"(d[0]), "+f"(d[1]), "+f"(d[2]), "+f"(d[3])
        : "r"(a[0]), "r"(a[1]), "r"(a[2]), "r"(a[3]), "r"(b[0]), "r"(b[1]));
}
__device__ __forceinline__ uint32_t pack_h2(f16 a, f16 b) {
    __half2 t(a, b);
    return *reinterpret_cast<uint32_t*>(&t);
}
__device__ __forceinline__ void cp16(uint32_t dst, const void* src) {
    asm volatile("cp.async.cg.shared.global [%0], [%1], 16;" :: "r"(dst), "l"(src));
}
#define CP_COMMIT() asm volatile("cp.async.commit_group;" ::: "memory")
#define CP_WAIT1()  asm volatile("cp.async.wait_group 1;" ::: "memory")

// [row][k] 16-bit tile, 64B rows, 16B-chunk XOR swizzle (conflict-free ldmatrix)
__device__ __forceinline__ uint32_t swoff(uint32_t row, uint32_t k) {
    uint32_t c = (k >> 3) ^ ((row >> 1) & 3u);
    return row * 64u + c * 16u + (k & 7u) * 2u;
}

// ===================== fp16 GEMM (1 or 2 product) =====================
// C[M,N] = (Ah [+ Al])[M,K] * B[N,K]^T, fp16 frags, fp32 accum.
// 128x128x32 tile, 8 warps (2M x 4N), 2 CTAs/SM, 3-stage cp.async.
// EPI: 0 none, 1 +bias[n], 2 mask[n]==0 ? -1e9 : acc*scale
// OUT: 0 fp32 -> p0 ; 2 fp16 single -> p0
// NPROD: 1 (A single) or 2 (A hi/lo)
#define BM 128
#define BN 128
#define BK 32
#define NTH 256
#define NSTAGES 3
#define F_OFF_AH 0
#define F_OFF_AL 8192
#define F_OFF_B  16384
#define F_STG    24576
#define SMEM_F16 (NSTAGES * F_STG)

template <int NPROD>
__device__ __forceinline__ void stage_load_f16(uint32_t st,
    const f16* __restrict__ pAh, const f16* __restrict__ pAl,
    const f16* __restrict__ pB, int K_, int k0, int tid)
{
#pragma unroll
    for (int i = 0; i < 2; i++) {
        int c = tid + i * NTH;
        int row = c >> 2;
        int kc = (c & 3) * 8;
        uint32_t off = swoff((uint32_t)row, (uint32_t)kc);
        long g = (long)row * K_ + k0 + kc;
        cp16(st + F_OFF_AH + off, pAh + g);
        if (NPROD == 2) cp16(st + F_OFF_AL + off, pAl + g);
        cp16(st + F_OFF_B  + off, pB  + g);
    }
}

template <int EPI, int OUT, int NPROD>
__global__ __launch_bounds__(NTH, 2)
void gemm_f16(const f16* __restrict__ Ah, const f16* __restrict__ Al,
              const f16* __restrict__ Bm,
              void* __restrict__ p0,
              int N_, int K_, long sA, long sB, long sC,
              const float* __restrict__ bias,
              const int* __restrict__ mask, long sMask, float scale)
{
    extern __shared__ char sm[];
    const uint32_t smb = smem_u32(sm);

    const int tid = threadIdx.x;
    const int lane = tid & 31;
    const int wid = tid >> 5;
    const int wm = wid & 1;
    const int wn = wid >> 1;

    const int bz = blockIdx.z;
    const int m0 = blockIdx.y * BM;
    const int n0 = blockIdx.x * BN;

    const f16* pAh = Ah + (long)bz * sA + (long)m0 * K_;
    const f16* pAl = (NPROD == 2) ? Al + (long)bz * sA + (long)m0 * K_ : nullptr;
    const f16* pB  = Bm + (long)bz * sB + (long)n0 * K_;

    const uint32_t a_row  = (uint32_t)(wm * 64 + (lane & 15));
    const uint32_t a_cadd = (uint32_t)(lane >> 4);
    const uint32_t b_row  = (uint32_t)(wn * 32 + (lane & 7) + ((lane >> 4) << 3));
    const uint32_t b_cadd = (uint32_t)((lane >> 3) & 1);

    float acc[4][4][4];
#pragma unroll
    for (int i = 0; i < 4; i++)
#pragma unroll
        for (int j = 0; j < 4; j++)
#pragma unroll
            for (int l = 0; l < 4; l++) acc[i][j][l] = 0.f;

    const int nkt = K_ / BK;

#pragma unroll
    for (int s = 0; s < NSTAGES - 1; s++) {
        stage_load_f16<NPROD>(smb + s * F_STG, pAh, pAl, pB, K_, s * BK, tid);
        CP_COMMIT();
    }

    for (int kt = 0; kt < nkt; kt++) {
        CP_WAIT1();
        __syncthreads();
        const uint32_t curb = smb + (uint32_t)(kt % NSTAGES) * F_STG;

        const int pf = kt + NSTAGES - 1;
        if (pf < nkt)
            stage_load_f16<NPROD>(smb + (uint32_t)(pf % NSTAGES) * F_STG, pAh, pAl, pB,
                                  K_, pf * BK, tid);
        CP_COMMIT();

#pragma unroll
        for (int ks = 0; ks < 2; ks++) {
            const uint32_t c0 = (uint32_t)(ks * 2);
            uint32_t ah[4][4], bb[2][4];
#pragma unroll
            for (int mf = 0; mf < 4; mf++)
                ldm_x4(ah[mf], curb + F_OFF_AH + swoff(a_row + mf * 16, (c0 + a_cadd) * 8));
#pragma unroll
            for (int np = 0; np < 2; np++)
                ldm_x4(bb[np], curb + F_OFF_B + swoff(b_row + np * 16, (c0 + b_cadd) * 8));
#pragma unroll
            for (int mf = 0; mf < 4; mf++)
#pragma unroll
                for (int nf = 0; nf < 4; nf++)
                    mma_f16(acc[mf][nf], ah[mf], &bb[nf >> 1][(nf & 1) * 2]);
            if (NPROD == 2) {
                uint32_t al[4][4];
#pragma unroll
                for (int mf = 0; mf < 4; mf++)
                    ldm_x4(al[mf], curb + F_OFF_AL + swoff(a_row + mf * 16, (c0 + a_cadd) * 8));
#pragma unroll
                for (int mf = 0; mf < 4; mf++)
#pragma unroll
                    for (int nf = 0; nf < 4; nf++)
                        mma_f16(acc[mf][nf], al[mf], &bb[nf >> 1][(nf & 1) * 2]);
            }
        }
    }

    // ---- epilogue ----
#pragma unroll
    for (int mf = 0; mf < 4; mf++) {
        const int r0 = m0 + wm * 64 + mf * 16 + (lane >> 2);
#pragma unroll
        for (int half = 0; half < 2; half++) {
            const long r = r0 + half * 8;
#pragma unroll
            for (int nf = 0; nf < 4; nf++) {
                const int n = n0 + wn * 32 + nf * 8 + (lane & 3) * 2;
                float v0 = acc[mf][nf][half * 2 + 0];
                float v1 = acc[mf][nf][half * 2 + 1];
                if (EPI == 1) { v0 += bias[n]; v1 += bias[n + 1]; }
                if (EPI == 2) {
                    int mv0 = mask[bz * sMask + n];
                    int mv1 = mask[bz * sMask + n + 1];
                    v0 = (mv0 == 0) ? -1e9f : v0 * scale;
                    v1 = (mv1 == 0) ? -1e9f : v1 * scale;
                }
                long o = (long)bz * sC + r * N_ + n;
                if (OUT == 0) {
                    float2 ov = { v0, v1 };
                    *reinterpret_cast<float2*>((float*)p0 + o) = ov;
                } else { // OUT == 2
                    *reinterpret_cast<uint32_t*>((f16*)p0 + o) =
                        pack_h2(__float2half_rn(v0), __float2half_rn(v1));
                }
            }
        }
    }
}

// ---------------- convert fp32 -> fp16 single ----------------
__global__ __launch_bounds__(256)
void cvt_f16(const float* __restrict__ in, f16* __restrict__ h, long n4)
{
    long i = (long)blockIdx.x * blockDim.x + threadIdx.x;
    if (i >= n4) return;
    float4 t = reinterpret_cast<const float4*>(in)[i];
    uint2 hh = { pack_h2(__float2half_rn(t.x), __float2half_rn(t.y)),
                 pack_h2(__float2half_rn(t.z), __float2half_rn(t.w)) };
    reinterpret_cast<uint2*>(h)[i] = hh;
}

// ---------------- transpose v[B,LK,D] fp32 -> vT fp16 [B,D,LK] ----------------
__global__ __launch_bounds__(256)
void transpose_f16(const float* __restrict__ in, f16* __restrict__ oh)
{
    __shared__ float t[32][33];
    const int b = blockIdx.z;
    const int lk0 = blockIdx.x * 32;
    const int d0 = blockIdx.y * 32;
    const float* ib = in + (size_t)b * LK_ * DIM_;
    f16* ohb = oh + (size_t)b * DIM_ * LK_;
    const int tx = threadIdx.x & 31;
    const int ty = threadIdx.x >> 5;
#pragma unroll
    for (int i = 0; i < 32; i += 8)
        t[ty + i][tx] = ib[(size_t)(lk0 + ty + i) * DIM_ + d0 + tx];
    __syncthreads();
#pragma unroll
    for (int i = 0; i < 32; i += 8)
        ohb[(size_t)(d0 + ty + i) * LK_ + lk0 + tx] = __float2half_rn(t[tx][ty + i]);
}

// ---------------- softmax + emit P fp16 (single) ----------------
__global__ __launch_bounds__(256)
void softmax_kernel(float* __restrict__ score, f16* __restrict__ ph)
{
    __shared__ float red[8];
    __shared__ float bcast;

    const long row = blockIdx.x;
    float* p = score + row * (long)LK_;
    const int tid = threadIdx.x;

    float4 a = reinterpret_cast<const float4*>(p)[tid];
    float4 b = reinterpret_cast<const float4*>(p)[tid + 256];

    float m = fmaxf(fmaxf(fmaxf(a.x, a.y), fmaxf(a.z, a.w)),
                    fmaxf(fmaxf(b.x, b.y), fmaxf(b.z, b.w)));
#pragma unroll
    for (int o = 16; o > 0; o >>= 1) m = fmaxf(m, __shfl_xor_sync(0xffffffffu, m, o));
    if ((tid & 31) == 0) red[tid >> 5] = m;
    __syncthreads();
    if (tid == 0) {
        float mm = red[0];
#pragma unroll
        for (int w = 1; w < 8; w++) mm = fmaxf(mm, red[w]);
        bcast = mm;
    }
    __syncthreads();
    m = bcast;
    __syncthreads();

    a.x = __expf(a.x - m); a.y = __expf(a.y - m);
    a.z = __expf(a.z - m); a.w = __expf(a.w - m);
    b.x = __expf(b.x - m); b.y = __expf(b.y - m);
    b.z = __expf(b.z - m); b.w = __expf(b.w - m);

    float s = (a.x + a.y) + (a.z + a.w) + (b.x + b.y) + (b.z + b.w);
#pragma unroll
    for (int o = 16; o > 0; o >>= 1) s += __shfl_xor_sync(0xffffffffu, s, o);
    if ((tid & 31) == 0) red[tid >> 5] = s;
    __syncthreads();
    if (tid == 0) {
        float ss = 0.f;
#pragma unroll
        for (int w = 0; w < 8; w++) ss += red[w];
        bcast = ss;
    }
    __syncthreads();
    s = bcast;

    float inv = 1.0f / s;
    a.x *= inv; a.y *= inv; a.z *= inv; a.w *= inv;
    b.x *= inv; b.y *= inv; b.z *= inv; b.w *= inv;

    reinterpret_cast<float4*>(p)[tid]       = a;
    reinterpret_cast<float4*>(p)[tid + 256] = b;

    f16* phr = ph + row * (long)LK_;
    uint2 h0 = { pack_h2(__float2half_rn(a.x), __float2half_rn(a.y)),
                 pack_h2(__float2half_rn(a.z), __float2half_rn(a.w)) };
    uint2 h1 = { pack_h2(__float2half_rn(b.x), __float2half_rn(b.y)),
                 pack_h2(__float2half_rn(b.z), __float2half_rn(b.w)) };
    reinterpret_cast<uint2*>(phr)[tid]       = h0;
    reinterpret_cast<uint2*>(phr)[tid + 256] = h1;
}

// ============================ launch ============================
extern "C" void kernel_launch(void* const* d_in, const int* in_sizes, int n_in,
                              void* d_out, int out_size)
{
    const float* key   = (const float*)d_in[0];
    const float* query = (const float*)d_in[1];
    const int*   mask  = (const int*)d_in[2];
    const float* Wq    = (const float*)d_in[3];
    const float* bq    = (const float*)d_in[4];
    const float* Wk    = (const float*)d_in[5];
    const float* bk    = (const float*)d_in[6];
    const float* Wv    = (const float*)d_in[7];
    const float* bv    = (const float*)d_in[8];

    float* out   = (float*)d_out;                         // [B, LQ, D]
    float* score = out + (size_t)B_ * LQ_ * DIM_;         // [B, LQ, LK]

    f16 *xq16, *xk16, *wq16, *wk16, *wv16;
    f16 *q16, *k16, *vt16, *ph;
    float* vbuf;
    cudaGetSymbolAddress((void**)&xq16, g_xq16);
    cudaGetSymbolAddress((void**)&xk16, g_xk16);
    cudaGetSymbolAddress((void**)&wq16, g_wq16);
    cudaGetSymbolAddress((void**)&wk16, g_wk16);
    cudaGetSymbolAddress((void**)&wv16, g_wv16);
    cudaGetSymbolAddress((void**)&q16, g_q16);
    cudaGetSymbolAddress((void**)&k16, g_k16);
    cudaGetSymbolAddress((void**)&vt16, g_vt16);
    cudaGetSymbolAddress((void**)&ph, g_ph);
    cudaGetSymbolAddress((void**)&vbuf, g_v);

    cudaFuncSetAttribute(gemm_f16<0,0,1>, cudaFuncAttributeMaxDynamicSharedMemorySize, SMEM_F16);
    cudaFuncSetAttribute(gemm_f16<1,0,1>, cudaFuncAttributeMaxDynamicSharedMemorySize, SMEM_F16);
    cudaFuncSetAttribute(gemm_f16<1,2,1>, cudaFuncAttributeMaxDynamicSharedMemorySize, SMEM_F16);
    cudaFuncSetAttribute(gemm_f16<2,0,1>, cudaFuncAttributeMaxDynamicSharedMemorySize, SMEM_F16);

    dim3 blk(NTH);
    const float scale = 0.03125f;  // 1/sqrt(1024)
    const long NBIG4 = (long)NE_BIG / 4;
    const long NW4 = (long)DIM_ * DIM_ / 4;
    const unsigned GB = (unsigned)((NBIG4 + 255) / 256);
    const unsigned GW = (unsigned)((NW4 + 255) / 256);

    // q path
    cvt_f16<<<GB, 256>>>(query, xq16, NBIG4);
    cvt_f16<<<GW, 256>>>(Wq, wq16, NW4);
    {   // q = query @ Wq^T + bq -> fp16 single (1-prod)
        dim3 g(DIM_ / BN, (B_ * LQ_) / BM, 1);
        gemm_f16<1,2,1><<<g, blk, SMEM_F16>>>(xq16, nullptr, wq16, q16,
                                              DIM_, DIM_, 0, 0, 0, bq, nullptr, 0, 1.f);
    }
    // k path (1-prod now)
    cvt_f16<<<GB, 256>>>(key, xk16, NBIG4);
    cvt_f16<<<GW, 256>>>(Wk, wk16, NW4);
    {   // k = key @ Wk^T + bk -> fp16 single (1-prod)
        dim3 g(DIM_ / BN, (B_ * LK_) / BM, 1);
        gemm_f16<1,2,1><<<g, blk, SMEM_F16>>>(xk16, nullptr, wk16, k16,
                                              DIM_, DIM_, 0, 0, 0, bk, nullptr, 0, 1.f);
    }
    // v path: A = k16 single, 1-prod
    cvt_f16<<<GW, 256>>>(Wv, wv16, NW4);
    {   // v = k_proj @ Wv^T + bv -> fp32 (1-prod)
        dim3 g(DIM_ / BN, (B_ * LK_) / BM, 1);
        gemm_f16<1,0,1><<<g, blk, SMEM_F16>>>(k16, nullptr, wv16, vbuf,
                                              DIM_, DIM_, 0, 0, 0, bv, nullptr, 0, 1.f);
    }
    // score_raw = (q @ k^T) * scale, masked (batched, 1-prod)
    {
        dim3 g(LK_ / BN, LQ_ / BM, B_);
        gemm_f16<2,0,1><<<g, blk, SMEM_F16>>>(q16, nullptr, k16, score,
                                              LK_, DIM_, (long)LQ_ * DIM_,
                                              (long)LK_ * DIM_, (long)LQ_ * LK_,
                                              nullptr, mask, LK_, scale);
    }
    // vT fp16
    {
        dim3 g(LK_ / 32, DIM_ / 32, B_);
        transpose_f16<<<g, 256>>>(vbuf, vt16);
    }
    // softmax rows in place + P fp16 single
    softmax_kernel<<<B_ * LQ_, 256>>>(score, ph);
    // output = P @ V (batched NT, K = LK, 1-prod)
    {
        dim3 g(DIM_ / BN, LQ_ / BM, B_);
        gemm_f16<0,0,1><<<g, blk, SMEM_F16>>>(ph, nullptr, vt16, out,
                                              DIM_, LK_, (long)LQ_ * LK_,
                                              (long)DIM_ * LK_, (long)LQ_ * DIM_,
                                              nullptr, nullptr, 0, 1.f);
    }
}

// round 14
// speedup vs baseline: 2.5295x; 1.0362x over previous
#include <cuda_runtime.h>
#include <cuda_fp16.h>
#include <cstdint>

// Problem constants: B=8, LQ=LK=2048, D=1024
#define B_   8
#define LQ_  2048
#define LK_  2048
#define DIM_ 1024

typedef __half f16;

// ---------------- device scratch (allocation-free rule) ----------------
#define NE_BIG ((size_t)B_ * LQ_ * DIM_)      // 16M
#define NE_P   ((size_t)B_ * LQ_ * LK_)       // 32M
__device__ f16  g_xq16[NE_BIG];                 // query fp16 single
__device__ f16  g_xk16[NE_BIG];                 // key fp16 single
__device__ f16  g_wq16[DIM_*DIM_];
__device__ f16  g_wk16[DIM_*DIM_];
__device__ f16  g_wv16[DIM_*DIM_];
__device__ f16  g_q16[NE_BIG];                  // q proj fp16 (score A)
__device__ f16  g_k16[NE_BIG];                  // k proj fp16 (score B / v-proj A)
__device__ float g_v[NE_BIG];                   // v proj fp32
__device__ f16  g_vt16[NE_BIG];                 // v transposed fp16 [B,D,LK]
__device__ f16  g_ph[NE_P];                     // softmax(P) fp16

// ============================ helpers ============================
__device__ __forceinline__ uint32_t smem_u32(const void* p) {
    uint32_t a;
    asm("{ .reg .u64 t; cvta.to.shared.u64 t, %1; cvt.u32.u64 %0, t; }" : "=r"(a) : "l"(p));
    return a;
}
__device__ __forceinline__ void ldm_x4(uint32_t* r, uint32_t addr) {
    asm volatile("ldmatrix.sync.aligned.m8n8.x4.shared.b16 {%0,%1,%2,%3}, [%4];"
        : "=r"(r[0]), "=r"(r[1]), "=r"(r[2]), "=r"(r[3]) : "r"(addr));
}
__device__ __forceinline__ void mma_f16(float* d, const uint32_t* a, const uint32_t* b) {
    asm volatile(
        "mma.sync.aligned.m16n8k16.row.col.f32.f16.f16.f32 "
        "{%0,%1,%2,%3}, {%4,%5,%6,%7}, {%8,%9}, {%0,%1,%2,%3};"
        : "+f"(d[0]), "+f"(d[1]), "+f"(d[2]), "+f"(d[3])
        : "r"(a[0]), "r"(a[1]), "r"(a[2]), "r"(a[3]), "r"(b[0]), "r"(b[1]));
}
__device__ __forceinline__ uint32_t pack_h2(f16 a, f16 b) {
    __half2 t(a, b);
    return *reinterpret_cast<uint32_t*>(&t);
}
__device__ __forceinline__ void cp16(uint32_t dst, const void* src) {
    asm volatile("cp.async.cg.shared.global [%0], [%1], 16;" :: "r"(dst), "l"(src));
}
#define CP_COMMIT() asm volatile("cp.async.commit_group;" ::: "memory")
#define CP_WAIT1()  asm volatile("cp.async.wait_group 1;" ::: "memory")

// [row][k] fp16 tile, 128B rows (64 halfs), 16B-chunk XOR swizzle:
// chunk column c = (k>>3) ^ (row & 7). Conflict-free for 8-lane ldmatrix
// phases (8 consecutive rows -> 8 distinct chunks) and for cp.async stores.
__device__ __forceinline__ uint32_t swoff(uint32_t row, uint32_t k) {
    uint32_t c = (k >> 3) ^ (row & 7u);
    return row * 128u + c * 16u + (k & 7u) * 2u;
}

// ===================== fp16 GEMM =====================
// C[M,N] = A[M,K] * B[N,K]^T, fp16 frags, fp32 accum.
// 128x128x64 tile, 8 warps (2M x 4N), 2 CTAs/SM, 3-stage cp.async.
// EPI: 0 none, 1 +bias[n], 2 mask[n]==0 ? -1e9 : acc*scale
// OUT: 0 fp32 -> p0 ; 2 fp16 -> p0
#define BM 128
#define BN 128
#define BK 64
#define NTH 256
#define NSTAGES 3
#define F_OFF_A 0
#define F_OFF_B 16384
#define F_STG   32768
#define SMEM_F16 (NSTAGES * F_STG)

__device__ __forceinline__ void stage_load_f16(uint32_t st,
    const f16* __restrict__ pA, const f16* __restrict__ pB,
    int K_, int k0, int tid)
{
    // 128 rows x 8 chunks (16B) per operand = 1024 chunks; 4 per thread each
#pragma unroll
    for (int i = 0; i < 4; i++) {
        int c = tid + i * NTH;
        int row = c >> 3;
        int kc = (c & 7) * 8;
        uint32_t off = swoff((uint32_t)row, (uint32_t)kc);
        long g = (long)row * K_ + k0 + kc;
        cp16(st + F_OFF_A + off, pA + g);
        cp16(st + F_OFF_B + off, pB + g);
    }
}

template <int EPI, int OUT>
__global__ __launch_bounds__(NTH, 2)
void gemm_f16(const f16* __restrict__ A, const f16* __restrict__ Bm,
              void* __restrict__ p0,
              int N_, int K_, long sA, long sB, long sC,
              const float* __restrict__ bias,
              const int* __restrict__ mask, long sMask, float scale)
{
    extern __shared__ char sm[];
    const uint32_t smb = smem_u32(sm);

    const int tid = threadIdx.x;
    const int lane = tid & 31;
    const int wid = tid >> 5;
    const int wm = wid & 1;
    const int wn = wid >> 1;

    const int bz = blockIdx.z;
    const int m0 = blockIdx.y * BM;
    const int n0 = blockIdx.x * BN;

    const f16* pA = A + (long)bz * sA + (long)m0 * K_;
    const f16* pB = Bm + (long)bz * sB + (long)n0 * K_;

    const uint32_t a_row  = (uint32_t)(wm * 64 + (lane & 15));
    const uint32_t a_cadd = (uint32_t)(lane >> 4);
    const uint32_t b_row  = (uint32_t)(wn * 32 + (lane & 7) + ((lane >> 4) << 3));
    const uint32_t b_cadd = (uint32_t)((lane >> 3) & 1);

    float acc[4][4][4];
#pragma unroll
    for (int i = 0; i < 4; i++)
#pragma unroll
        for (int j = 0; j < 4; j++)
#pragma unroll
            for (int l = 0; l < 4; l++) acc[i][j][l] = 0.f;

    const int nkt = K_ / BK;

#pragma unroll
    for (int s = 0; s < NSTAGES - 1; s++) {
        stage_load_f16(smb + s * F_STG, pA, pB, K_, s * BK, tid);
        CP_COMMIT();
    }

    for (int kt = 0; kt < nkt; kt++) {
        CP_WAIT1();
        __syncthreads();
        const uint32_t curb = smb + (uint32_t)(kt % NSTAGES) * F_STG;

        const int pf = kt + NSTAGES - 1;
        if (pf < nkt)
            stage_load_f16(smb + (uint32_t)(pf % NSTAGES) * F_STG, pA, pB,
                           K_, pf * BK, tid);
        CP_COMMIT();

#pragma unroll
        for (int ks = 0; ks < 4; ks++) {
            const uint32_t c0 = (uint32_t)(ks * 2);
            uint32_t ah[4][4], bb[2][4];
#pragma unroll
            for (int mf = 0; mf < 4; mf++)
                ldm_x4(ah[mf], curb + F_OFF_A + swoff(a_row + mf * 16, (c0 + a_cadd) * 8));
#pragma unroll
            for (int np = 0; np < 2; np++)
                ldm_x4(bb[np], curb + F_OFF_B + swoff(b_row + np * 16, (c0 + b_cadd) * 8));
#pragma unroll
            for (int mf = 0; mf < 4; mf++)
#pragma unroll
                for (int nf = 0; nf < 4; nf++)
                    mma_f16(acc[mf][nf], ah[mf], &bb[nf >> 1][(nf & 1) * 2]);
        }
    }

    // ---- epilogue ----
#pragma unroll
    for (int mf = 0; mf < 4; mf++) {
        const int r0 = m0 + wm * 64 + mf * 16 + (lane >> 2);
#pragma unroll
        for (int half = 0; half < 2; half++) {
            const long r = r0 + half * 8;
#pragma unroll
            for (int nf = 0; nf < 4; nf++) {
                const int n = n0 + wn * 32 + nf * 8 + (lane & 3) * 2;
                float v0 = acc[mf][nf][half * 2 + 0];
                float v1 = acc[mf][nf][half * 2 + 1];
                if (EPI == 1) { v0 += bias[n]; v1 += bias[n + 1]; }
                if (EPI == 2) {
                    int mv0 = mask[bz * sMask + n];
                    int mv1 = mask[bz * sMask + n + 1];
                    v0 = (mv0 == 0) ? -1e9f : v0 * scale;
                    v1 = (mv1 == 0) ? -1e9f : v1 * scale;
                }
                long o = (long)bz * sC + r * N_ + n;
                if (OUT == 0) {
                    float2 ov = { v0, v1 };
                    *reinterpret_cast<float2*>((float*)p0 + o) = ov;
                } else { // OUT == 2
                    *reinterpret_cast<uint32_t*>((f16*)p0 + o) =
                        pack_h2(__float2half_rn(v0), __float2half_rn(v1));
                }
            }
        }
    }
}

// ---------------- convert fp32 -> fp16 ----------------
__global__ __launch_bounds__(256)
void cvt_f16(const float* __restrict__ in, f16* __restrict__ h, long n4)
{
    long i = (long)blockIdx.x * blockDim.x + threadIdx.x;
    if (i >= n4) return;
    float4 t = reinterpret_cast<const float4*>(in)[i];
    uint2 hh = { pack_h2(__float2half_rn(t.x), __float2half_rn(t.y)),
                 pack_h2(__float2half_rn(t.z), __float2half_rn(t.w)) };
    reinterpret_cast<uint2*>(h)[i] = hh;
}

// ---------------- transpose v[B,LK,D] fp32 -> vT fp16 [B,D,LK] ----------------
__global__ __launch_bounds__(256)
void transpose_f16(const float* __restrict__ in, f16* __restrict__ oh)
{
    __shared__ float t[32][33];
    const int b = blockIdx.z;
    const int lk0 = blockIdx.x * 32;
    const int d0 = blockIdx.y * 32;
    const float* ib = in + (size_t)b * LK_ * DIM_;
    f16* ohb = oh + (size_t)b * DIM_ * LK_;
    const int tx = threadIdx.x & 31;
    const int ty = threadIdx.x >> 5;
#pragma unroll
    for (int i = 0; i < 32; i += 8)
        t[ty + i][tx] = ib[(size_t)(lk0 + ty + i) * DIM_ + d0 + tx];
    __syncthreads();
#pragma unroll
    for (int i = 0; i < 32; i += 8)
        ohb[(size_t)(d0 + ty + i) * LK_ + lk0 + tx] = __float2half_rn(t[tx][ty + i]);
}

// ---------------- softmax + emit P fp16 ----------------
__global__ __launch_bounds__(256)
void softmax_kernel(float* __restrict__ score, f16* __restrict__ ph)
{
    __shared__ float red[8];
    __shared__ float bcast;

    const long row = blockIdx.x;
    float* p = score + row * (long)LK_;
    const int tid = threadIdx.x;

    float4 a = reinterpret_cast<const float4*>(p)[tid];
    float4 b = reinterpret_cast<const float4*>(p)[tid + 256];

    float m = fmaxf(fmaxf(fmaxf(a.x, a.y), fmaxf(a.z, a.w)),
                    fmaxf(fmaxf(b.x, b.y), fmaxf(b.z, b.w)));
#pragma unroll
    for (int o = 16; o > 0; o >>= 1) m = fmaxf(m, __shfl_xor_sync(0xffffffffu, m, o));
    if ((tid & 31) == 0) red[tid >> 5] = m;
    __syncthreads();
    if (tid == 0) {
        float mm = red[0];
#pragma unroll
        for (int w = 1; w < 8; w++) mm = fmaxf(mm, red[w]);
        bcast = mm;
    }
    __syncthreads();
    m = bcast;
    __syncthreads();

    a.x = __expf(a.x - m); a.y = __expf(a.y - m);
    a.z = __expf(a.z - m); a.w = __expf(a.w - m);
    b.x = __expf(b.x - m); b.y = __expf(b.y - m);
    b.z = __expf(b.z - m); b.w = __expf(b.w - m);

    float s = (a.x + a.y) + (a.z + a.w) + (b.x + b.y) + (b.z + b.w);
#pragma unroll
    for (int o = 16; o > 0; o >>= 1) s += __shfl_xor_sync(0xffffffffu, s, o);
    if ((tid & 31) == 0) red[tid >> 5] = s;
    __syncthreads();
    if (tid == 0) {
        float ss = 0.f;
#pragma unroll
        for (int w = 0; w < 8; w++) ss += red[w];
        bcast = ss;
    }
    __syncthreads();
    s = bcast;

    float inv = 1.0f / s;
    a.x *= inv; a.y *= inv; a.z *= inv; a.w *= inv;
    b.x *= inv; b.y *= inv; b.z *= inv; b.w *= inv;

    reinterpret_cast<float4*>(p)[tid]       = a;
    reinterpret_cast<float4*>(p)[tid + 256] = b;

    f16* phr = ph + row * (long)LK_;
    uint2 h0 = { pack_h2(__float2half_rn(a.x), __float2half_rn(a.y)),
                 pack_h2(__float2half_rn(a.z), __float2half_rn(a.w)) };
    uint2 h1 = { pack_h2(__float2half_rn(b.x), __float2half_rn(b.y)),
                 pack_h2(__float2half_rn(b.z), __float2half_rn(b.w)) };
    reinterpret_cast<uint2*>(phr)[tid]       = h0;
    reinterpret_cast<uint2*>(phr)[tid + 256] = h1;
}

// ============================ launch ============================
extern "C" void kernel_launch(void* const* d_in, const int* in_sizes, int n_in,
                              void* d_out, int out_size)
{
    const float* key   = (const float*)d_in[0];
    const float* query = (const float*)d_in[1];
    const int*   mask  = (const int*)d_in[2];
    const float* Wq    = (const float*)d_in[3];
    const float* bq    = (const float*)d_in[4];
    const float* Wk    = (const float*)d_in[5];
    const float* bk    = (const float*)d_in[6];
    const float* Wv    = (const float*)d_in[7];
    const float* bv    = (const float*)d_in[8];

    float* out   = (float*)d_out;                         // [B, LQ, D]
    float* score = out + (size_t)B_ * LQ_ * DIM_;         // [B, LQ, LK]

    f16 *xq16, *xk16, *wq16, *wk16, *wv16;
    f16 *q16, *k16, *vt16, *ph;
    float* vbuf;
    cudaGetSymbolAddress((void**)&xq16, g_xq16);
    cudaGetSymbolAddress((void**)&xk16, g_xk16);
    cudaGetSymbolAddress((void**)&wq16, g_wq16);
    cudaGetSymbolAddress((void**)&wk16, g_wk16);
    cudaGetSymbolAddress((void**)&wv16, g_wv16);
    cudaGetSymbolAddress((void**)&q16, g_q16);
    cudaGetSymbolAddress((void**)&k16, g_k16);
    cudaGetSymbolAddress((void**)&vt16, g_vt16);
    cudaGetSymbolAddress((void**)&ph, g_ph);
    cudaGetSymbolAddress((void**)&vbuf, g_v);

    cudaFuncSetAttribute(gemm_f16<0,0>, cudaFuncAttributeMaxDynamicSharedMemorySize, SMEM_F16);
    cudaFuncSetAttribute(gemm_f16<1,0>, cudaFuncAttributeMaxDynamicSharedMemorySize, SMEM_F16);
    cudaFuncSetAttribute(gemm_f16<1,2>, cudaFuncAttributeMaxDynamicSharedMemorySize, SMEM_F16);
    cudaFuncSetAttribute(gemm_f16<2,0>, cudaFuncAttributeMaxDynamicSharedMemorySize, SMEM_F16);

    dim3 blk(NTH);
    const float scale = 0.03125f;  // 1/sqrt(1024)
    const long NBIG4 = (long)NE_BIG / 4;
    const long NW4 = (long)DIM_ * DIM_ / 4;
    const unsigned GB = (unsigned)((NBIG4 + 255) / 256);
    const unsigned GW = (unsigned)((NW4 + 255) / 256);

    // q path
    cvt_f16<<<GB, 256>>>(query, xq16, NBIG4);
    cvt_f16<<<GW, 256>>>(Wq, wq16, NW4);
    {   // q = query @ Wq^T + bq -> fp16
        dim3 g(DIM_ / BN, (B_ * LQ_) / BM, 1);
        gemm_f16<1,2><<<g, blk, SMEM_F16>>>(xq16, wq16, q16,
                                            DIM_, DIM_, 0, 0, 0, bq, nullptr, 0, 1.f);
    }
    // k path
    cvt_f16<<<GB, 256>>>(key, xk16, NBIG4);
    cvt_f16<<<GW, 256>>>(Wk, wk16, NW4);
    {   // k = key @ Wk^T + bk -> fp16
        dim3 g(DIM_ / BN, (B_ * LK_) / BM, 1);
        gemm_f16<1,2><<<g, blk, SMEM_F16>>>(xk16, wk16, k16,
                                            DIM_, DIM_, 0, 0, 0, bk, nullptr, 0, 1.f);
    }
    // v path
    cvt_f16<<<GW, 256>>>(Wv, wv16, NW4);
    {   // v = k_proj @ Wv^T + bv -> fp32
        dim3 g(DIM_ / BN, (B_ * LK_) / BM, 1);
        gemm_f16<1,0><<<g, blk, SMEM_F16>>>(k16, wv16, vbuf,
                                            DIM_, DIM_, 0, 0, 0, bv, nullptr, 0, 1.f);
    }
    // score_raw = (q @ k^T) * scale, masked (batched)
    {
        dim3 g(LK_ / BN, LQ_ / BM, B_);
        gemm_f16<2,0><<<g, blk, SMEM_F16>>>(q16, k16, score,
                                            LK_, DIM_, (long)LQ_ * DIM_,
                                            (long)LK_ * DIM_, (long)LQ_ * LK_,
                                            nullptr, mask, LK_, scale);
    }
    // vT fp16
    {
        dim3 g(LK_ / 32, DIM_ / 32, B_);
        transpose_f16<<<g, 256>>>(vbuf, vt16);
    }
    // softmax rows in place + P fp16
    softmax_kernel<<<B_ * LQ_, 256>>>(score, ph);
    // output = P @ V (batched NT, K = LK)
    {
        dim3 g(DIM_ / BN, LQ_ / BM, B_);
        gemm_f16<0,0><<<g, blk, SMEM_F16>>>(ph, vt16, out,
                                            DIM_, LK_, (long)LQ_ * LK_,
                                            (long)DIM_ * LK_, (long)LQ_ * DIM_,
                                            nullptr, nullptr, 0, 1.f);
    }
}

// round 15
// speedup vs baseline: 2.5749x; 1.0180x over previous
#include <cuda_runtime.h>
#include <cuda_fp16.h>
#include <cstdint>

// Problem constants: B=8, LQ=LK=2048, D=1024
#define B_   8
#define LQ_  2048
#define LK_  2048
#define DIM_ 1024

typedef __half f16;

// ---------------- device scratch (allocation-free rule) ----------------
#define NE_BIG ((size_t)B_ * LQ_ * DIM_)      // 16M
#define NE_P   ((size_t)B_ * LQ_ * LK_)       // 32M
__device__ f16  g_xq16[NE_BIG];                 // query fp16
__device__ f16  g_xk16[NE_BIG];                 // key fp16
__device__ f16  g_wq16[DIM_*DIM_];
__device__ f16  g_wk16[DIM_*DIM_];
__device__ f16  g_wv16[DIM_*DIM_];
__device__ f16  g_q16[NE_BIG];                  // q proj fp16 (score A)
__device__ f16  g_k16[NE_BIG];                  // k proj fp16 (score B / v-proj A)
__device__ f16  g_v16[NE_BIG];                  // v proj fp16 [B,LK,D] (PV B, trans-load)
__device__ f16  g_ph[NE_P];                     // softmax(P) fp16

// ============================ helpers ============================
__device__ __forceinline__ uint32_t smem_u32(const void* p) {
    uint32_t a;
    asm("{ .reg .u64 t; cvta.to.shared.u64 t, %1; cvt.u32.u64 %0, t; }" : "=r"(a) : "l"(p));
    return a;
}
__device__ __forceinline__ void ldm_x4(uint32_t* r, uint32_t addr) {
    asm volatile("ldmatrix.sync.aligned.m8n8.x4.shared.b16 {%0,%1,%2,%3}, [%4];"
        : "=r"(r[0]), "=r"(r[1]), "=r"(r[2]), "=r"(r[3]) : "r"(addr));
}
__device__ __forceinline__ void ldm_x4_t(uint32_t* r, uint32_t addr) {
    asm volatile("ldmatrix.sync.aligned.m8n8.x4.trans.shared.b16 {%0,%1,%2,%3}, [%4];"
        : "=r"(r[0]), "=r"(r[1]), "=r"(r[2]), "=r"(r[3]) : "r"(addr));
}
__device__ __forceinline__ void mma_f16(float* d, const uint32_t* a, const uint32_t* b) {
    asm volatile(
        "mma.sync.aligned.m16n8k16.row.col.f32.f16.f16.f32 "
        "{%0,%1,%2,%3}, {%4,%5,%6,%7}, {%8,%9}, {%0,%1,%2,%3};"
        : "+f"(d[0]), "+f"(d[1]), "+f"(d[2]), "+f"(d[3])
        : "r"(a[0]), "r"(a[1]), "r"(a[2]), "r"(a[3]), "r"(b[0]), "r"(b[1]));
}
__device__ __forceinline__ uint32_t pack_h2(f16 a, f16 b) {
    __half2 t(a, b);
    return *reinterpret_cast<uint32_t*>(&t);
}
__device__ __forceinline__ void cp16(uint32_t dst, const void* src) {
    asm volatile("cp.async.cg.shared.global [%0], [%1], 16;" :: "r"(dst), "l"(src));
}
#define CP_COMMIT() asm volatile("cp.async.commit_group;" ::: "memory")
#define CP_WAIT1()  asm volatile("cp.async.wait_group 1;" ::: "memory")

// K-major tile: 128B rows (64 halfs), chunk swizzle c = (k>>3) ^ (row&7)
__device__ __forceinline__ uint32_t swoff(uint32_t row, uint32_t k) {
    uint32_t c = (k >> 3) ^ (row & 7u);
    return row * 128u + c * 16u + (k & 7u) * 2u;
}
// TRB tile (rows = k, 256B rows of 128 n-halfs): c = (n>>3) ^ (row&7)
__device__ __forceinline__ uint32_t swoff_t(uint32_t row, uint32_t n) {
    uint32_t c = (n >> 3) ^ (row & 7u);
    return row * 256u + c * 16u + (n & 7u) * 2u;
}

// ===================== fp16 GEMM =====================
// TRB=0: C[M,N] = A[M,K] * B[N,K]^T  (B K-contiguous)
// TRB=1: C[M,N] = A[M,K] * B[K,N]    (B N-contiguous, ldmatrix.trans)
// 128x128x64 tile, 8 warps (2M x 4N), 2 CTAs/SM, 3-stage cp.async.
// EPI: 0 none, 1 +bias[n], 2 mask[n]==0 ? -1e9 : acc*scale
// OUT: 0 fp32 -> p0 ; 2 fp16 -> p0
#define BM 128
#define BN 128
#define BK 64
#define NTH 256
#define NSTAGES 3
#define F_OFF_A 0
#define F_OFF_B 16384
#define F_STG   32768
#define SMEM_F16 (NSTAGES * F_STG)

template <int TRB>
__device__ __forceinline__ void stage_load_f16(uint32_t st,
    const f16* __restrict__ pA, const f16* __restrict__ pB,
    int K_, int ldB, int k0, int tid)
{
    // A: 128 rows x 8 chunks = 1024 chunks; 4 per thread
#pragma unroll
    for (int i = 0; i < 4; i++) {
        int c = tid + i * NTH;
        int row = c >> 3;
        int kc = (c & 7) * 8;
        cp16(st + F_OFF_A + swoff((uint32_t)row, (uint32_t)kc),
             pA + (long)row * K_ + k0 + kc);
    }
    if (TRB == 0) {
        // B: 128 rows(n) x 8 chunks(k)
#pragma unroll
        for (int i = 0; i < 4; i++) {
            int c = tid + i * NTH;
            int row = c >> 3;
            int kc = (c & 7) * 8;
            cp16(st + F_OFF_B + swoff((uint32_t)row, (uint32_t)kc),
                 pB + (long)row * ldB + k0 + kc);
        }
    } else {
        // B: 64 rows(k) x 16 chunks(n)
#pragma unroll
        for (int i = 0; i < 4; i++) {
            int c = tid + i * NTH;
            int row = c >> 4;            // 0..63 (k within tile)
            int nc = (c & 15) * 8;       // 0..120 (n within tile)
            cp16(st + F_OFF_B + swoff_t((uint32_t)row, (uint32_t)nc),
                 pB + (long)(k0 + row) * ldB + nc);
        }
    }
}

template <int EPI, int OUT, int TRB>
__global__ __launch_bounds__(NTH, 2)
void gemm_f16(const f16* __restrict__ A, const f16* __restrict__ Bm,
              void* __restrict__ p0,
              int N_, int K_, int ldB, long sA, long sB, long sC,
              const float* __restrict__ bias,
              const int* __restrict__ mask, long sMask, float scale)
{
    extern __shared__ char sm[];
    const uint32_t smb = smem_u32(sm);

    const int tid = threadIdx.x;
    const int lane = tid & 31;
    const int wid = tid >> 5;
    const int wm = wid & 1;
    const int wn = wid >> 1;

    const int bz = blockIdx.z;
    const int m0 = blockIdx.y * BM;
    const int n0 = blockIdx.x * BN;

    const f16* pA = A + (long)bz * sA + (long)m0 * K_;
    // TRB=0: row offset n0 applied here. TRB=1: column offset n0.
    const f16* pB = Bm + (long)bz * sB + (TRB == 0 ? (long)n0 * ldB : (long)n0);

    const uint32_t a_row  = (uint32_t)(wm * 64 + (lane & 15));
    const uint32_t a_cadd = (uint32_t)(lane >> 4);
    // TRB=0 fragment addressing
    const uint32_t b_row  = (uint32_t)(wn * 32 + (lane & 7) + ((lane >> 4) << 3));
    const uint32_t b_cadd = (uint32_t)((lane >> 3) & 1);
    // TRB=1 fragment addressing: lanes 0-7 -> k0-7, 8-15 -> k8-15 (same n chunk),
    // 16-31 -> next n chunk.
    const uint32_t bt_radd = (uint32_t)((lane & 7) + ((lane >> 3) & 1) * 8);
    const uint32_t bt_cadd = (uint32_t)(wn * 4 + (lane >> 4));

    float acc[4][4][4];
#pragma unroll
    for (int i = 0; i < 4; i++)
#pragma unroll
        for (int j = 0; j < 4; j++)
#pragma unroll
            for (int l = 0; l < 4; l++) acc[i][j][l] = 0.f;

    const int nkt = K_ / BK;

#pragma unroll
    for (int s = 0; s < NSTAGES - 1; s++) {
        stage_load_f16<TRB>(smb + s * F_STG, pA, pB, K_, ldB, s * BK, tid);
        CP_COMMIT();
    }

    for (int kt = 0; kt < nkt; kt++) {
        CP_WAIT1();
        __syncthreads();
        const uint32_t curb = smb + (uint32_t)(kt % NSTAGES) * F_STG;

        const int pf = kt + NSTAGES - 1;
        if (pf < nkt)
            stage_load_f16<TRB>(smb + (uint32_t)(pf % NSTAGES) * F_STG, pA, pB,
                                K_, ldB, pf * BK, tid);
        CP_COMMIT();

#pragma unroll
        for (int ks = 0; ks < 4; ks++) {
            const uint32_t c0 = (uint32_t)(ks * 2);
            uint32_t ah[4][4], bb[2][4];
#pragma unroll
            for (int mf = 0; mf < 4; mf++)
                ldm_x4(ah[mf], curb + F_OFF_A + swoff(a_row + mf * 16, (c0 + a_cadd) * 8));
            if (TRB == 0) {
#pragma unroll
                for (int np = 0; np < 2; np++)
                    ldm_x4(bb[np], curb + F_OFF_B + swoff(b_row + np * 16, (c0 + b_cadd) * 8));
            } else {
#pragma unroll
                for (int np = 0; np < 2; np++) {
                    uint32_t row = (uint32_t)(ks * 16) + bt_radd;
                    uint32_t ch  = bt_cadd + np * 2;
                    uint32_t off = row * 256u + ((ch ^ (row & 7u)) * 16u);
                    ldm_x4_t(bb[np], curb + F_OFF_B + off);
                }
            }
#pragma unroll
            for (int mf = 0; mf < 4; mf++)
#pragma unroll
                for (int nf = 0; nf < 4; nf++)
                    mma_f16(acc[mf][nf], ah[mf], &bb[nf >> 1][(nf & 1) * 2]);
        }
    }

    // ---- epilogue ----
#pragma unroll
    for (int mf = 0; mf < 4; mf++) {
        const int r0 = m0 + wm * 64 + mf * 16 + (lane >> 2);
#pragma unroll
        for (int half = 0; half < 2; half++) {
            const long r = r0 + half * 8;
#pragma unroll
            for (int nf = 0; nf < 4; nf++) {
                const int n = n0 + wn * 32 + nf * 8 + (lane & 3) * 2;
                float v0 = acc[mf][nf][half * 2 + 0];
                float v1 = acc[mf][nf][half * 2 + 1];
                if (EPI == 1) { v0 += bias[n]; v1 += bias[n + 1]; }
                if (EPI == 2) {
                    int mv0 = mask[bz * sMask + n];
                    int mv1 = mask[bz * sMask + n + 1];
                    v0 = (mv0 == 0) ? -1e9f : v0 * scale;
                    v1 = (mv1 == 0) ? -1e9f : v1 * scale;
                }
                long o = (long)bz * sC + r * N_ + n;
                if (OUT == 0) {
                    float2 ov = { v0, v1 };
                    *reinterpret_cast<float2*>((float*)p0 + o) = ov;
                } else { // OUT == 2
                    *reinterpret_cast<uint32_t*>((f16*)p0 + o) =
                        pack_h2(__float2half_rn(v0), __float2half_rn(v1));
                }
            }
        }
    }
}

// ---------------- convert fp32 -> fp16 ----------------
__global__ __launch_bounds__(256)
void cvt_f16(const float* __restrict__ in, f16* __restrict__ h, long n4)
{
    long i = (long)blockIdx.x * blockDim.x + threadIdx.x;
    if (i >= n4) return;
    float4 t = reinterpret_cast<const float4*>(in)[i];
    uint2 hh = { pack_h2(__float2half_rn(t.x), __float2half_rn(t.y)),
                 pack_h2(__float2half_rn(t.z), __float2half_rn(t.w)) };
    reinterpret_cast<uint2*>(h)[i] = hh;
}

// ---------------- softmax + emit P fp16 ----------------
__global__ __launch_bounds__(256)
void softmax_kernel(float* __restrict__ score, f16* __restrict__ ph)
{
    __shared__ float red[8];
    __shared__ float bcast;

    const long row = blockIdx.x;
    float* p = score + row * (long)LK_;
    const int tid = threadIdx.x;

    float4 a = reinterpret_cast<const float4*>(p)[tid];
    float4 b = reinterpret_cast<const float4*>(p)[tid + 256];

    float m = fmaxf(fmaxf(fmaxf(a.x, a.y), fmaxf(a.z, a.w)),
                    fmaxf(fmaxf(b.x, b.y), fmaxf(b.z, b.w)));
#pragma unroll
    for (int o = 16; o > 0; o >>= 1) m = fmaxf(m, __shfl_xor_sync(0xffffffffu, m, o));
    if ((tid & 31) == 0) red[tid >> 5] = m;
    __syncthreads();
    if (tid == 0) {
        float mm = red[0];
#pragma unroll
        for (int w = 1; w < 8; w++) mm = fmaxf(mm, red[w]);
        bcast = mm;
    }
    __syncthreads();
    m = bcast;
    __syncthreads();

    a.x = __expf(a.x - m); a.y = __expf(a.y - m);
    a.z = __expf(a.z - m); a.w = __expf(a.w - m);
    b.x = __expf(b.x - m); b.y = __expf(b.y - m);
    b.z = __expf(b.z - m); b.w = __expf(b.w - m);

    float s = (a.x + a.y) + (a.z + a.w) + (b.x + b.y) + (b.z + b.w);
#pragma unroll
    for (int o = 16; o > 0; o >>= 1) s += __shfl_xor_sync(0xffffffffu, s, o);
    if ((tid & 31) == 0) red[tid >> 5] = s;
    __syncthreads();
    if (tid == 0) {
        float ss = 0.f;
#pragma unroll
        for (int w = 0; w < 8; w++) ss += red[w];
        bcast = ss;
    }
    __syncthreads();
    s = bcast;

    float inv = 1.0f / s;
    a.x *= inv; a.y *= inv; a.z *= inv; a.w *= inv;
    b.x *= inv; b.y *= inv; b.z *= inv; b.w *= inv;

    reinterpret_cast<float4*>(p)[tid]       = a;
    reinterpret_cast<float4*>(p)[tid + 256] = b;

    f16* phr = ph + row * (long)LK_;
    uint2 h0 = { pack_h2(__float2half_rn(a.x), __float2half_rn(a.y)),
                 pack_h2(__float2half_rn(a.z), __float2half_rn(a.w)) };
    uint2 h1 = { pack_h2(__float2half_rn(b.x), __float2half_rn(b.y)),
                 pack_h2(__float2half_rn(b.z), __float2half_rn(b.w)) };
    reinterpret_cast<uint2*>(phr)[tid]       = h0;
    reinterpret_cast<uint2*>(phr)[tid + 256] = h1;
}

// ============================ launch ============================
extern "C" void kernel_launch(void* const* d_in, const int* in_sizes, int n_in,
                              void* d_out, int out_size)
{
    const float* key   = (const float*)d_in[0];
    const float* query = (const float*)d_in[1];
    const int*   mask  = (const int*)d_in[2];
    const float* Wq    = (const float*)d_in[3];
    const float* bq    = (const float*)d_in[4];
    const float* Wk    = (const float*)d_in[5];
    const float* bk    = (const float*)d_in[6];
    const float* Wv    = (const float*)d_in[7];
    const float* bv    = (const float*)d_in[8];

    float* out   = (float*)d_out;                         // [B, LQ, D]
    float* score = out + (size_t)B_ * LQ_ * DIM_;         // [B, LQ, LK]

    f16 *xq16, *xk16, *wq16, *wk16, *wv16;
    f16 *q16, *k16, *v16, *ph;
    cudaGetSymbolAddress((void**)&xq16, g_xq16);
    cudaGetSymbolAddress((void**)&xk16, g_xk16);
    cudaGetSymbolAddress((void**)&wq16, g_wq16);
    cudaGetSymbolAddress((void**)&wk16, g_wk16);
    cudaGetSymbolAddress((void**)&wv16, g_wv16);
    cudaGetSymbolAddress((void**)&q16, g_q16);
    cudaGetSymbolAddress((void**)&k16, g_k16);
    cudaGetSymbolAddress((void**)&v16, g_v16);
    cudaGetSymbolAddress((void**)&ph, g_ph);

    cudaFuncSetAttribute(gemm_f16<0,0,1>, cudaFuncAttributeMaxDynamicSharedMemorySize, SMEM_F16);
    cudaFuncSetAttribute(gemm_f16<1,2,0>, cudaFuncAttributeMaxDynamicSharedMemorySize, SMEM_F16);
    cudaFuncSetAttribute(gemm_f16<2,0,0>, cudaFuncAttributeMaxDynamicSharedMemorySize, SMEM_F16);

    dim3 blk(NTH);
    const float scale = 0.03125f;  // 1/sqrt(1024)
    const long NBIG4 = (long)NE_BIG / 4;
    const long NW4 = (long)DIM_ * DIM_ / 4;
    const unsigned GB = (unsigned)((NBIG4 + 255) / 256);
    const unsigned GW = (unsigned)((NW4 + 255) / 256);

    // q path
    cvt_f16<<<GB, 256>>>(query, xq16, NBIG4);
    cvt_f16<<<GW, 256>>>(Wq, wq16, NW4);
    {   // q = query @ Wq^T + bq -> fp16
        dim3 g(DIM_ / BN, (B_ * LQ_) / BM, 1);
        gemm_f16<1,2,0><<<g, blk, SMEM_F16>>>(xq16, wq16, q16,
                                              DIM_, DIM_, DIM_, 0, 0, 0,
                                              bq, nullptr, 0, 1.f);
    }
    // k path
    cvt_f16<<<GB, 256>>>(key, xk16, NBIG4);
    cvt_f16<<<GW, 256>>>(Wk, wk16, NW4);
    {   // k = key @ Wk^T + bk -> fp16
        dim3 g(DIM_ / BN, (B_ * LK_) / BM, 1);
        gemm_f16<1,2,0><<<g, blk, SMEM_F16>>>(xk16, wk16, k16,
                                              DIM_, DIM_, DIM_, 0, 0, 0,
                                              bk, nullptr, 0, 1.f);
    }
    // v path: v = k_proj @ Wv^T + bv -> fp16 [B,LK,D] directly
    cvt_f16<<<GW, 256>>>(Wv, wv16, NW4);
    {
        dim3 g(DIM_ / BN, (B_ * LK_) / BM, 1);
        gemm_f16<1,2,0><<<g, blk, SMEM_F16>>>(k16, wv16, v16,
                                              DIM_, DIM_, DIM_, 0, 0, 0,
                                              bv, nullptr, 0, 1.f);
    }
    // score_raw = (q @ k^T) * scale, masked (batched)
    {
        dim3 g(LK_ / BN, LQ_ / BM, B_);
        gemm_f16<2,0,0><<<g, blk, SMEM_F16>>>(q16, k16, score,
                                              LK_, DIM_, DIM_,
                                              (long)LQ_ * DIM_, (long)LK_ * DIM_,
                                              (long)LQ_ * LK_,
                                              nullptr, mask, LK_, scale);
    }
    // softmax rows in place + P fp16
    softmax_kernel<<<B_ * LQ_, 256>>>(score, ph);
    // output = P @ V (batched, B = v16 [LK, D] N-contiguous, trans-load)
    {
        dim3 g(DIM_ / BN, LQ_ / BM, B_);
        gemm_f16<0,0,1><<<g, blk, SMEM_F16>>>(ph, v16, out,
                                              DIM_, LK_, DIM_,
                                              (long)LQ_ * LK_, (long)LK_ * DIM_,
                                              (long)LQ_ * DIM_,
                                              nullptr, nullptr, 0, 1.f);
    }
}

// round 16
// speedup vs baseline: 2.5998x; 1.0096x over previous
#include <cuda_runtime.h>
#include <cuda_fp16.h>
#include <cstdint>

// Problem constants: B=8, LQ=LK=2048, D=1024
#define B_   8
#define LQ_  2048
#define LK_  2048
#define DIM_ 1024

typedef __half f16;

// ---------------- device scratch (allocation-free rule) ----------------
#define NE_BIG ((size_t)B_ * LQ_ * DIM_)      // 16M
#define NE_P   ((size_t)B_ * LQ_ * LK_)       // 32M
__device__ f16  g_xq16[NE_BIG];                 // query fp16
__device__ f16  g_xk16[NE_BIG];                 // key fp16
__device__ f16  g_wq16[DIM_*DIM_];
__device__ f16  g_wk16[DIM_*DIM_];
__device__ f16  g_wv16[DIM_*DIM_];
__device__ f16  g_q16[NE_BIG];                  // q proj fp16 (score A)
__device__ f16  g_k16[NE_BIG];                  // k proj fp16 (score B / v-proj A)
__device__ f16  g_v16[NE_BIG];                  // v proj fp16 [B,LK,D] (PV B, trans-load)
__device__ f16  g_ph[NE_P];                     // softmax(P) fp16

// ============================ helpers ============================
__device__ __forceinline__ uint32_t smem_u32(const void* p) {
    uint32_t a;
    asm("{ .reg .u64 t; cvta.to.shared.u64 t, %1; cvt.u32.u64 %0, t; }" : "=r"(a) : "l"(p));
    return a;
}
__device__ __forceinline__ void ldm_x4(uint32_t* r, uint32_t addr) {
    asm volatile("ldmatrix.sync.aligned.m8n8.x4.shared.b16 {%0,%1,%2,%3}, [%4];"
        : "=r"(r[0]), "=r"(r[1]), "=r"(r[2]), "=r"(r[3]) : "r"(addr));
}
__device__ __forceinline__ void ldm_x4_t(uint32_t* r, uint32_t addr) {
    asm volatile("ldmatrix.sync.aligned.m8n8.x4.trans.shared.b16 {%0,%1,%2,%3}, [%4];"
        : "=r"(r[0]), "=r"(r[1]), "=r"(r[2]), "=r"(r[3]) : "r"(addr));
}
__device__ __forceinline__ void mma_f16(float* d, const uint32_t* a, const uint32_t* b) {
    asm volatile(
        "mma.sync.aligned.m16n8k16.row.col.f32.f16.f16.f32 "
        "{%0,%1,%2,%3}, {%4,%5,%6,%7}, {%8,%9}, {%0,%1,%2,%3};"
        : "+f"(d[0]), "+f"(d[1]), "+f"(d[2]), "+f"(d[3])
        : "r"(a[0]), "r"(a[1]), "r"(a[2]), "r"(a[3]), "r"(b[0]), "r"(b[1]));
}
__device__ __forceinline__ uint32_t pack_h2(f16 a, f16 b) {
    __half2 t(a, b);
    return *reinterpret_cast<uint32_t*>(&t);
}
__device__ __forceinline__ void cp16(uint32_t dst, const void* src) {
    asm volatile("cp.async.cg.shared.global [%0], [%1], 16;" :: "r"(dst), "l"(src));
}
#define CP_COMMIT() asm volatile("cp.async.commit_group;" ::: "memory")
#define CP_WAIT1()  asm volatile("cp.async.wait_group 1;" ::: "memory")

// K-major tile: 128B rows (64 halfs), chunk swizzle c = (k>>3) ^ (row&7)
__device__ __forceinline__ uint32_t swoff(uint32_t row, uint32_t k) {
    uint32_t c = (k >> 3) ^ (row & 7u);
    return row * 128u + c * 16u + (k & 7u) * 2u;
}
// TRB tile (rows = k, 256B rows of 128 n-halfs): c = (n>>3) ^ (row&7)
__device__ __forceinline__ uint32_t swoff_t(uint32_t row, uint32_t n) {
    uint32_t c = (n >> 3) ^ (row & 7u);
    return row * 256u + c * 16u + (n & 7u) * 2u;
}

// ===================== fp16 GEMM =====================
// TRB=0: C[M,N] = A[M,K] * B[N,K]^T  (B K-contiguous)
// TRB=1: C[M,N] = A[M,K] * B[K,N]    (B N-contiguous, ldmatrix.trans)
// 128x128x64 tile, 8 warps (2M x 4N), 2 CTAs/SM, 3-stage cp.async,
// B fragments double-buffered across the 4 ks steps.
// EPI: 0 none, 1 +bias[n], 2 mask[n]==0 ? -1e9 : acc*scale
// OUT: 0 fp32 -> p0 ; 2 fp16 -> p0
#define BM 128
#define BN 128
#define BK 64
#define NTH 256
#define NSTAGES 3
#define F_OFF_A 0
#define F_OFF_B 16384
#define F_STG   32768
#define SMEM_F16 (NSTAGES * F_STG)

template <int TRB>
__device__ __forceinline__ void stage_load_f16(uint32_t st,
    const f16* __restrict__ pA, const f16* __restrict__ pB,
    int K_, int ldB, int k0, int tid)
{
#pragma unroll
    for (int i = 0; i < 4; i++) {
        int c = tid + i * NTH;
        int row = c >> 3;
        int kc = (c & 7) * 8;
        cp16(st + F_OFF_A + swoff((uint32_t)row, (uint32_t)kc),
             pA + (long)row * K_ + k0 + kc);
    }
    if (TRB == 0) {
#pragma unroll
        for (int i = 0; i < 4; i++) {
            int c = tid + i * NTH;
            int row = c >> 3;
            int kc = (c & 7) * 8;
            cp16(st + F_OFF_B + swoff((uint32_t)row, (uint32_t)kc),
                 pB + (long)row * ldB + k0 + kc);
        }
    } else {
#pragma unroll
        for (int i = 0; i < 4; i++) {
            int c = tid + i * NTH;
            int row = c >> 4;            // 0..63 (k within tile)
            int nc = (c & 15) * 8;       // 0..120 (n within tile)
            cp16(st + F_OFF_B + swoff_t((uint32_t)row, (uint32_t)nc),
                 pB + (long)(k0 + row) * ldB + nc);
        }
    }
}

template <int EPI, int OUT, int TRB>
__global__ __launch_bounds__(NTH, 2)
void gemm_f16(const f16* __restrict__ A, const f16* __restrict__ Bm,
              void* __restrict__ p0,
              int N_, int K_, int ldB, long sA, long sB, long sC,
              const float* __restrict__ bias,
              const int* __restrict__ mask, long sMask, float scale)
{
    extern __shared__ char sm[];
    const uint32_t smb = smem_u32(sm);

    const int tid = threadIdx.x;
    const int lane = tid & 31;
    const int wid = tid >> 5;
    const int wm = wid & 1;
    const int wn = wid >> 1;

    const int bz = blockIdx.z;
    const int m0 = blockIdx.y * BM;
    const int n0 = blockIdx.x * BN;

    const f16* pA = A + (long)bz * sA + (long)m0 * K_;
    const f16* pB = Bm + (long)bz * sB + (TRB == 0 ? (long)n0 * ldB : (long)n0);

    const uint32_t a_row  = (uint32_t)(wm * 64 + (lane & 15));
    const uint32_t a_cadd = (uint32_t)(lane >> 4);
    const uint32_t b_row  = (uint32_t)(wn * 32 + (lane & 7) + ((lane >> 4) << 3));
    const uint32_t b_cadd = (uint32_t)((lane >> 3) & 1);
    const uint32_t bt_radd = (uint32_t)((lane & 7) + ((lane >> 3) & 1) * 8);
    const uint32_t bt_cadd = (uint32_t)(wn * 4 + (lane >> 4));

    float acc[4][4][4];
#pragma unroll
    for (int i = 0; i < 4; i++)
#pragma unroll
        for (int j = 0; j < 4; j++)
#pragma unroll
            for (int l = 0; l < 4; l++) acc[i][j][l] = 0.f;

    const int nkt = K_ / BK;

#pragma unroll
    for (int s = 0; s < NSTAGES - 1; s++) {
        stage_load_f16<TRB>(smb + s * F_STG, pA, pB, K_, ldB, s * BK, tid);
        CP_COMMIT();
    }

    for (int kt = 0; kt < nkt; kt++) {
        CP_WAIT1();
        __syncthreads();
        const uint32_t curb = smb + (uint32_t)(kt % NSTAGES) * F_STG;

        const int pf = kt + NSTAGES - 1;
        if (pf < nkt)
            stage_load_f16<TRB>(smb + (uint32_t)(pf % NSTAGES) * F_STG, pA, pB,
                                K_, ldB, pf * BK, tid);
        CP_COMMIT();

        // ---- B-fragment double buffer across ks ----
        uint32_t bb[2][2][4];
        // preload B frags for ks=0
        if (TRB == 0) {
#pragma unroll
            for (int np = 0; np < 2; np++)
                ldm_x4(bb[0][np], curb + F_OFF_B + swoff(b_row + np * 16, b_cadd * 8));
        } else {
#pragma unroll
            for (int np = 0; np < 2; np++) {
                uint32_t row = bt_radd;
                uint32_t ch  = bt_cadd + np * 2;
                ldm_x4_t(bb[0][np], curb + F_OFF_B + row * 256u + ((ch ^ (row & 7u)) * 16u));
            }
        }
#pragma unroll
        for (int ks = 0; ks < 4; ks++) {
            const uint32_t c0 = (uint32_t)(ks * 2);
            uint32_t ah[4][4];
#pragma unroll
            for (int mf = 0; mf < 4; mf++)
                ldm_x4(ah[mf], curb + F_OFF_A + swoff(a_row + mf * 16, (c0 + a_cadd) * 8));
            if (ks < 3) {
                const uint32_t c1 = (uint32_t)((ks + 1) * 2);
                if (TRB == 0) {
#pragma unroll
                    for (int np = 0; np < 2; np++)
                        ldm_x4(bb[(ks + 1) & 1][np],
                               curb + F_OFF_B + swoff(b_row + np * 16, (c1 + b_cadd) * 8));
                } else {
#pragma unroll
                    for (int np = 0; np < 2; np++) {
                        uint32_t row = (uint32_t)((ks + 1) * 16) + bt_radd;
                        uint32_t ch  = bt_cadd + np * 2;
                        ldm_x4_t(bb[(ks + 1) & 1][np],
                                 curb + F_OFF_B + row * 256u + ((ch ^ (row & 7u)) * 16u));
                    }
                }
            }
#pragma unroll
            for (int mf = 0; mf < 4; mf++)
#pragma unroll
                for (int nf = 0; nf < 4; nf++)
                    mma_f16(acc[mf][nf], ah[mf], &bb[ks & 1][nf >> 1][(nf & 1) * 2]);
        }
    }

    // ---- epilogue ----
#pragma unroll
    for (int mf = 0; mf < 4; mf++) {
        const int r0 = m0 + wm * 64 + mf * 16 + (lane >> 2);
#pragma unroll
        for (int half = 0; half < 2; half++) {
            const long r = r0 + half * 8;
#pragma unroll
            for (int nf = 0; nf < 4; nf++) {
                const int n = n0 + wn * 32 + nf * 8 + (lane & 3) * 2;
                float v0 = acc[mf][nf][half * 2 + 0];
                float v1 = acc[mf][nf][half * 2 + 1];
                if (EPI == 1) { v0 += bias[n]; v1 += bias[n + 1]; }
                if (EPI == 2) {
                    int2 mv = *reinterpret_cast<const int2*>(mask + bz * sMask + n);
                    v0 = (mv.x == 0) ? -1e9f : v0 * scale;
                    v1 = (mv.y == 0) ? -1e9f : v1 * scale;
                }
                long o = (long)bz * sC + r * N_ + n;
                if (OUT == 0) {
                    float2 ov = { v0, v1 };
                    *reinterpret_cast<float2*>((float*)p0 + o) = ov;
                } else { // OUT == 2
                    *reinterpret_cast<uint32_t*>((f16*)p0 + o) =
                        pack_h2(__float2half_rn(v0), __float2half_rn(v1));
                }
            }
        }
    }
}

// ---------------- fused convert fp32 -> fp16 (5 segments) ----------------
__global__ __launch_bounds__(256)
void cvt_multi(const float* s0, f16* d0, long n0,   // query (float4 units)
               const float* s1, f16* d1, long n1,   // key
               const float* s2, f16* d2, long n2,   // Wq
               const float* s3, f16* d3, long n3,   // Wk
               const float* s4, f16* d4, long n4)   // Wv
{
    long i = (long)blockIdx.x * blockDim.x + threadIdx.x;
    const float* s; f16* d; long off;
    if (i < n0)                       { s = s0; d = d0; off = i; }
    else if ((i -= n0) < n1)          { s = s1; d = d1; off = i; }
    else if ((i -= n1) < n2)          { s = s2; d = d2; off = i; }
    else if ((i -= n2) < n3)          { s = s3; d = d3; off = i; }
    else if ((i -= n3) < n4)          { s = s4; d = d4; off = i; }
    else return;
    float4 t = reinterpret_cast<const float4*>(s)[off];
    uint2 hh = { pack_h2(__float2half_rn(t.x), __float2half_rn(t.y)),
                 pack_h2(__float2half_rn(t.z), __float2half_rn(t.w)) };
    reinterpret_cast<uint2*>(d)[off] = hh;
}

// ---------------- softmax + emit P fp16 ----------------
__global__ __launch_bounds__(256)
void softmax_kernel(float* __restrict__ score, f16* __restrict__ ph)
{
    __shared__ float red[8];
    __shared__ float bcast;

    const long row = blockIdx.x;
    float* p = score + row * (long)LK_;
    const int tid = threadIdx.x;

    float4 a = reinterpret_cast<const float4*>(p)[tid];
    float4 b = reinterpret_cast<const float4*>(p)[tid + 256];

    float m = fmaxf(fmaxf(fmaxf(a.x, a.y), fmaxf(a.z, a.w)),
                    fmaxf(fmaxf(b.x, b.y), fmaxf(b.z, b.w)));
#pragma unroll
    for (int o = 16; o > 0; o >>= 1) m = fmaxf(m, __shfl_xor_sync(0xffffffffu, m, o));
    if ((tid & 31) == 0) red[tid >> 5] = m;
    __syncthreads();
    if (tid == 0) {
        float mm = red[0];
#pragma unroll
        for (int w = 1; w < 8; w++) mm = fmaxf(mm, red[w]);
        bcast = mm;
    }
    __syncthreads();
    m = bcast;
    __syncthreads();

    a.x = __expf(a.x - m); a.y = __expf(a.y - m);
    a.z = __expf(a.z - m); a.w = __expf(a.w - m);
    b.x = __expf(b.x - m); b.y = __expf(b.y - m);
    b.z = __expf(b.z - m); b.w = __expf(b.w - m);

    float s = (a.x + a.y) + (a.z + a.w) + (b.x + b.y) + (b.z + b.w);
#pragma unroll
    for (int o = 16; o > 0; o >>= 1) s += __shfl_xor_sync(0xffffffffu, s, o);
    if ((tid & 31) == 0) red[tid >> 5] = s;
    __syncthreads();
    if (tid == 0) {
        float ss = 0.f;
#pragma unroll
        for (int w = 0; w < 8; w++) ss += red[w];
        bcast = ss;
    }
    __syncthreads();
    s = bcast;

    float inv = 1.0f / s;
    a.x *= inv; a.y *= inv; a.z *= inv; a.w *= inv;
    b.x *= inv; b.y *= inv; b.z *= inv; b.w *= inv;

    reinterpret_cast<float4*>(p)[tid]       = a;
    reinterpret_cast<float4*>(p)[tid + 256] = b;

    f16* phr = ph + row * (long)LK_;
    uint2 h0 = { pack_h2(__float2half_rn(a.x), __float2half_rn(a.y)),
                 pack_h2(__float2half_rn(a.z), __float2half_rn(a.w)) };
    uint2 h1 = { pack_h2(__float2half_rn(b.x), __float2half_rn(b.y)),
                 pack_h2(__float2half_rn(b.z), __float2half_rn(b.w)) };
    reinterpret_cast<uint2*>(phr)[tid]       = h0;
    reinterpret_cast<uint2*>(phr)[tid + 256] = h1;
}

// ============================ launch ============================
extern "C" void kernel_launch(void* const* d_in, const int* in_sizes, int n_in,
                              void* d_out, int out_size)
{
    const float* key   = (const float*)d_in[0];
    const float* query = (const float*)d_in[1];
    const int*   mask  = (const int*)d_in[2];
    const float* Wq    = (const float*)d_in[3];
    const float* bq    = (const float*)d_in[4];
    const float* Wk    = (const float*)d_in[5];
    const float* bk    = (const float*)d_in[6];
    const float* Wv    = (const float*)d_in[7];
    const float* bv    = (const float*)d_in[8];

    float* out   = (float*)d_out;                         // [B, LQ, D]
    float* score = out + (size_t)B_ * LQ_ * DIM_;         // [B, LQ, LK]

    f16 *xq16, *xk16, *wq16, *wk16, *wv16;
    f16 *q16, *k16, *v16, *ph;
    cudaGetSymbolAddress((void**)&xq16, g_xq16);
    cudaGetSymbolAddress((void**)&xk16, g_xk16);
    cudaGetSymbolAddress((void**)&wq16, g_wq16);
    cudaGetSymbolAddress((void**)&wk16, g_wk16);
    cudaGetSymbolAddress((void**)&wv16, g_wv16);
    cudaGetSymbolAddress((void**)&q16, g_q16);
    cudaGetSymbolAddress((void**)&k16, g_k16);
    cudaGetSymbolAddress((void**)&v16, g_v16);
    cudaGetSymbolAddress((void**)&ph, g_ph);

    cudaFuncSetAttribute(gemm_f16<0,0,1>, cudaFuncAttributeMaxDynamicSharedMemorySize, SMEM_F16);
    cudaFuncSetAttribute(gemm_f16<1,2,0>, cudaFuncAttributeMaxDynamicSharedMemorySize, SMEM_F16);
    cudaFuncSetAttribute(gemm_f16<2,0,0>, cudaFuncAttributeMaxDynamicSharedMemorySize, SMEM_F16);

    dim3 blk(NTH);
    const float scale = 0.03125f;  // 1/sqrt(1024)
    const long NBIG4 = (long)NE_BIG / 4;
    const long NW4 = (long)DIM_ * DIM_ / 4;

    // 0: all fp32->fp16 conversions in one launch
    {
        long total = 2 * NBIG4 + 3 * NW4;
        cvt_multi<<<(unsigned)((total + 255) / 256), 256>>>(
            query, xq16, NBIG4, key, xk16, NBIG4,
            Wq, wq16, NW4, Wk, wk16, NW4, Wv, wv16, NW4);
    }
    // 1: q = query @ Wq^T + bq -> fp16
    {
        dim3 g(DIM_ / BN, (B_ * LQ_) / BM, 1);
        gemm_f16<1,2,0><<<g, blk, SMEM_F16>>>(xq16, wq16, q16,
                                              DIM_, DIM_, DIM_, 0, 0, 0,
                                              bq, nullptr, 0, 1.f);
    }
    // 2: k = key @ Wk^T + bk -> fp16
    {
        dim3 g(DIM_ / BN, (B_ * LK_) / BM, 1);
        gemm_f16<1,2,0><<<g, blk, SMEM_F16>>>(xk16, wk16, k16,
                                              DIM_, DIM_, DIM_, 0, 0, 0,
                                              bk, nullptr, 0, 1.f);
    }
    // 3: v = k_proj @ Wv^T + bv -> fp16 [B,LK,D]
    {
        dim3 g(DIM_ / BN, (B_ * LK_) / BM, 1);
        gemm_f16<1,2,0><<<g, blk, SMEM_F16>>>(k16, wv16, v16,
                                              DIM_, DIM_, DIM_, 0, 0, 0,
                                              bv, nullptr, 0, 1.f);
    }
    // 4: score_raw = (q @ k^T) * scale, masked (batched)
    {
        dim3 g(LK_ / BN, LQ_ / BM, B_);
        gemm_f16<2,0,0><<<g, blk, SMEM_F16>>>(q16, k16, score,
                                              LK_, DIM_, DIM_,
                                              (long)LQ_ * DIM_, (long)LK_ * DIM_,
                                              (long)LQ_ * LK_,
                                              nullptr, mask, LK_, scale);
    }
    // 5: softmax rows in place + P fp16
    softmax_kernel<<<B_ * LQ_, 256>>>(score, ph);
    // 6: output = P @ V (batched, v16 [LK,D] N-contiguous, trans-load)
    {
        dim3 g(DIM_ / BN, LQ_ / BM, B_);
        gemm_f16<0,0,1><<<g, blk, SMEM_F16>>>(ph, v16, out,
                                              DIM_, LK_, DIM_,
                                              (long)LQ_ * LK_, (long)LK_ * DIM_,
                                              (long)LQ_ * DIM_,
                                              nullptr, nullptr, 0, 1.f);
    }
}

// round 17
// speedup vs baseline: 2.6201x; 1.0078x over previous
#include <cuda_runtime.h>
#include <cuda_fp16.h>
#include <cstdint>

// Problem constants: B=8, LQ=LK=2048, D=1024
#define B_   8
#define LQ_  2048
#define LK_  2048
#define DIM_ 1024

typedef __half f16;

// ---------------- device scratch (allocation-free rule) ----------------
#define NE_BIG ((size_t)B_ * LQ_ * DIM_)      // 16M
#define NE_P   ((size_t)B_ * LQ_ * LK_)       // 32M
__device__ f16  g_xq16[NE_BIG];                 // query fp16
__device__ f16  g_xk16[NE_BIG];                 // key fp16
__device__ f16  g_wq16[DIM_*DIM_];
__device__ f16  g_wk16[DIM_*DIM_];
__device__ f16  g_wv16[DIM_*DIM_];
__device__ f16  g_q16[NE_BIG];                  // q proj fp16 (score A)
__device__ f16  g_k16[NE_BIG];                  // k proj fp16 (score B / v-proj A)
__device__ f16  g_v16[NE_BIG];                  // v proj fp16 [B,LK,D] (PV B, trans-load)
__device__ f16  g_ph[NE_P];                     // softmax(P) fp16

// ============================ helpers ============================
__device__ __forceinline__ uint32_t smem_u32(const void* p) {
    uint32_t a;
    asm("{ .reg .u64 t; cvta.to.shared.u64 t, %1; cvt.u32.u64 %0, t; }" : "=r"(a) : "l"(p));
    return a;
}
__device__ __forceinline__ void ldm_x4(uint32_t* r, uint32_t addr) {
    asm volatile("ldmatrix.sync.aligned.m8n8.x4.shared.b16 {%0,%1,%2,%3}, [%4];"
        : "=r"(r[0]), "=r"(r[1]), "=r"(r[2]), "=r"(r[3]) : "r"(addr));
}
__device__ __forceinline__ void ldm_x4_t(uint32_t* r, uint32_t addr) {
    asm volatile("ldmatrix.sync.aligned.m8n8.x4.trans.shared.b16 {%0,%1,%2,%3}, [%4];"
        : "=r"(r[0]), "=r"(r[1]), "=r"(r[2]), "=r"(r[3]) : "r"(addr));
}
__device__ __forceinline__ void mma_f16(float* d, const uint32_t* a, const uint32_t* b) {
    asm volatile(
        "mma.sync.aligned.m16n8k16.row.col.f32.f16.f16.f32 "
        "{%0,%1,%2,%3}, {%4,%5,%6,%7}, {%8,%9}, {%0,%1,%2,%3};"
        : "+f"(d[0]), "+f"(d[1]), "+f"(d[2]), "+f"(d[3])
        : "r"(a[0]), "r"(a[1]), "r"(a[2]), "r"(a[3]), "r"(b[0]), "r"(b[1]));
}
__device__ __forceinline__ uint32_t pack_h2(f16 a, f16 b) {
    __half2 t(a, b);
    return *reinterpret_cast<uint32_t*>(&t);
}
__device__ __forceinline__ void cp16(uint32_t dst, const void* src) {
    asm volatile("cp.async.cg.shared.global [%0], [%1], 16;" :: "r"(dst), "l"(src));
}
#define CP_COMMIT() asm volatile("cp.async.commit_group;" ::: "memory")
#define CP_WAIT1()  asm volatile("cp.async.wait_group 1;" ::: "memory")

// K-major tile: 128B rows (64 halfs), chunk swizzle c = (k>>3) ^ (row&7)
__device__ __forceinline__ uint32_t swoff(uint32_t row, uint32_t k) {
    uint32_t c = (k >> 3) ^ (row & 7u);
    return row * 128u + c * 16u + (k & 7u) * 2u;
}
// TRB tile (rows = k, 256B rows of 128 n-halfs): c = (n>>3) ^ (row&7)
__device__ __forceinline__ uint32_t swoff_t(uint32_t row, uint32_t n) {
    uint32_t c = (n >> 3) ^ (row & 7u);
    return row * 256u + c * 16u + (n & 7u) * 2u;
}

// ===================== fp16 GEMM =====================
// TRB=0: C[M,N] = A[M,K] * B[N,K]^T ; TRB=1: C[M,N] = A[M,K] * B[K,N] (trans-load)
// 128x128x64 tile, 8 warps (2M x 4N), 2 CTAs/SM, 3-stage cp.async.
// B frags double-buffered across ks; A frags rotate in a 2-deep buffer across mf.
// EPI: 0 none, 1 +bias[n], 2 mask[n]==0 ? -1e9 : acc*scale
// OUT: 0 fp32 -> p0 ; 2 fp16 -> p0
#define BM 128
#define BN 128
#define BK 64
#define NTH 256
#define NSTAGES 3
#define F_OFF_A 0
#define F_OFF_B 16384
#define F_STG   32768
#define SMEM_F16 (NSTAGES * F_STG)

template <int TRB>
__device__ __forceinline__ void stage_load_f16(uint32_t st,
    const f16* __restrict__ pA, const f16* __restrict__ pB,
    int K_, int ldB, int k0, int tid)
{
#pragma unroll
    for (int i = 0; i < 4; i++) {
        int c = tid + i * NTH;
        int row = c >> 3;
        int kc = (c & 7) * 8;
        cp16(st + F_OFF_A + swoff((uint32_t)row, (uint32_t)kc),
             pA + (long)row * K_ + k0 + kc);
    }
    if (TRB == 0) {
#pragma unroll
        for (int i = 0; i < 4; i++) {
            int c = tid + i * NTH;
            int row = c >> 3;
            int kc = (c & 7) * 8;
            cp16(st + F_OFF_B + swoff((uint32_t)row, (uint32_t)kc),
                 pB + (long)row * ldB + k0 + kc);
        }
    } else {
#pragma unroll
        for (int i = 0; i < 4; i++) {
            int c = tid + i * NTH;
            int row = c >> 4;            // 0..63 (k within tile)
            int nc = (c & 15) * 8;       // 0..120 (n within tile)
            cp16(st + F_OFF_B + swoff_t((uint32_t)row, (uint32_t)nc),
                 pB + (long)(k0 + row) * ldB + nc);
        }
    }
}

template <int EPI, int OUT, int TRB>
__global__ __launch_bounds__(NTH, 2)
void gemm_f16(const f16* __restrict__ A, const f16* __restrict__ Bm,
              void* __restrict__ p0,
              int N_, int K_, int ldB, long sA, long sB, long sC,
              const float* __restrict__ bias,
              const int* __restrict__ mask, long sMask, float scale)
{
    extern __shared__ char sm[];
    const uint32_t smb = smem_u32(sm);

    const int tid = threadIdx.x;
    const int lane = tid & 31;
    const int wid = tid >> 5;
    const int wm = wid & 1;
    const int wn = wid >> 1;

    const int bz = blockIdx.z;
    const int m0 = blockIdx.y * BM;
    const int n0 = blockIdx.x * BN;

    const f16* pA = A + (long)bz * sA + (long)m0 * K_;
    const f16* pB = Bm + (long)bz * sB + (TRB == 0 ? (long)n0 * ldB : (long)n0);

    const uint32_t a_row  = (uint32_t)(wm * 64 + (lane & 15));
    const uint32_t a_cadd = (uint32_t)(lane >> 4);
    const uint32_t b_row  = (uint32_t)(wn * 32 + (lane & 7) + ((lane >> 4) << 3));
    const uint32_t b_cadd = (uint32_t)((lane >> 3) & 1);
    const uint32_t bt_radd = (uint32_t)((lane & 7) + ((lane >> 3) & 1) * 8);
    const uint32_t bt_cadd = (uint32_t)(wn * 4 + (lane >> 4));

    float acc[4][4][4];
#pragma unroll
    for (int i = 0; i < 4; i++)
#pragma unroll
        for (int j = 0; j < 4; j++)
#pragma unroll
            for (int l = 0; l < 4; l++) acc[i][j][l] = 0.f;

    const int nkt = K_ / BK;

#pragma unroll
    for (int s = 0; s < NSTAGES - 1; s++) {
        stage_load_f16<TRB>(smb + s * F_STG, pA, pB, K_, ldB, s * BK, tid);
        CP_COMMIT();
    }

    for (int kt = 0; kt < nkt; kt++) {
        CP_WAIT1();
        __syncthreads();
        const uint32_t curb = smb + (uint32_t)(kt % NSTAGES) * F_STG;

        const int pf = kt + NSTAGES - 1;
        if (pf < nkt)
            stage_load_f16<TRB>(smb + (uint32_t)(pf % NSTAGES) * F_STG, pA, pB,
                                K_, ldB, pf * BK, tid);
        CP_COMMIT();

        // ---- B double-buffer across ks, A rotating 2-deep across mf ----
        uint32_t bb[2][2][4];
        uint32_t aa[2][4];
        if (TRB == 0) {
#pragma unroll
            for (int np = 0; np < 2; np++)
                ldm_x4(bb[0][np], curb + F_OFF_B + swoff(b_row + np * 16, b_cadd * 8));
        } else {
#pragma unroll
            for (int np = 0; np < 2; np++) {
                uint32_t row = bt_radd;
                uint32_t ch  = bt_cadd + np * 2;
                ldm_x4_t(bb[0][np], curb + F_OFF_B + row * 256u + ((ch ^ (row & 7u)) * 16u));
            }
        }
        ldm_x4(aa[0], curb + F_OFF_A + swoff(a_row, a_cadd * 8));  // A(mf=0, ks=0)

#pragma unroll
        for (int ks = 0; ks < 4; ks++) {
            const uint32_t c0 = (uint32_t)(ks * 2);
            // prefetch next ks's B frags while mf=0 MMAs run
            if (ks < 3) {
                const uint32_t c1 = (uint32_t)((ks + 1) * 2);
                if (TRB == 0) {
#pragma unroll
                    for (int np = 0; np < 2; np++)
                        ldm_x4(bb[(ks + 1) & 1][np],
                               curb + F_OFF_B + swoff(b_row + np * 16, (c1 + b_cadd) * 8));
                } else {
#pragma unroll
                    for (int np = 0; np < 2; np++) {
                        uint32_t row = (uint32_t)((ks + 1) * 16) + bt_radd;
                        uint32_t ch  = bt_cadd + np * 2;
                        ldm_x4_t(bb[(ks + 1) & 1][np],
                                 curb + F_OFF_B + row * 256u + ((ch ^ (row & 7u)) * 16u));
                    }
                }
            }
#pragma unroll
            for (int mf = 0; mf < 4; mf++) {
                // prefetch next A frag (next mf, or mf=0 of next ks)
                if (mf < 3) {
                    ldm_x4(aa[(mf + 1) & 1],
                           curb + F_OFF_A + swoff(a_row + (mf + 1) * 16, (c0 + a_cadd) * 8));
                } else if (ks < 3) {
                    ldm_x4(aa[0],
                           curb + F_OFF_A + swoff(a_row, ((uint32_t)((ks + 1) * 2) + a_cadd) * 8));
                }
#pragma unroll
                for (int nf = 0; nf < 4; nf++)
                    mma_f16(acc[mf][nf], aa[mf & 1], &bb[ks & 1][nf >> 1][(nf & 1) * 2]);
            }
        }
    }

    // ---- epilogue ----
#pragma unroll
    for (int mf = 0; mf < 4; mf++) {
        const int r0 = m0 + wm * 64 + mf * 16 + (lane >> 2);
#pragma unroll
        for (int half = 0; half < 2; half++) {
            const long r = r0 + half * 8;
#pragma unroll
            for (int nf = 0; nf < 4; nf++) {
                const int n = n0 + wn * 32 + nf * 8 + (lane & 3) * 2;
                float v0 = acc[mf][nf][half * 2 + 0];
                float v1 = acc[mf][nf][half * 2 + 1];
                if (EPI == 1) { v0 += bias[n]; v1 += bias[n + 1]; }
                if (EPI == 2) {
                    int2 mv = *reinterpret_cast<const int2*>(mask + bz * sMask + n);
                    v0 = (mv.x == 0) ? -1e9f : v0 * scale;
                    v1 = (mv.y == 0) ? -1e9f : v1 * scale;
                }
                long o = (long)bz * sC + r * N_ + n;
                if (OUT == 0) {
                    float2 ov = { v0, v1 };
                    *reinterpret_cast<float2*>((float*)p0 + o) = ov;
                } else { // OUT == 2
                    *reinterpret_cast<uint32_t*>((f16*)p0 + o) =
                        pack_h2(__float2half_rn(v0), __float2half_rn(v1));
                }
            }
        }
    }
}

// ---------------- fused convert fp32 -> fp16 (5 segments) ----------------
__global__ __launch_bounds__(256)
void cvt_multi(const float* s0, f16* d0, long n0,
               const float* s1, f16* d1, long n1,
               const float* s2, f16* d2, long n2,
               const float* s3, f16* d3, long n3,
               const float* s4, f16* d4, long n4)
{
    long i = (long)blockIdx.x * blockDim.x + threadIdx.x;
    const float* s; f16* d; long off;
    if (i < n0)                       { s = s0; d = d0; off = i; }
    else if ((i -= n0) < n1)          { s = s1; d = d1; off = i; }
    else if ((i -= n1) < n2)          { s = s2; d = d2; off = i; }
    else if ((i -= n2) < n3)          { s = s3; d = d3; off = i; }
    else if ((i -= n3) < n4)          { s = s4; d = d4; off = i; }
    else return;
    float4 t = reinterpret_cast<const float4*>(s)[off];
    uint2 hh = { pack_h2(__float2half_rn(t.x), __float2half_rn(t.y)),
                 pack_h2(__float2half_rn(t.z), __float2half_rn(t.w)) };
    reinterpret_cast<uint2*>(d)[off] = hh;
}

// ---------------- softmax + emit P fp16 ----------------
__global__ __launch_bounds__(256)
void softmax_kernel(float* __restrict__ score, f16* __restrict__ ph)
{
    __shared__ float red[8];
    __shared__ float bcast;

    const long row = blockIdx.x;
    float* p = score + row * (long)LK_;
    const int tid = threadIdx.x;

    float4 a = reinterpret_cast<const float4*>(p)[tid];
    float4 b = reinterpret_cast<const float4*>(p)[tid + 256];

    float m = fmaxf(fmaxf(fmaxf(a.x, a.y), fmaxf(a.z, a.w)),
                    fmaxf(fmaxf(b.x, b.y), fmaxf(b.z, b.w)));
#pragma unroll
    for (int o = 16; o > 0; o >>= 1) m = fmaxf(m, __shfl_xor_sync(0xffffffffu, m, o));
    if ((tid & 31) == 0) red[tid >> 5] = m;
    __syncthreads();
    if (tid == 0) {
        float mm = red[0];
#pragma unroll
        for (int w = 1; w < 8; w++) mm = fmaxf(mm, red[w]);
        bcast = mm;
    }
    __syncthreads();
    m = bcast;
    __syncthreads();

    a.x = __expf(a.x - m); a.y = __expf(a.y - m);
    a.z = __expf(a.z - m); a.w = __expf(a.w - m);
    b.x = __expf(b.x - m); b.y = __expf(b.y - m);
    b.z = __expf(b.z - m); b.w = __expf(b.w - m);

    float s = (a.x + a.y) + (a.z + a.w) + (b.x + b.y) + (b.z + b.w);
#pragma unroll
    for (int o = 16; o > 0; o >>= 1) s += __shfl_xor_sync(0xffffffffu, s, o);
    if ((tid & 31) == 0) red[tid >> 5] = s;
    __syncthreads();
    if (tid == 0) {
        float ss = 0.f;
#pragma unroll
        for (int w = 0; w < 8; w++) ss += red[w];
        bcast = ss;
    }
    __syncthreads();
    s = bcast;

    float inv = 1.0f / s;
    a.x *= inv; a.y *= inv; a.z *= inv; a.w *= inv;
    b.x *= inv; b.y *= inv; b.z *= inv; b.w *= inv;

    reinterpret_cast<float4*>(p)[tid]       = a;
    reinterpret_cast<float4*>(p)[tid + 256] = b;

    f16* phr = ph + row * (long)LK_;
    uint2 h0 = { pack_h2(__float2half_rn(a.x), __float2half_rn(a.y)),
                 pack_h2(__float2half_rn(a.z), __float2half_rn(a.w)) };
    uint2 h1 = { pack_h2(__float2half_rn(b.x), __float2half_rn(b.y)),
                 pack_h2(__float2half_rn(b.z), __float2half_rn(b.w)) };
    reinterpret_cast<uint2*>(phr)[tid]       = h0;
    reinterpret_cast<uint2*>(phr)[tid + 256] = h1;
}

// ============================ launch ============================
extern "C" void kernel_launch(void* const* d_in, const int* in_sizes, int n_in,
                              void* d_out, int out_size)
{
    const float* key   = (const float*)d_in[0];
    const float* query = (const float*)d_in[1];
    const int*   mask  = (const int*)d_in[2];
    const float* Wq    = (const float*)d_in[3];
    const float* bq    = (const float*)d_in[4];
    const float* Wk    = (const float*)d_in[5];
    const float* bk    = (const float*)d_in[6];
    const float* Wv    = (const float*)d_in[7];
    const float* bv    = (const float*)d_in[8];

    float* out   = (float*)d_out;                         // [B, LQ, D]
    float* score = out + (size_t)B_ * LQ_ * DIM_;         // [B, LQ, LK]

    f16 *xq16, *xk16, *wq16, *wk16, *wv16;
    f16 *q16, *k16, *v16, *ph;
    cudaGetSymbolAddress((void**)&xq16, g_xq16);
    cudaGetSymbolAddress((void**)&xk16, g_xk16);
    cudaGetSymbolAddress((void**)&wq16, g_wq16);
    cudaGetSymbolAddress((void**)&wk16, g_wk16);
    cudaGetSymbolAddress((void**)&wv16, g_wv16);
    cudaGetSymbolAddress((void**)&q16, g_q16);
    cudaGetSymbolAddress((void**)&k16, g_k16);
    cudaGetSymbolAddress((void**)&v16, g_v16);
    cudaGetSymbolAddress((void**)&ph, g_ph);

    cudaFuncSetAttribute(gemm_f16<0,0,1>, cudaFuncAttributeMaxDynamicSharedMemorySize, SMEM_F16);
    cudaFuncSetAttribute(gemm_f16<1,2,0>, cudaFuncAttributeMaxDynamicSharedMemorySize, SMEM_F16);
    cudaFuncSetAttribute(gemm_f16<2,0,0>, cudaFuncAttributeMaxDynamicSharedMemorySize, SMEM_F16);

    dim3 blk(NTH);
    const float scale = 0.03125f;  // 1/sqrt(1024)
    const long NBIG4 = (long)NE_BIG / 4;
    const long NW4 = (long)DIM_ * DIM_ / 4;

    // 0: all fp32->fp16 conversions in one launch
    {
        long total = 2 * NBIG4 + 3 * NW4;
        cvt_multi<<<(unsigned)((total + 255) / 256), 256>>>(
            query, xq16, NBIG4, key, xk16, NBIG4,
            Wq, wq16, NW4, Wk, wk16, NW4, Wv, wv16, NW4);
    }
    // 1: q = query @ Wq^T + bq -> fp16
    {
        dim3 g(DIM_ / BN, (B_ * LQ_) / BM, 1);
        gemm_f16<1,2,0><<<g, blk, SMEM_F16>>>(xq16, wq16, q16,
                                              DIM_, DIM_, DIM_, 0, 0, 0,
                                              bq, nullptr, 0, 1.f);
    }
    // 2: k = key @ Wk^T + bk -> fp16
    {
        dim3 g(DIM_ / BN, (B_ * LK_) / BM, 1);
        gemm_f16<1,2,0><<<g, blk, SMEM_F16>>>(xk16, wk16, k16,
                                              DIM_, DIM_, DIM_, 0, 0, 0,
                                              bk, nullptr, 0, 1.f);
    }
    // 3: v = k_proj @ Wv^T + bv -> fp16 [B,LK,D]
    {
        dim3 g(DIM_ / BN, (B_ * LK_) / BM, 1);
        gemm_f16<1,2,0><<<g, blk, SMEM_F16>>>(k16, wv16, v16,
                                              DIM_, DIM_, DIM_, 0, 0, 0,
                                              bv, nullptr, 0, 1.f);
    }
    // 4: score_raw = (q @ k^T) * scale, masked (batched)
    {
        dim3 g(LK_ / BN, LQ_ / BM, B_);
        gemm_f16<2,0,0><<<g, blk, SMEM_F16>>>(q16, k16, score,
                                              LK_, DIM_, DIM_,
                                              (long)LQ_ * DIM_, (long)LK_ * DIM_,
                                              (long)LQ_ * LK_,
                                              nullptr, mask, LK_, scale);
    }
    // 5: softmax rows in place + P fp16
    softmax_kernel<<<B_ * LQ_, 256>>>(score, ph);
    // 6: output = P @ V (batched, v16 [LK,D] N-contiguous, trans-load)
    {
        dim3 g(DIM_ / BN, LQ_ / BM, B_);
        gemm_f16<0,0,1><<<g, blk, SMEM_F16>>>(ph, v16, out,
                                              DIM_, LK_, DIM_,
                                              (long)LQ_ * LK_, (long)LK_ * DIM_,
                                              (long)LQ_ * DIM_,
                                              nullptr, nullptr, 0, 1.f);
    }
}